// round 5
// baseline (speedup 1.0000x reference)
#include <cuda_runtime.h>
#include <cuda_bf16.h>
#include <cuda_fp16.h>
#include <math.h>
#include <stdint.h>

#define NN 10000
#define EE 160000
#define ET 170000   // edges + self loops

// ---------------- scratch (device globals; no allocations allowed) ----------
__device__ float g_hmat[NN * 2048];
__device__ float g_es  [NN * 4];
__device__ float g_ed  [NN * 4];
__device__ float g_alpha[ET * 4];
__device__ int   g_counts [NN];
__device__ int   g_rowptr [NN + 1];
__device__ int   g_fillpos[NN];
__device__ int   g_csrsrc [ET];
__device__ int   g_is64;
// 16-bit hi/lo activation pairs (ping-pong) + weight pair (bf16 or fp16 views)
__device__ __align__(16) uint16_t g_P0h[NN * 2048];
__device__ __align__(16) uint16_t g_P0l[NN * 2048];
__device__ __align__(16) uint16_t g_P1h[NN * 2048];
__device__ __align__(16) uint16_t g_P1l[NN * 2048];
__device__ __align__(16) uint16_t g_Wh[2048 * 2048];
__device__ __align__(16) uint16_t g_Wl[2048 * 2048];

// ============================ PTX helpers (baseline, sm_80+) =================
__device__ __forceinline__ uint32_t smem_to_u32(const void* p) {
    uint32_t a;
    asm("{ .reg .u64 t; cvta.to.shared.u64 t, %1; cvt.u32.u64 %0, t; }" : "=r"(a) : "l"(p));
    return a;
}

__device__ __forceinline__ void cp16(uint32_t dst, const void* src, bool v) {
    int sz = v ? 16 : 0;
    asm volatile("cp.async.cg.shared.global [%0], [%1], 16, %2;\n"
                 :: "r"(dst), "l"(src), "r"(sz) : "memory");
}
#define CP_COMMIT() asm volatile("cp.async.commit_group;" ::: "memory")
#define CP_WAIT1()  asm volatile("cp.async.wait_group 1;" ::: "memory")

__device__ __forceinline__ void ldsm4(uint32_t* r, uint32_t addr) {
    asm volatile("ldmatrix.sync.aligned.m8n8.x4.shared.b16 {%0,%1,%2,%3}, [%4];"
                 : "=r"(r[0]), "=r"(r[1]), "=r"(r[2]), "=r"(r[3]) : "r"(addr));
}

__device__ __forceinline__ void mma_bf16(float* c, const uint32_t* a, const uint32_t* b) {
    asm volatile(
        "mma.sync.aligned.m16n8k16.row.col.f32.bf16.bf16.f32 "
        "{%0,%1,%2,%3}, {%4,%5,%6,%7}, {%8,%9}, {%0,%1,%2,%3};"
        : "+f"(c[0]), "+f"(c[1]), "+f"(c[2]), "+f"(c[3])
        : "r"(a[0]), "r"(a[1]), "r"(a[2]), "r"(a[3]), "r"(b[0]), "r"(b[1]));
}
__device__ __forceinline__ void mma_fp16(float* c, const uint32_t* a, const uint32_t* b) {
    asm volatile(
        "mma.sync.aligned.m16n8k16.row.col.f32.f16.f16.f32 "
        "{%0,%1,%2,%3}, {%4,%5,%6,%7}, {%8,%9}, {%0,%1,%2,%3};"
        : "+f"(c[0]), "+f"(c[1]), "+f"(c[2]), "+f"(c[3])
        : "r"(a[0]), "r"(a[1]), "r"(a[2]), "r"(a[3]), "r"(b[0]), "r"(b[1]));
}

__device__ __forceinline__ int edge_at(const void* ei, long long idx) {
    if (g_is64) return (int)((const long long*)ei)[idx];
    return ((const int*)ei)[idx];
}

// ---------------- CSR build ---------------------------------------------------
__global__ void detect_init_kernel(const unsigned int* p) {
    int i = blockIdx.x * blockDim.x + threadIdx.x;
    if (i < NN) g_counts[i] = 1;           // self loop pre-counted
    if (i == 0) {
        int is64 = 1;
        for (int j = 0; j < 128; j++)
            if (p[2 * j + 1] != 0u) { is64 = 0; break; }
        g_is64 = is64;
    }
}
__global__ void count_kernel(const void* ei) {
    int e = blockIdx.x * blockDim.x + threadIdx.x;
    if (e < EE) atomicAdd(&g_counts[edge_at(ei, (long long)EE + e)], 1);
}
__global__ void scan_fillself_kernel() {
    __shared__ int sh[1024];
    int t = threadIdx.x;
    const int chunk = (NN + 1023) >> 10;
    int base = t * chunk;
    int s = 0;
    for (int j = 0; j < chunk; j++) { int idx = base + j; if (idx < NN) s += g_counts[idx]; }
    sh[t] = s;
    __syncthreads();
    for (int off = 1; off < 1024; off <<= 1) {
        int v = (t >= off) ? sh[t - off] : 0;
        __syncthreads();
        sh[t] += v;
        __syncthreads();
    }
    int prefix = (t > 0) ? sh[t - 1] : 0;
    for (int j = 0; j < chunk; j++) {
        int idx = base + j;
        if (idx < NN) { g_rowptr[idx] = prefix; prefix += g_counts[idx]; }
    }
    if (t == 0) g_rowptr[NN] = sh[1023];
    __syncthreads();
    for (int idx = t; idx < NN; idx += 1024) {
        int r = g_rowptr[idx];
        g_csrsrc[r] = idx;
        g_fillpos[idx] = r + 1;
    }
}
__global__ void filledges_kernel(const void* ei) {
    int e = blockIdx.x * blockDim.x + threadIdx.x;
    if (e < EE) {
        int s = edge_at(ei, e);
        int d = edge_at(ei, (long long)EE + e);
        g_csrsrc[atomicAdd(&g_fillpos[d], 1)] = s;
    }
}

// ---------------- fp32 -> bf16 hi/lo split (input x only) --------------------
__global__ void cvt_split_kernel(const float* __restrict__ x,
                                 uint16_t* __restrict__ hi,
                                 uint16_t* __restrict__ lo, int n4) {
    int i = blockIdx.x * blockDim.x + threadIdx.x;
    if (i >= n4) return;
    float4 v = ((const float4*)x)[i];
    __nv_bfloat16 h0 = __float2bfloat16(v.x);
    __nv_bfloat16 h1 = __float2bfloat16(v.y);
    __nv_bfloat16 h2 = __float2bfloat16(v.z);
    __nv_bfloat16 h3 = __float2bfloat16(v.w);
    __nv_bfloat16 l0 = __float2bfloat16(v.x - __bfloat162float(h0));
    __nv_bfloat16 l1 = __float2bfloat16(v.y - __bfloat162float(h1));
    __nv_bfloat16 l2 = __float2bfloat16(v.z - __bfloat162float(h2));
    __nv_bfloat16 l3 = __float2bfloat16(v.w - __bfloat162float(h3));
    ((__nv_bfloat162*)hi)[2 * i]     = __nv_bfloat162(h0, h1);
    ((__nv_bfloat162*)hi)[2 * i + 1] = __nv_bfloat162(h2, h3);
    ((__nv_bfloat162*)lo)[2 * i]     = __nv_bfloat162(l0, l1);
    ((__nv_bfloat162*)lo)[2 * i + 1] = __nv_bfloat162(l2, l3);
}

// ---------------- weight transpose + split: W[K,N] -> Wt[N,K] ----------------
__global__ void cvt_transpose_bf16_kernel(const float* __restrict__ W,
                                          uint16_t* __restrict__ th,
                                          uint16_t* __restrict__ tl, int K, int N) {
    __shared__ float tile[32][33];
    int n0 = blockIdx.x * 32, k0 = blockIdx.y * 32;
    int tx = threadIdx.x, ty = threadIdx.y;   // 32 x 8
    for (int r = ty; r < 32; r += 8)
        tile[r][tx] = W[(size_t)(k0 + r) * N + n0 + tx];
    __syncthreads();
    for (int r = ty; r < 32; r += 8) {
        float v = tile[tx][r];
        __nv_bfloat16 h = __float2bfloat16(v);
        size_t o = (size_t)(n0 + r) * K + k0 + tx;
        ((__nv_bfloat16*)th)[o] = h;
        ((__nv_bfloat16*)tl)[o] = __float2bfloat16(v - __bfloat162float(h));
    }
}
__global__ void cvt_transpose_f16_kernel(const float* __restrict__ W,
                                         uint16_t* __restrict__ th, int K, int N) {
    __shared__ float tile[32][33];
    int n0 = blockIdx.x * 32, k0 = blockIdx.y * 32;
    int tx = threadIdx.x, ty = threadIdx.y;
    for (int r = ty; r < 32; r += 8)
        tile[r][tx] = W[(size_t)(k0 + r) * N + n0 + tx];
    __syncthreads();
    for (int r = ty; r < 32; r += 8) {
        float v = tile[tx][r];
        ((__half*)th)[(size_t)(n0 + r) * K + k0 + tx] = __float2half(v);
    }
}

// ---------------- mma.sync GEMM: C = A[M,K] @ Bt[N,K]^T (+bias) --------------
// CTA 128x128, BK=64, 3-stage cp.async pipeline, 8 warps of 64x32.
// PASSES==3: bf16 hi/lo x3 (Ah*Bh + Ah*Bl + Al*Bh). Tiles: Ah,Al,Bh,Bl.
// PASSES==2: fp16, A split x2 (Ah*Bh + Al*Bh). Tiles: Ah,Al,Bh.
// EPI 0: fp32 out (+bias). EPI 1: bf16 hi/lo split out (+bias).
#define GT 16384                      // one operand tile: 128 rows x 128B

__device__ __forceinline__ uint32_t swz(uint32_t base, int row, int kelem) {
    return base + row * 128 + ((((kelem >> 3) ^ row) & 7) << 4);
}

template <int PASSES, int EPI>
__global__ void __launch_bounds__(256, 1) gemm_mma_kernel(
    const uint16_t* __restrict__ Ah, const uint16_t* __restrict__ Al,
    const uint16_t* __restrict__ Bh, const uint16_t* __restrict__ Bl,
    const float* __restrict__ bias, float* __restrict__ Cf,
    uint16_t* __restrict__ Ch, uint16_t* __restrict__ Cl,
    int M, int N, int K)
{
    constexpr int NT = (PASSES == 3) ? 4 : 3;       // tiles per stage
    constexpr uint32_t STAGE = NT * GT;
    extern __shared__ char smem[];
    const uint32_t sb = smem_to_u32(smem);
    const int tid = threadIdx.x;
    const int lane = tid & 31, wid = tid >> 5;
    const int m0 = blockIdx.y * 128, n0 = blockIdx.x * 128;
    const int nk = K >> 6;

    auto load_stage = [&](int s, int j) {
        const uint32_t sbase = sb + (uint32_t)s * STAGE;
        const int lrow = tid >> 3;
        const int lchk = tid & 7;
        const bool jv = (j < nk);
        const long long k0 = jv ? ((long long)j << 6) : 0;
#pragma unroll
        for (int it = 0; it < 4; it++) {
            int row = lrow + it * 32;
            bool av = jv && (m0 + row < M);
            int gr = (m0 + row < M) ? (m0 + row) : 0;
            size_t aoff = (size_t)gr * K + k0 + lchk * 8;
            size_t boff = (size_t)(n0 + row) * K + k0 + lchk * 8;
            uint32_t d = swz(sbase, row, lchk * 8);
            cp16(d,      Ah + aoff, av);
            cp16(d + GT, Al + aoff, av);
            uint32_t db = swz(sbase + 2 * GT, row, lchk * 8);
            cp16(db, Bh + boff, jv);
            if (PASSES == 3) cp16(db + GT, Bl + boff, jv);
        }
    };

    float acc[4][4][4];
#pragma unroll
    for (int a = 0; a < 4; a++)
#pragma unroll
        for (int b = 0; b < 4; b++)
#pragma unroll
            for (int c = 0; c < 4; c++) acc[a][b][c] = 0.f;

    load_stage(0, 0);
    CP_COMMIT();
    load_stage(1, 1);
    CP_COMMIT();

    const int mw = (wid & 1) * 64;     // warp M offset
    const int nw = (wid >> 1) * 32;    // warp N offset
    const int rsel = lane & 15;
    const int khalf = (lane >> 4) * 8;

    for (int i = 0; i < nk; i++) {
        CP_WAIT1();
        __syncthreads();
        load_stage((i + 2) % 3, i + 2);   // zero-fill past end
        CP_COMMIT();

        const uint32_t sA = sb + (uint32_t)(i % 3) * STAGE;
        const uint32_t sB = sA + 2 * GT;
#pragma unroll
        for (int ks = 0; ks < 4; ks++) {
            const int ke = ks * 16 + khalf;
            uint32_t ah[4][4], al[4][4], bh[2][4], bl[2][4];
#pragma unroll
            for (int mi = 0; mi < 4; mi++) {
                uint32_t ad = swz(sA, mw + mi * 16 + rsel, ke);
                ldsm4(ah[mi], ad);
                ldsm4(al[mi], ad + GT);
            }
#pragma unroll
            for (int bi = 0; bi < 2; bi++) {
                uint32_t bd = swz(sB, nw + bi * 16 + rsel, ke);
                ldsm4(bh[bi], bd);
                if (PASSES == 3) ldsm4(bl[bi], bd + GT);
            }
#pragma unroll
            for (int mi = 0; mi < 4; mi++) {
#pragma unroll
                for (int nj = 0; nj < 4; nj++) {
                    uint32_t b2h[2] = { bh[nj >> 1][nj & 1], bh[nj >> 1][(nj & 1) + 2] };
                    if (PASSES == 3) {
                        uint32_t b2l[2] = { bl[nj >> 1][nj & 1], bl[nj >> 1][(nj & 1) + 2] };
                        mma_bf16(acc[mi][nj], ah[mi], b2h);
                        mma_bf16(acc[mi][nj], ah[mi], b2l);
                        mma_bf16(acc[mi][nj], al[mi], b2h);
                    } else {
                        mma_fp16(acc[mi][nj], ah[mi], b2h);
                        mma_fp16(acc[mi][nj], al[mi], b2h);
                    }
                }
            }
        }
        __syncthreads();
    }

    // epilogue
#pragma unroll
    for (int mi = 0; mi < 4; mi++) {
#pragma unroll
        for (int nj = 0; nj < 4; nj++) {
            int col = n0 + nw + nj * 8 + (lane & 3) * 2;
            float bx = 0.f, by = 0.f;
            if (bias) { bx = bias[col]; by = bias[col + 1]; }
            int r0 = m0 + mw + mi * 16 + (lane >> 2);
            int r1 = r0 + 8;
            if (EPI == 0) {
                if (r0 < M)
                    *(float2*)(Cf + (size_t)r0 * N + col) =
                        make_float2(acc[mi][nj][0] + bx, acc[mi][nj][1] + by);
                if (r1 < M)
                    *(float2*)(Cf + (size_t)r1 * N + col) =
                        make_float2(acc[mi][nj][2] + bx, acc[mi][nj][3] + by);
            } else {
                if (r0 < M) {
                    float v0 = acc[mi][nj][0] + bx, v1 = acc[mi][nj][1] + by;
                    __nv_bfloat16 h0 = __float2bfloat16(v0), h1 = __float2bfloat16(v1);
                    size_t o = ((size_t)r0 * N + col) >> 1;
                    ((__nv_bfloat162*)Ch)[o] = __nv_bfloat162(h0, h1);
                    ((__nv_bfloat162*)Cl)[o] = __nv_bfloat162(
                        __float2bfloat16(v0 - __bfloat162float(h0)),
                        __float2bfloat16(v1 - __bfloat162float(h1)));
                }
                if (r1 < M) {
                    float v0 = acc[mi][nj][2] + bx, v1 = acc[mi][nj][3] + by;
                    __nv_bfloat16 h0 = __float2bfloat16(v0), h1 = __float2bfloat16(v1);
                    size_t o = ((size_t)r1 * N + col) >> 1;
                    ((__nv_bfloat162*)Ch)[o] = __nv_bfloat162(h0, h1);
                    ((__nv_bfloat162*)Cl)[o] = __nv_bfloat162(
                        __float2bfloat16(v0 - __bfloat162float(h0)),
                        __float2bfloat16(v1 - __bfloat162float(h1)));
                }
            }
        }
    }
}

// ---------------- per-node attention coefficients es/ed ----------------------
__global__ void attn_kernel(const float* __restrict__ hmat,
                            const float* __restrict__ a_src,
                            const float* __restrict__ a_dst, int H) {
    const int C = 512;
    int i = blockIdx.x;
    int hh = threadIdx.x >> 5;
    int lane = threadIdx.x & 31;
    const float* hr = hmat + (size_t)i * H * C + hh * C;
    float s = 0.f, d = 0.f;
    for (int c = lane; c < C; c += 32) {
        float v = hr[c];
        s += v * a_src[hh * C + c];
        d += v * a_dst[hh * C + c];
    }
#pragma unroll
    for (int o = 16; o > 0; o >>= 1) {
        s += __shfl_xor_sync(0xffffffffu, s, o);
        d += __shfl_xor_sync(0xffffffffu, d, o);
    }
    if (lane == 0) { g_es[i * H + hh] = s; g_ed[i * H + hh] = d; }
}

// ---------------- segment softmax over dst-CSR rows --------------------------
__global__ void softmax_kernel(int H) {
    int idx = blockIdx.x * blockDim.x + threadIdx.x;
    if (idx >= NN * H) return;
    int i = idx % NN;
    int hh = idx / NN;
    float edi = g_ed[i * H + hh];
    int p0 = g_rowptr[i], p1 = g_rowptr[i + 1];
    float m = -1e30f;
    for (int p = p0; p < p1; p++) {
        float e = g_es[g_csrsrc[p] * H + hh] + edi;
        e = (e > 0.f) ? e : 0.2f * e;
        m = fmaxf(m, e);
    }
    float den = 0.f;
    for (int p = p0; p < p1; p++) {
        float e = g_es[g_csrsrc[p] * H + hh] + edi;
        e = (e > 0.f) ? e : 0.2f * e;
        float a = expf(e - m);
        g_alpha[p * 4 + hh] = a;
        den += a;
    }
    float inv = 1.f / den;
    for (int p = p0; p < p1; p++) g_alpha[p * 4 + hh] *= inv;
}

// ---------------- weighted aggregation (float4) ------------------------------
// MODE 0: concat heads + bias + ELU, write fp16 hi/lo split (next GEMM input).
// MODE 1: mean over 2 heads + bias, write fp32.
template <int HC, int MODE>
__global__ void aggregate_kernel(const float* __restrict__ hmat,
                                 const float* __restrict__ bias,
                                 float* __restrict__ outF,
                                 uint16_t* __restrict__ outH,
                                 uint16_t* __restrict__ outL) {
    constexpr int PT = HC / 1024;
    int i = blockIdx.x;
    int t = threadIdx.x;
    int hsel = t >> 7;
    float4 acc[PT];
#pragma unroll
    for (int k = 0; k < PT; k++) acc[k] = make_float4(0.f, 0.f, 0.f, 0.f);

    int p0 = g_rowptr[i], p1 = g_rowptr[i + 1];
    for (int p = p0; p < p1; p++) {
        int s = g_csrsrc[p];
        float4 a4 = *(const float4*)(g_alpha + p * 4);
        const float* al = (const float*)&a4;
        const float4* hr = (const float4*)(hmat + (size_t)s * HC);
#pragma unroll
        for (int k = 0; k < PT; k++) {
            float av = al[2 * k + hsel];
            float4 h = hr[t + k * 256];
            acc[k].x += av * h.x;
            acc[k].y += av * h.y;
            acc[k].z += av * h.z;
            acc[k].w += av * h.w;
        }
    }

    if (MODE == 0) {
#pragma unroll
        for (int k = 0; k < PT; k++) {
            int col4 = t + k * 256;
            float4 b = *(const float4*)(bias + col4 * 4);
            float4 v = acc[k];
            v.x += b.x; v.y += b.y; v.z += b.z; v.w += b.w;
            v.x = (v.x > 0.f) ? v.x : (expf(v.x) - 1.f);
            v.y = (v.y > 0.f) ? v.y : (expf(v.y) - 1.f);
            v.z = (v.z > 0.f) ? v.z : (expf(v.z) - 1.f);
            v.w = (v.w > 0.f) ? v.w : (expf(v.w) - 1.f);
            __half h0 = __float2half(v.x), h1 = __float2half(v.y);
            __half h2 = __float2half(v.z), h3 = __float2half(v.w);
            size_t o2 = ((size_t)i * HC + col4 * 4) >> 1;
            ((__half2*)outH)[o2]     = __halves2half2(h0, h1);
            ((__half2*)outH)[o2 + 1] = __halves2half2(h2, h3);
            ((__half2*)outL)[o2] = __halves2half2(
                __float2half(v.x - __half2float(h0)),
                __float2half(v.y - __half2float(h1)));
            ((__half2*)outL)[o2 + 1] = __halves2half2(
                __float2half(v.z - __half2float(h2)),
                __float2half(v.w - __half2float(h3)));
        }
    } else {
        __shared__ float4 sh[256];
        sh[t] = acc[0];
        __syncthreads();
        if (t < 128) {
            float4 v0 = sh[t], v1 = sh[t + 128];
            float4 b = ((const float4*)bias)[t];
            float4 r;
            r.x = 0.5f * (v0.x + v1.x) + b.x;
            r.y = 0.5f * (v0.y + v1.y) + b.y;
            r.z = 0.5f * (v0.z + v1.z) + b.z;
            r.w = 0.5f * (v0.w + v1.w) + b.w;
            ((float4*)outF)[(size_t)i * 128 + t] = r;
        }
    }
}

// ---------------- host launch helpers ----------------------------------------
#define GSMEM3 (3 * 4 * GT)   // 196608
#define GSMEM2 (3 * 3 * GT)   // 147456

static void run_gemm3_f32(const uint16_t* ah, const uint16_t* al,
                          const uint16_t* wh, const uint16_t* wl,
                          const float* bias, float* C, int M, int N, int K) {
    dim3 grid(N / 128, (M + 127) / 128);
    gemm_mma_kernel<3, 0><<<grid, 256, GSMEM3>>>(ah, al, wh, wl, bias, C, nullptr, nullptr, M, N, K);
}
static void run_gemm3_split(const uint16_t* ah, const uint16_t* al,
                            const uint16_t* wh, const uint16_t* wl,
                            const float* bias, uint16_t* ch, uint16_t* cl,
                            int M, int N, int K) {
    dim3 grid(N / 128, (M + 127) / 128);
    gemm_mma_kernel<3, 1><<<grid, 256, GSMEM3>>>(ah, al, wh, wl, bias, nullptr, ch, cl, M, N, K);
}
static void run_gemm2_f32(const uint16_t* ah, const uint16_t* al,
                          const uint16_t* wh,
                          const float* bias, float* C, int M, int N, int K) {
    dim3 grid(N / 128, (M + 127) / 128);
    gemm_mma_kernel<2, 0><<<grid, 256, GSMEM2>>>(ah, al, wh, nullptr, bias, C, nullptr, nullptr, M, N, K);
}

extern "C" void kernel_launch(void* const* d_in, const int* in_sizes, int n_in,
                              void* d_out, int out_size) {
    const float* x      = (const float*)d_in[0];
    const void*  ei     = d_in[1];
    const float* proj_w = (const float*)d_in[2];
    const float* proj_b = (const float*)d_in[3];
    const float* w1  = (const float*)d_in[4];
    const float* as1 = (const float*)d_in[5];
    const float* ad1 = (const float*)d_in[6];
    const float* b1  = (const float*)d_in[7];
    const float* w2  = (const float*)d_in[8];
    const float* as2 = (const float*)d_in[9];
    const float* ad2 = (const float*)d_in[10];
    const float* b2  = (const float*)d_in[11];
    const float* w3  = (const float*)d_in[12];
    const float* as3 = (const float*)d_in[13];
    const float* ad3 = (const float*)d_in[14];
    const float* b3  = (const float*)d_in[15];
    float* out = (float*)d_out;

    float* hmat;
    uint16_t *P0h, *P0l, *P1h, *P1l, *Wh, *Wl;
    cudaGetSymbolAddress((void**)&hmat, g_hmat);
    cudaGetSymbolAddress((void**)&P0h, g_P0h);
    cudaGetSymbolAddress((void**)&P0l, g_P0l);
    cudaGetSymbolAddress((void**)&P1h, g_P1h);
    cudaGetSymbolAddress((void**)&P1l, g_P1l);
    cudaGetSymbolAddress((void**)&Wh, g_Wh);
    cudaGetSymbolAddress((void**)&Wl, g_Wl);

    static bool attr_set = false;
    if (!attr_set) {
        cudaFuncSetAttribute((const void*)gemm_mma_kernel<3, 0>,
                             cudaFuncAttributeMaxDynamicSharedMemorySize, GSMEM3);
        cudaFuncSetAttribute((const void*)gemm_mma_kernel<3, 1>,
                             cudaFuncAttributeMaxDynamicSharedMemorySize, GSMEM3);
        cudaFuncSetAttribute((const void*)gemm_mma_kernel<2, 0>,
                             cudaFuncAttributeMaxDynamicSharedMemorySize, GSMEM2);
        attr_set = true;
    }

    // our idx 0-2: input split, proj_w transpose, detect/init
    cvt_split_kernel<<<(NN * 256 / 4 + 255) / 256, 256>>>(x, P0h, P0l, NN * 256 / 4);
    cvt_transpose_bf16_kernel<<<dim3(512 / 32, 256 / 32), dim3(32, 8)>>>(proj_w, Wh, Wl, 256, 512);
    detect_init_kernel<<<(NN + 255) / 256, 256>>>((const unsigned int*)ei);
    // our idx 3: proj GEMM  <-- ncu -s 5 -c 1 profiles this launch
    run_gemm3_split(P0h, P0l, Wh, Wl, proj_b, P1h, P1l, NN, 512, 256);
    // CSR build (independent of GEMM chain)
    count_kernel<<<(EE + 255) / 256, 256>>>(ei);
    scan_fillself_kernel<<<1, 1024>>>();
    filledges_kernel<<<(EE + 255) / 256, 256>>>(ei);

    // ---- GAT layer 1 (H=4, C=512, concat, ELU): bf16 3-pass, N=2048, K=512 ----
    cvt_transpose_bf16_kernel<<<dim3(2048 / 32, 512 / 32), dim3(32, 8)>>>(w1, Wh, Wl, 512, 2048);
    run_gemm3_f32(P1h, P1l, Wh, Wl, nullptr, hmat, NN, 2048, 512);
    attn_kernel<<<NN, 128>>>(hmat, as1, ad1, 4);
    softmax_kernel<<<(NN * 4 + 255) / 256, 256>>>(4);
    aggregate_kernel<2048, 0><<<NN, 256>>>(hmat, b1, nullptr, P0h, P0l);

    // ---- GAT layer 2 (H=4, C=512, concat, ELU): fp16 2-pass, N=2048, K=2048 ----
    cvt_transpose_f16_kernel<<<dim3(2048 / 32, 2048 / 32), dim3(32, 8)>>>(w2, Wh, 2048, 2048);
    run_gemm2_f32(P0h, P0l, Wh, nullptr, hmat, NN, 2048, 2048);
    attn_kernel<<<NN, 128>>>(hmat, as2, ad2, 4);
    softmax_kernel<<<(NN * 4 + 255) / 256, 256>>>(4);
    aggregate_kernel<2048, 0><<<NN, 256>>>(hmat, b2, nullptr, P1h, P1l);

    // ---- GAT layer 3 (H=2, C=512, mean): fp16 2-pass, N=1024, K=2048 ----
    cvt_transpose_f16_kernel<<<dim3(1024 / 32, 2048 / 32), dim3(32, 8)>>>(w3, Wh, 2048, 1024);
    run_gemm2_f32(P1h, P1l, Wh, nullptr, hmat, NN, 1024, 2048);
    attn_kernel<<<NN, 64>>>(hmat, as3, ad3, 2);
    softmax_kernel<<<(NN * 2 + 255) / 256, 256>>>(2);
    aggregate_kernel<1024, 1><<<NN, 256>>>(hmat, b3, out, nullptr, nullptr);
}

// round 6
// speedup vs baseline: 1.2469x; 1.2469x over previous
#include <cuda_runtime.h>
#include <cuda_bf16.h>
#include <math.h>
#include <stdint.h>

#define NN 10000
#define EE 160000
#define ET 170000   // edges + self loops

// ---------------- scratch (device globals; no allocations allowed) ----------
__device__ float g_hmat[NN * 2048];
__device__ float g_es  [NN * 4];
__device__ float g_ed  [NN * 4];
__device__ float g_alpha[ET * 4];
__device__ int   g_counts [NN];
__device__ int   g_rowptr [NN + 1];
__device__ int   g_fillpos[NN];
__device__ int   g_csrsrc [ET];
__device__ int   g_is64;
// bf16 hi/lo activation pairs (ping-pong) + weight pair
__device__ __align__(16) __nv_bfloat16 g_P0h[NN * 2048];
__device__ __align__(16) __nv_bfloat16 g_P0l[NN * 2048];
__device__ __align__(16) __nv_bfloat16 g_P1h[NN * 2048];
__device__ __align__(16) __nv_bfloat16 g_P1l[NN * 2048];
__device__ __align__(16) __nv_bfloat16 g_Wh[2048 * 2048];
__device__ __align__(16) __nv_bfloat16 g_Wl[2048 * 2048];

// ============================ PTX helpers (baseline, sm_80+) =================
__device__ __forceinline__ uint32_t smem_to_u32(const void* p) {
    uint32_t a;
    asm("{ .reg .u64 t; cvta.to.shared.u64 t, %1; cvt.u32.u64 %0, t; }" : "=r"(a) : "l"(p));
    return a;
}

__device__ __forceinline__ void cp16(uint32_t dst, const void* src, bool v) {
    int sz = v ? 16 : 0;
    asm volatile("cp.async.cg.shared.global [%0], [%1], 16, %2;\n"
                 :: "r"(dst), "l"(src), "r"(sz) : "memory");
}
#define CP_COMMIT() asm volatile("cp.async.commit_group;" ::: "memory")
#define CP_WAIT1()  asm volatile("cp.async.wait_group 1;" ::: "memory")

__device__ __forceinline__ void ldsm4(uint32_t* r, uint32_t addr) {
    asm volatile("ldmatrix.sync.aligned.m8n8.x4.shared.b16 {%0,%1,%2,%3}, [%4];"
                 : "=r"(r[0]), "=r"(r[1]), "=r"(r[2]), "=r"(r[3]) : "r"(addr));
}

__device__ __forceinline__ void mma_bf16(float* c, const uint32_t* a, const uint32_t* b) {
    asm volatile(
        "mma.sync.aligned.m16n8k16.row.col.f32.bf16.bf16.f32 "
        "{%0,%1,%2,%3}, {%4,%5,%6,%7}, {%8,%9}, {%0,%1,%2,%3};"
        : "+f"(c[0]), "+f"(c[1]), "+f"(c[2]), "+f"(c[3])
        : "r"(a[0]), "r"(a[1]), "r"(a[2]), "r"(a[3]), "r"(b[0]), "r"(b[1]));
}

__device__ __forceinline__ int edge_at(const void* ei, long long idx) {
    if (g_is64) return (int)((const long long*)ei)[idx];
    return ((const int*)ei)[idx];
}

// ---------------- CSR build ---------------------------------------------------
__global__ void detect_init_kernel(const unsigned int* p) {
    int i = blockIdx.x * blockDim.x + threadIdx.x;
    if (i < NN) g_counts[i] = 1;           // self loop pre-counted
    if (i == 0) {
        int is64 = 1;
        for (int j = 0; j < 128; j++)
            if (p[2 * j + 1] != 0u) { is64 = 0; break; }
        g_is64 = is64;
    }
}
__global__ void count_kernel(const void* ei) {
    int e = blockIdx.x * blockDim.x + threadIdx.x;
    if (e < EE) atomicAdd(&g_counts[edge_at(ei, (long long)EE + e)], 1);
}
__global__ void scan_fillself_kernel() {
    __shared__ int sh[1024];
    int t = threadIdx.x;
    const int chunk = (NN + 1023) >> 10;
    int base = t * chunk;
    int s = 0;
    for (int j = 0; j < chunk; j++) { int idx = base + j; if (idx < NN) s += g_counts[idx]; }
    sh[t] = s;
    __syncthreads();
    for (int off = 1; off < 1024; off <<= 1) {
        int v = (t >= off) ? sh[t - off] : 0;
        __syncthreads();
        sh[t] += v;
        __syncthreads();
    }
    int prefix = (t > 0) ? sh[t - 1] : 0;
    for (int j = 0; j < chunk; j++) {
        int idx = base + j;
        if (idx < NN) { g_rowptr[idx] = prefix; prefix += g_counts[idx]; }
    }
    if (t == 0) g_rowptr[NN] = sh[1023];
    __syncthreads();
    for (int idx = t; idx < NN; idx += 1024) {
        int r = g_rowptr[idx];
        g_csrsrc[r] = idx;
        g_fillpos[idx] = r + 1;
    }
}
__global__ void filledges_kernel(const void* ei) {
    int e = blockIdx.x * blockDim.x + threadIdx.x;
    if (e < EE) {
        int s = edge_at(ei, e);
        int d = edge_at(ei, (long long)EE + e);
        g_csrsrc[atomicAdd(&g_fillpos[d], 1)] = s;
    }
}

// ---------------- fp32 -> bf16 hi/lo split (input x only) --------------------
__global__ void cvt_split_kernel(const float* __restrict__ x,
                                 __nv_bfloat16* __restrict__ hi,
                                 __nv_bfloat16* __restrict__ lo, int n4) {
    int i = blockIdx.x * blockDim.x + threadIdx.x;
    if (i >= n4) return;
    float4 v = ((const float4*)x)[i];
    __nv_bfloat16 h0 = __float2bfloat16(v.x);
    __nv_bfloat16 h1 = __float2bfloat16(v.y);
    __nv_bfloat16 h2 = __float2bfloat16(v.z);
    __nv_bfloat16 h3 = __float2bfloat16(v.w);
    __nv_bfloat16 l0 = __float2bfloat16(v.x - __bfloat162float(h0));
    __nv_bfloat16 l1 = __float2bfloat16(v.y - __bfloat162float(h1));
    __nv_bfloat16 l2 = __float2bfloat16(v.z - __bfloat162float(h2));
    __nv_bfloat16 l3 = __float2bfloat16(v.w - __bfloat162float(h3));
    ((__nv_bfloat162*)hi)[2 * i]     = __nv_bfloat162(h0, h1);
    ((__nv_bfloat162*)hi)[2 * i + 1] = __nv_bfloat162(h2, h3);
    ((__nv_bfloat162*)lo)[2 * i]     = __nv_bfloat162(l0, l1);
    ((__nv_bfloat162*)lo)[2 * i + 1] = __nv_bfloat162(l2, l3);
}

// ---------------- weight transpose + split: W[K,N] -> Wt[N,K] hi/lo ----------
__global__ void cvt_transpose_kernel(const float* __restrict__ W,
                                     __nv_bfloat16* __restrict__ th,
                                     __nv_bfloat16* __restrict__ tl, int K, int N) {
    __shared__ float tile[32][33];
    int n0 = blockIdx.x * 32, k0 = blockIdx.y * 32;
    int tx = threadIdx.x, ty = threadIdx.y;   // 32 x 8
    for (int r = ty; r < 32; r += 8)
        tile[r][tx] = W[(size_t)(k0 + r) * N + n0 + tx];
    __syncthreads();
    for (int r = ty; r < 32; r += 8) {
        float v = tile[tx][r];
        __nv_bfloat16 h = __float2bfloat16(v);
        size_t o = (size_t)(n0 + r) * K + k0 + tx;
        th[o] = h;
        tl[o] = __float2bfloat16(v - __bfloat162float(h));
    }
}

// ---------------- mma.sync bf16x3 GEMM: C = A[M,K] @ Bt[N,K]^T (+bias) -------
// CTA 128x128, BK=64, 3-stage cp.async pipeline, 512 threads / 16 warps (4x4),
// warp tile 32x32. 3-pass bf16 hi/lo (Ah*Bh + Ah*Bl + Al*Bh).
// EPI 0: fp32 out (+bias). EPI 1: bf16 hi/lo split out (+bias).
#define GT 16384                      // one operand tile: 128 rows x 128B
#define GSTAGE (4 * GT)               // Ah, Al, Bh, Bl = 65536
#define GSMEM  (3 * GSTAGE)           // 196608

__device__ __forceinline__ uint32_t swz(uint32_t base, int row, int kelem) {
    return base + row * 128 + ((((kelem >> 3) ^ row) & 7) << 4);
}

template <int EPI>
__global__ void __launch_bounds__(512, 1) gemm_mma_kernel(
    const __nv_bfloat16* __restrict__ Ah, const __nv_bfloat16* __restrict__ Al,
    const __nv_bfloat16* __restrict__ Bh, const __nv_bfloat16* __restrict__ Bl,
    const float* __restrict__ bias, float* __restrict__ Cf,
    __nv_bfloat16* __restrict__ Ch, __nv_bfloat16* __restrict__ Cl,
    int M, int N, int K)
{
    extern __shared__ char smem[];
    const uint32_t sb = smem_to_u32(smem);
    const int tid = threadIdx.x;
    const int lane = tid & 31, wid = tid >> 5;
    const int m0 = blockIdx.y * 128, n0 = blockIdx.x * 128;
    const int nk = K >> 6;

    auto load_stage = [&](int s, int j) {
        const uint32_t sbase = sb + (uint32_t)s * GSTAGE;
        const int lchk = tid & 7;           // 16B chunk in 128B row
        const int lrow = tid >> 3;          // 0..63
        const bool jv = (j < nk);
        const long long k0 = jv ? ((long long)j << 6) : 0;
#pragma unroll
        for (int it = 0; it < 2; it++) {
            int row = lrow + it * 64;
            bool av = jv && (m0 + row < M);
            int gr = (m0 + row < M) ? (m0 + row) : 0;
            size_t aoff = (size_t)gr * K + k0 + lchk * 8;
            size_t boff = (size_t)(n0 + row) * K + k0 + lchk * 8;
            uint32_t d = swz(sbase, row, lchk * 8);
            cp16(d,      Ah + aoff, av);
            cp16(d + GT, Al + aoff, av);
            uint32_t db = swz(sbase + 2 * GT, row, lchk * 8);
            cp16(db,      Bh + boff, jv);
            cp16(db + GT, Bl + boff, jv);
        }
    };

    float acc[2][4][4];
#pragma unroll
    for (int a = 0; a < 2; a++)
#pragma unroll
        for (int b = 0; b < 4; b++)
#pragma unroll
            for (int c = 0; c < 4; c++) acc[a][b][c] = 0.f;

    load_stage(0, 0);
    CP_COMMIT();
    load_stage(1, 1);
    CP_COMMIT();

    const int mw = (wid & 3) * 32;      // warp M offset (4 rows of warps)
    const int nw = (wid >> 2) * 32;     // warp N offset (4 cols of warps)
    const int rsel = lane & 15;
    const int khalf = (lane >> 4) * 8;

    for (int i = 0; i < nk; i++) {
        CP_WAIT1();
        __syncthreads();
        load_stage((i + 2) % 3, i + 2);   // zero-fill past end
        CP_COMMIT();

        const uint32_t sA = sb + (uint32_t)(i % 3) * GSTAGE;
        const uint32_t sB = sA + 2 * GT;
#pragma unroll
        for (int ks = 0; ks < 4; ks++) {
            const int ke = ks * 16 + khalf;
            uint32_t ah[2][4], al[2][4], bh[2][4], bl[2][4];
#pragma unroll
            for (int mi = 0; mi < 2; mi++) {
                uint32_t ad = swz(sA, mw + mi * 16 + rsel, ke);
                ldsm4(ah[mi], ad);
                ldsm4(al[mi], ad + GT);
            }
#pragma unroll
            for (int bi = 0; bi < 2; bi++) {
                uint32_t bd = swz(sB, nw + bi * 16 + rsel, ke);
                ldsm4(bh[bi], bd);
                ldsm4(bl[bi], bd + GT);
            }
#pragma unroll
            for (int mi = 0; mi < 2; mi++) {
#pragma unroll
                for (int nj = 0; nj < 4; nj++) {
                    uint32_t b2h[2] = { bh[nj >> 1][nj & 1], bh[nj >> 1][(nj & 1) + 2] };
                    uint32_t b2l[2] = { bl[nj >> 1][nj & 1], bl[nj >> 1][(nj & 1) + 2] };
                    mma_bf16(acc[mi][nj], ah[mi], b2h);
                    mma_bf16(acc[mi][nj], ah[mi], b2l);
                    mma_bf16(acc[mi][nj], al[mi], b2h);
                }
            }
        }
        __syncthreads();
    }

    // epilogue
#pragma unroll
    for (int mi = 0; mi < 2; mi++) {
#pragma unroll
        for (int nj = 0; nj < 4; nj++) {
            int col = n0 + nw + nj * 8 + (lane & 3) * 2;
            float bx = 0.f, by = 0.f;
            if (bias) { bx = bias[col]; by = bias[col + 1]; }
            int r0 = m0 + mw + mi * 16 + (lane >> 2);
            int r1 = r0 + 8;
            if (EPI == 0) {
                if (r0 < M)
                    *(float2*)(Cf + (size_t)r0 * N + col) =
                        make_float2(acc[mi][nj][0] + bx, acc[mi][nj][1] + by);
                if (r1 < M)
                    *(float2*)(Cf + (size_t)r1 * N + col) =
                        make_float2(acc[mi][nj][2] + bx, acc[mi][nj][3] + by);
            } else {
                if (r0 < M) {
                    float v0 = acc[mi][nj][0] + bx, v1 = acc[mi][nj][1] + by;
                    __nv_bfloat16 h0 = __float2bfloat16(v0), h1 = __float2bfloat16(v1);
                    size_t o = ((size_t)r0 * N + col) >> 1;
                    ((__nv_bfloat162*)Ch)[o] = __nv_bfloat162(h0, h1);
                    ((__nv_bfloat162*)Cl)[o] = __nv_bfloat162(
                        __float2bfloat16(v0 - __bfloat162float(h0)),
                        __float2bfloat16(v1 - __bfloat162float(h1)));
                }
                if (r1 < M) {
                    float v0 = acc[mi][nj][2] + bx, v1 = acc[mi][nj][3] + by;
                    __nv_bfloat16 h0 = __float2bfloat16(v0), h1 = __float2bfloat16(v1);
                    size_t o = ((size_t)r1 * N + col) >> 1;
                    ((__nv_bfloat162*)Ch)[o] = __nv_bfloat162(h0, h1);
                    ((__nv_bfloat162*)Cl)[o] = __nv_bfloat162(
                        __float2bfloat16(v0 - __bfloat162float(h0)),
                        __float2bfloat16(v1 - __bfloat162float(h1)));
                }
            }
        }
    }
}

// ---------------- per-node attention coefficients es/ed ----------------------
__global__ void attn_kernel(const float* __restrict__ hmat,
                            const float* __restrict__ a_src,
                            const float* __restrict__ a_dst, int H) {
    const int C = 512;
    int i = blockIdx.x;
    int hh = threadIdx.x >> 5;
    int lane = threadIdx.x & 31;
    const float* hr = hmat + (size_t)i * H * C + hh * C;
    float s = 0.f, d = 0.f;
    for (int c = lane; c < C; c += 32) {
        float v = hr[c];
        s += v * a_src[hh * C + c];
        d += v * a_dst[hh * C + c];
    }
#pragma unroll
    for (int o = 16; o > 0; o >>= 1) {
        s += __shfl_xor_sync(0xffffffffu, s, o);
        d += __shfl_xor_sync(0xffffffffu, d, o);
    }
    if (lane == 0) { g_es[i * H + hh] = s; g_ed[i * H + hh] = d; }
}

// ---------------- segment softmax over dst-CSR rows --------------------------
__global__ void softmax_kernel(int H) {
    int idx = blockIdx.x * blockDim.x + threadIdx.x;
    if (idx >= NN * H) return;
    int i = idx % NN;
    int hh = idx / NN;
    float edi = g_ed[i * H + hh];
    int p0 = g_rowptr[i], p1 = g_rowptr[i + 1];
    float m = -1e30f;
    for (int p = p0; p < p1; p++) {
        float e = g_es[g_csrsrc[p] * H + hh] + edi;
        e = (e > 0.f) ? e : 0.2f * e;
        m = fmaxf(m, e);
    }
    float den = 0.f;
    for (int p = p0; p < p1; p++) {
        float e = g_es[g_csrsrc[p] * H + hh] + edi;
        e = (e > 0.f) ? e : 0.2f * e;
        float a = expf(e - m);
        g_alpha[p * 4 + hh] = a;
        den += a;
    }
    float inv = 1.f / den;
    for (int p = p0; p < p1; p++) g_alpha[p * 4 + hh] *= inv;
}

// ---------------- weighted aggregation (float4) ------------------------------
// MODE 0: concat heads + bias + ELU, write bf16 hi/lo split (next GEMM input).
// MODE 1: mean over 2 heads + bias, write fp32.
template <int HC, int MODE>
__global__ void aggregate_kernel(const float* __restrict__ hmat,
                                 const float* __restrict__ bias,
                                 float* __restrict__ outF,
                                 __nv_bfloat16* __restrict__ outH,
                                 __nv_bfloat16* __restrict__ outL) {
    constexpr int PT = HC / 1024;
    int i = blockIdx.x;
    int t = threadIdx.x;
    int hsel = t >> 7;
    float4 acc[PT];
#pragma unroll
    for (int k = 0; k < PT; k++) acc[k] = make_float4(0.f, 0.f, 0.f, 0.f);

    int p0 = g_rowptr[i], p1 = g_rowptr[i + 1];
    for (int p = p0; p < p1; p++) {
        int s = g_csrsrc[p];
        float4 a4 = *(const float4*)(g_alpha + p * 4);
        const float* al = (const float*)&a4;
        const float4* hr = (const float4*)(hmat + (size_t)s * HC);
#pragma unroll
        for (int k = 0; k < PT; k++) {
            float av = al[2 * k + hsel];
            float4 h = hr[t + k * 256];
            acc[k].x += av * h.x;
            acc[k].y += av * h.y;
            acc[k].z += av * h.z;
            acc[k].w += av * h.w;
        }
    }

    if (MODE == 0) {
#pragma unroll
        for (int k = 0; k < PT; k++) {
            int col4 = t + k * 256;
            float4 b = *(const float4*)(bias + col4 * 4);
            float4 v = acc[k];
            v.x += b.x; v.y += b.y; v.z += b.z; v.w += b.w;
            v.x = (v.x > 0.f) ? v.x : (expf(v.x) - 1.f);
            v.y = (v.y > 0.f) ? v.y : (expf(v.y) - 1.f);
            v.z = (v.z > 0.f) ? v.z : (expf(v.z) - 1.f);
            v.w = (v.w > 0.f) ? v.w : (expf(v.w) - 1.f);
            __nv_bfloat16 h0 = __float2bfloat16(v.x), h1 = __float2bfloat16(v.y);
            __nv_bfloat16 h2 = __float2bfloat16(v.z), h3 = __float2bfloat16(v.w);
            size_t o2 = ((size_t)i * HC + col4 * 4) >> 1;
            ((__nv_bfloat162*)outH)[o2]     = __nv_bfloat162(h0, h1);
            ((__nv_bfloat162*)outH)[o2 + 1] = __nv_bfloat162(h2, h3);
            ((__nv_bfloat162*)outL)[o2] = __nv_bfloat162(
                __float2bfloat16(v.x - __bfloat162float(h0)),
                __float2bfloat16(v.y - __bfloat162float(h1)));
            ((__nv_bfloat162*)outL)[o2 + 1] = __nv_bfloat162(
                __float2bfloat16(v.z - __bfloat162float(h2)),
                __float2bfloat16(v.w - __bfloat162float(h3)));
        }
    } else {
        __shared__ float4 sh[256];
        sh[t] = acc[0];
        __syncthreads();
        if (t < 128) {
            float4 v0 = sh[t], v1 = sh[t + 128];
            float4 b = ((const float4*)bias)[t];
            float4 r;
            r.x = 0.5f * (v0.x + v1.x) + b.x;
            r.y = 0.5f * (v0.y + v1.y) + b.y;
            r.z = 0.5f * (v0.z + v1.z) + b.z;
            r.w = 0.5f * (v0.w + v1.w) + b.w;
            ((float4*)outF)[(size_t)i * 128 + t] = r;
        }
    }
}

// ---------------- host launch helpers ----------------------------------------
static void run_gemm_f32(const __nv_bfloat16* ah, const __nv_bfloat16* al,
                         const __nv_bfloat16* wh, const __nv_bfloat16* wl,
                         const float* bias, float* C, int M, int N, int K) {
    dim3 grid(N / 128, (M + 127) / 128);
    gemm_mma_kernel<0><<<grid, 512, GSMEM>>>(ah, al, wh, wl, bias, C, nullptr, nullptr, M, N, K);
}
static void run_gemm_split(const __nv_bfloat16* ah, const __nv_bfloat16* al,
                           const __nv_bfloat16* wh, const __nv_bfloat16* wl,
                           const float* bias, __nv_bfloat16* ch, __nv_bfloat16* cl,
                           int M, int N, int K) {
    dim3 grid(N / 128, (M + 127) / 128);
    gemm_mma_kernel<1><<<grid, 512, GSMEM>>>(ah, al, wh, wl, bias, nullptr, ch, cl, M, N, K);
}

extern "C" void kernel_launch(void* const* d_in, const int* in_sizes, int n_in,
                              void* d_out, int out_size) {
    const float* x      = (const float*)d_in[0];
    const void*  ei     = d_in[1];
    const float* proj_w = (const float*)d_in[2];
    const float* proj_b = (const float*)d_in[3];
    const float* w1  = (const float*)d_in[4];
    const float* as1 = (const float*)d_in[5];
    const float* ad1 = (const float*)d_in[6];
    const float* b1  = (const float*)d_in[7];
    const float* w2  = (const float*)d_in[8];
    const float* as2 = (const float*)d_in[9];
    const float* ad2 = (const float*)d_in[10];
    const float* b2  = (const float*)d_in[11];
    const float* w3  = (const float*)d_in[12];
    const float* as3 = (const float*)d_in[13];
    const float* ad3 = (const float*)d_in[14];
    const float* b3  = (const float*)d_in[15];
    float* out = (float*)d_out;

    float* hmat;
    __nv_bfloat16 *P0h, *P0l, *P1h, *P1l, *Wh, *Wl;
    cudaGetSymbolAddress((void**)&hmat, g_hmat);
    cudaGetSymbolAddress((void**)&P0h, g_P0h);
    cudaGetSymbolAddress((void**)&P0l, g_P0l);
    cudaGetSymbolAddress((void**)&P1h, g_P1h);
    cudaGetSymbolAddress((void**)&P1l, g_P1l);
    cudaGetSymbolAddress((void**)&Wh, g_Wh);
    cudaGetSymbolAddress((void**)&Wl, g_Wl);

    static bool attr_set = false;
    if (!attr_set) {
        cudaFuncSetAttribute((const void*)gemm_mma_kernel<0>,
                             cudaFuncAttributeMaxDynamicSharedMemorySize, GSMEM);
        cudaFuncSetAttribute((const void*)gemm_mma_kernel<1>,
                             cudaFuncAttributeMaxDynamicSharedMemorySize, GSMEM);
        attr_set = true;
    }

    // our idx 0-2: input split, proj_w transpose, detect/init
    cvt_split_kernel<<<(NN * 256 / 4 + 255) / 256, 256>>>(x, P0h, P0l, NN * 256 / 4);
    cvt_transpose_kernel<<<dim3(512 / 32, 256 / 32), dim3(32, 8)>>>(proj_w, Wh, Wl, 256, 512);
    detect_init_kernel<<<(NN + 255) / 256, 256>>>((const unsigned int*)ei);
    // our idx 3: proj GEMM  <-- ncu -s 5 -c 1 profiles this launch
    run_gemm_split(P0h, P0l, Wh, Wl, proj_b, P1h, P1l, NN, 512, 256);
    // CSR build (independent of GEMM chain)
    count_kernel<<<(EE + 255) / 256, 256>>>(ei);
    scan_fillself_kernel<<<1, 1024>>>();
    filledges_kernel<<<(EE + 255) / 256, 256>>>(ei);

    // ---- GAT layer 1 (H=4, C=512, concat, ELU): N=2048, K=512 ----
    cvt_transpose_kernel<<<dim3(2048 / 32, 512 / 32), dim3(32, 8)>>>(w1, Wh, Wl, 512, 2048);
    run_gemm_f32(P1h, P1l, Wh, Wl, nullptr, hmat, NN, 2048, 512);
    attn_kernel<<<NN, 128>>>(hmat, as1, ad1, 4);
    softmax_kernel<<<(NN * 4 + 255) / 256, 256>>>(4);
    aggregate_kernel<2048, 0><<<NN, 256>>>(hmat, b1, nullptr, P0h, P0l);

    // ---- GAT layer 2 (H=4, C=512, concat, ELU): N=2048, K=2048 ----
    cvt_transpose_kernel<<<dim3(2048 / 32, 2048 / 32), dim3(32, 8)>>>(w2, Wh, Wl, 2048, 2048);
    run_gemm_f32(P0h, P0l, Wh, Wl, nullptr, hmat, NN, 2048, 2048);
    attn_kernel<<<NN, 128>>>(hmat, as2, ad2, 4);
    softmax_kernel<<<(NN * 4 + 255) / 256, 256>>>(4);
    aggregate_kernel<2048, 0><<<NN, 256>>>(hmat, b2, nullptr, P1h, P1l);

    // ---- GAT layer 3 (H=2, C=512, mean): N=1024, K=2048 ----
    cvt_transpose_kernel<<<dim3(1024 / 32, 2048 / 32), dim3(32, 8)>>>(w3, Wh, Wl, 2048, 1024);
    run_gemm_f32(P1h, P1l, Wh, Wl, nullptr, hmat, NN, 1024, 2048);
    attn_kernel<<<NN, 64>>>(hmat, as3, ad3, 2);
    softmax_kernel<<<(NN * 2 + 255) / 256, 256>>>(2);
    aggregate_kernel<1024, 1><<<NN, 256>>>(hmat, b3, out, nullptr, nullptr);
}

// round 7
// speedup vs baseline: 1.2562x; 1.0075x over previous
#include <cuda_runtime.h>
#include <cuda_bf16.h>
#include <math.h>
#include <stdint.h>

#define NN 10000
#define EE 160000
#define ET 170000   // edges + self loops

// ---------------- scratch (device globals; no allocations allowed) ----------
__device__ float g_hmat[NN * 2048];
__device__ float g_es  [NN * 4];
__device__ float g_ed  [NN * 4];
__device__ float g_alpha[ET * 4];
__device__ int   g_counts [NN];
__device__ int   g_rowptr [NN + 1];
__device__ int   g_fillpos[NN];
__device__ int   g_csrsrc [ET];
__device__ int   g_is64;
// bf16 hi/lo activation pairs (ping-pong) + weight pair
__device__ __align__(16) __nv_bfloat16 g_P0h[NN * 2048];
__device__ __align__(16) __nv_bfloat16 g_P0l[NN * 2048];
__device__ __align__(16) __nv_bfloat16 g_P1h[NN * 2048];
__device__ __align__(16) __nv_bfloat16 g_P1l[NN * 2048];
__device__ __align__(16) __nv_bfloat16 g_Wh[2048 * 2048];
__device__ __align__(16) __nv_bfloat16 g_Wl[2048 * 2048];

// ============================ PTX helpers (baseline, sm_80+) =================
__device__ __forceinline__ uint32_t smem_to_u32(const void* p) {
    uint32_t a;
    asm("{ .reg .u64 t; cvta.to.shared.u64 t, %1; cvt.u32.u64 %0, t; }" : "=r"(a) : "l"(p));
    return a;
}

__device__ __forceinline__ void cp16(uint32_t dst, const void* src, bool v) {
    int sz = v ? 16 : 0;
    asm volatile("cp.async.cg.shared.global [%0], [%1], 16, %2;\n"
                 :: "r"(dst), "l"(src), "r"(sz) : "memory");
}
#define CP_COMMIT() asm volatile("cp.async.commit_group;" ::: "memory")
#define CP_WAIT1()  asm volatile("cp.async.wait_group 1;" ::: "memory")

__device__ __forceinline__ void ldsm4(uint32_t* r, uint32_t addr) {
    asm volatile("ldmatrix.sync.aligned.m8n8.x4.shared.b16 {%0,%1,%2,%3}, [%4];"
                 : "=r"(r[0]), "=r"(r[1]), "=r"(r[2]), "=r"(r[3]) : "r"(addr));
}

__device__ __forceinline__ void mma_bf16(float* c, const uint32_t* a, const uint32_t* b) {
    asm volatile(
        "mma.sync.aligned.m16n8k16.row.col.f32.bf16.bf16.f32 "
        "{%0,%1,%2,%3}, {%4,%5,%6,%7}, {%8,%9}, {%0,%1,%2,%3};"
        : "+f"(c[0]), "+f"(c[1]), "+f"(c[2]), "+f"(c[3])
        : "r"(a[0]), "r"(a[1]), "r"(a[2]), "r"(a[3]), "r"(b[0]), "r"(b[1]));
}

__device__ __forceinline__ int edge_at(const void* ei, long long idx) {
    if (g_is64) return (int)((const long long*)ei)[idx];
    return ((const int*)ei)[idx];
}

// ---------------- CSR build ---------------------------------------------------
__global__ void detect_init_kernel(const unsigned int* p) {
    int i = blockIdx.x * blockDim.x + threadIdx.x;
    if (i < NN) g_counts[i] = 1;           // self loop pre-counted
    if (i == 0) {
        int is64 = 1;
        for (int j = 0; j < 128; j++)
            if (p[2 * j + 1] != 0u) { is64 = 0; break; }
        g_is64 = is64;
    }
}
__global__ void count_kernel(const void* ei) {
    int e = blockIdx.x * blockDim.x + threadIdx.x;
    if (e < EE) atomicAdd(&g_counts[edge_at(ei, (long long)EE + e)], 1);
}
__global__ void scan_fillself_kernel() {
    __shared__ int sh[1024];
    int t = threadIdx.x;
    const int chunk = (NN + 1023) >> 10;
    int base = t * chunk;
    int s = 0;
    for (int j = 0; j < chunk; j++) { int idx = base + j; if (idx < NN) s += g_counts[idx]; }
    sh[t] = s;
    __syncthreads();
    for (int off = 1; off < 1024; off <<= 1) {
        int v = (t >= off) ? sh[t - off] : 0;
        __syncthreads();
        sh[t] += v;
        __syncthreads();
    }
    int prefix = (t > 0) ? sh[t - 1] : 0;
    for (int j = 0; j < chunk; j++) {
        int idx = base + j;
        if (idx < NN) { g_rowptr[idx] = prefix; prefix += g_counts[idx]; }
    }
    if (t == 0) g_rowptr[NN] = sh[1023];
    __syncthreads();
    for (int idx = t; idx < NN; idx += 1024) {
        int r = g_rowptr[idx];
        g_csrsrc[r] = idx;
        g_fillpos[idx] = r + 1;
    }
}
__global__ void filledges_kernel(const void* ei) {
    int e = blockIdx.x * blockDim.x + threadIdx.x;
    if (e < EE) {
        int s = edge_at(ei, e);
        int d = edge_at(ei, (long long)EE + e);
        g_csrsrc[atomicAdd(&g_fillpos[d], 1)] = s;
    }
}

// ---------------- fp32 -> bf16 hi/lo split (input x only) --------------------
__global__ void cvt_split_kernel(const float* __restrict__ x,
                                 __nv_bfloat16* __restrict__ hi,
                                 __nv_bfloat16* __restrict__ lo, int n4) {
    int i = blockIdx.x * blockDim.x + threadIdx.x;
    if (i >= n4) return;
    float4 v = ((const float4*)x)[i];
    __nv_bfloat16 h0 = __float2bfloat16(v.x);
    __nv_bfloat16 h1 = __float2bfloat16(v.y);
    __nv_bfloat16 h2 = __float2bfloat16(v.z);
    __nv_bfloat16 h3 = __float2bfloat16(v.w);
    __nv_bfloat16 l0 = __float2bfloat16(v.x - __bfloat162float(h0));
    __nv_bfloat16 l1 = __float2bfloat16(v.y - __bfloat162float(h1));
    __nv_bfloat16 l2 = __float2bfloat16(v.z - __bfloat162float(h2));
    __nv_bfloat16 l3 = __float2bfloat16(v.w - __bfloat162float(h3));
    ((__nv_bfloat162*)hi)[2 * i]     = __nv_bfloat162(h0, h1);
    ((__nv_bfloat162*)hi)[2 * i + 1] = __nv_bfloat162(h2, h3);
    ((__nv_bfloat162*)lo)[2 * i]     = __nv_bfloat162(l0, l1);
    ((__nv_bfloat162*)lo)[2 * i + 1] = __nv_bfloat162(l2, l3);
}

// ---------------- weight transpose + split: W[K,N] -> Wt[N,K] hi/lo ----------
__global__ void cvt_transpose_kernel(const float* __restrict__ W,
                                     __nv_bfloat16* __restrict__ th,
                                     __nv_bfloat16* __restrict__ tl, int K, int N) {
    __shared__ float tile[32][33];
    int n0 = blockIdx.x * 32, k0 = blockIdx.y * 32;
    int tx = threadIdx.x, ty = threadIdx.y;   // 32 x 8
    for (int r = ty; r < 32; r += 8)
        tile[r][tx] = W[(size_t)(k0 + r) * N + n0 + tx];
    __syncthreads();
    for (int r = ty; r < 32; r += 8) {
        float v = tile[tx][r];
        __nv_bfloat16 h = __float2bfloat16(v);
        size_t o = (size_t)(n0 + r) * K + k0 + tx;
        th[o] = h;
        tl[o] = __float2bfloat16(v - __bfloat162float(h));
    }
}

// ---------------- mma.sync bf16x3 GEMM: C = A[M,K] @ Bt[N,K]^T (+bias) -------
// CTA 128x128, BK=64, 3-stage cp.async pipeline, 512 threads / 16 warps (4x4),
// warp tile 32x32. 3-pass bf16 hi/lo, pass-separated for acc-RAW spacing.
// Single __syncthreads per BK iter (trailing barrier proven redundant).
#define GT 16384                      // one operand tile: 128 rows x 128B
#define GSTAGE (4 * GT)               // Ah, Al, Bh, Bl = 65536
#define GSMEM  (3 * GSTAGE)           // 196608

__device__ __forceinline__ uint32_t swz(uint32_t base, int row, int kelem) {
    return base + row * 128 + ((((kelem >> 3) ^ row) & 7) << 4);
}

template <int EPI>
__global__ void __launch_bounds__(512, 1) gemm_mma_kernel(
    const __nv_bfloat16* __restrict__ Ah, const __nv_bfloat16* __restrict__ Al,
    const __nv_bfloat16* __restrict__ Bh, const __nv_bfloat16* __restrict__ Bl,
    const float* __restrict__ bias, float* __restrict__ Cf,
    __nv_bfloat16* __restrict__ Ch, __nv_bfloat16* __restrict__ Cl,
    int M, int N, int K)
{
    extern __shared__ char smem[];
    const uint32_t sb = smem_to_u32(smem);
    const int tid = threadIdx.x;
    const int lane = tid & 31, wid = tid >> 5;
    const int m0 = blockIdx.y * 128, n0 = blockIdx.x * 128;
    const int nk = K >> 6;

    auto load_stage = [&](int s, int j) {
        const uint32_t sbase = sb + (uint32_t)s * GSTAGE;
        const int lchk = tid & 7;           // 16B chunk in 128B row
        const int lrow = tid >> 3;          // 0..63
        const bool jv = (j < nk);
        const long long k0 = jv ? ((long long)j << 6) : 0;
#pragma unroll
        for (int it = 0; it < 2; it++) {
            int row = lrow + it * 64;
            bool av = jv && (m0 + row < M);
            int gr = (m0 + row < M) ? (m0 + row) : 0;
            size_t aoff = (size_t)gr * K + k0 + lchk * 8;
            size_t boff = (size_t)(n0 + row) * K + k0 + lchk * 8;
            uint32_t d = swz(sbase, row, lchk * 8);
            cp16(d,      Ah + aoff, av);
            cp16(d + GT, Al + aoff, av);
            uint32_t db = swz(sbase + 2 * GT, row, lchk * 8);
            cp16(db,      Bh + boff, jv);
            cp16(db + GT, Bl + boff, jv);
        }
    };

    float acc[2][4][4];
#pragma unroll
    for (int a = 0; a < 2; a++)
#pragma unroll
        for (int b = 0; b < 4; b++)
#pragma unroll
            for (int c = 0; c < 4; c++) acc[a][b][c] = 0.f;

    load_stage(0, 0);
    CP_COMMIT();
    load_stage(1, 1);
    CP_COMMIT();

    const int mw = (wid & 3) * 32;      // warp M offset (4 rows of warps)
    const int nw = (wid >> 2) * 32;     // warp N offset (4 cols of warps)
    const int rsel = lane & 15;
    const int khalf = (lane >> 4) * 8;

    for (int i = 0; i < nk; i++) {
        CP_WAIT1();
        __syncthreads();                  // single barrier per BK iter
        load_stage((i + 2) % 3, i + 2);   // zero-fill past end
        CP_COMMIT();

        const uint32_t sA = sb + (uint32_t)(i % 3) * GSTAGE;
        const uint32_t sB = sA + 2 * GT;
#pragma unroll
        for (int ks = 0; ks < 4; ks++) {
            const int ke = ks * 16 + khalf;
            uint32_t ah[2][4], al[2][4], bh[2][4], bl[2][4];
#pragma unroll
            for (int mi = 0; mi < 2; mi++) {
                uint32_t ad = swz(sA, mw + mi * 16 + rsel, ke);
                ldsm4(ah[mi], ad);
                ldsm4(al[mi], ad + GT);
            }
#pragma unroll
            for (int bi = 0; bi < 2; bi++) {
                uint32_t bd = swz(sB, nw + bi * 16 + rsel, ke);
                ldsm4(bh[bi], bd);
                ldsm4(bl[bi], bd + GT);
            }
            // pass 1: Ah*Bh — 8 independent accumulators back-to-back
#pragma unroll
            for (int mi = 0; mi < 2; mi++)
#pragma unroll
                for (int nj = 0; nj < 4; nj++) {
                    uint32_t b2[2] = { bh[nj >> 1][nj & 1], bh[nj >> 1][(nj & 1) + 2] };
                    mma_bf16(acc[mi][nj], ah[mi], b2);
                }
            // pass 2: Ah*Bl
#pragma unroll
            for (int mi = 0; mi < 2; mi++)
#pragma unroll
                for (int nj = 0; nj < 4; nj++) {
                    uint32_t b2[2] = { bl[nj >> 1][nj & 1], bl[nj >> 1][(nj & 1) + 2] };
                    mma_bf16(acc[mi][nj], ah[mi], b2);
                }
            // pass 3: Al*Bh
#pragma unroll
            for (int mi = 0; mi < 2; mi++)
#pragma unroll
                for (int nj = 0; nj < 4; nj++) {
                    uint32_t b2[2] = { bh[nj >> 1][nj & 1], bh[nj >> 1][(nj & 1) + 2] };
                    mma_bf16(acc[mi][nj], al[mi], b2);
                }
        }
    }

    // epilogue
#pragma unroll
    for (int mi = 0; mi < 2; mi++) {
#pragma unroll
        for (int nj = 0; nj < 4; nj++) {
            int col = n0 + nw + nj * 8 + (lane & 3) * 2;
            float bx = 0.f, by = 0.f;
            if (bias) { bx = bias[col]; by = bias[col + 1]; }
            int r0 = m0 + mw + mi * 16 + (lane >> 2);
            int r1 = r0 + 8;
            if (EPI == 0) {
                if (r0 < M)
                    *(float2*)(Cf + (size_t)r0 * N + col) =
                        make_float2(acc[mi][nj][0] + bx, acc[mi][nj][1] + by);
                if (r1 < M)
                    *(float2*)(Cf + (size_t)r1 * N + col) =
                        make_float2(acc[mi][nj][2] + bx, acc[mi][nj][3] + by);
            } else {
                if (r0 < M) {
                    float v0 = acc[mi][nj][0] + bx, v1 = acc[mi][nj][1] + by;
                    __nv_bfloat16 h0 = __float2bfloat16(v0), h1 = __float2bfloat16(v1);
                    size_t o = ((size_t)r0 * N + col) >> 1;
                    ((__nv_bfloat162*)Ch)[o] = __nv_bfloat162(h0, h1);
                    ((__nv_bfloat162*)Cl)[o] = __nv_bfloat162(
                        __float2bfloat16(v0 - __bfloat162float(h0)),
                        __float2bfloat16(v1 - __bfloat162float(h1)));
                }
                if (r1 < M) {
                    float v0 = acc[mi][nj][2] + bx, v1 = acc[mi][nj][3] + by;
                    __nv_bfloat16 h0 = __float2bfloat16(v0), h1 = __float2bfloat16(v1);
                    size_t o = ((size_t)r1 * N + col) >> 1;
                    ((__nv_bfloat162*)Ch)[o] = __nv_bfloat162(h0, h1);
                    ((__nv_bfloat162*)Cl)[o] = __nv_bfloat162(
                        __float2bfloat16(v0 - __bfloat162float(h0)),
                        __float2bfloat16(v1 - __bfloat162float(h1)));
                }
            }
        }
    }
}

// ---------------- per-node attention coefficients es/ed ----------------------
__global__ void attn_kernel(const float* __restrict__ hmat,
                            const float* __restrict__ a_src,
                            const float* __restrict__ a_dst, int H) {
    const int C = 512;
    int i = blockIdx.x;
    int hh = threadIdx.x >> 5;
    int lane = threadIdx.x & 31;
    const float* hr = hmat + (size_t)i * H * C + hh * C;
    float s = 0.f, d = 0.f;
    for (int c = lane; c < C; c += 32) {
        float v = hr[c];
        s += v * a_src[hh * C + c];
        d += v * a_dst[hh * C + c];
    }
#pragma unroll
    for (int o = 16; o > 0; o >>= 1) {
        s += __shfl_xor_sync(0xffffffffu, s, o);
        d += __shfl_xor_sync(0xffffffffu, d, o);
    }
    if (lane == 0) { g_es[i * H + hh] = s; g_ed[i * H + hh] = d; }
}

// ---------------- segment softmax over dst-CSR rows --------------------------
__global__ void softmax_kernel(int H) {
    int idx = blockIdx.x * blockDim.x + threadIdx.x;
    if (idx >= NN * H) return;
    int i = idx % NN;
    int hh = idx / NN;
    float edi = g_ed[i * H + hh];
    int p0 = g_rowptr[i], p1 = g_rowptr[i + 1];
    float m = -1e30f;
    for (int p = p0; p < p1; p++) {
        float e = g_es[g_csrsrc[p] * H + hh] + edi;
        e = (e > 0.f) ? e : 0.2f * e;
        m = fmaxf(m, e);
    }
    float den = 0.f;
    for (int p = p0; p < p1; p++) {
        float e = g_es[g_csrsrc[p] * H + hh] + edi;
        e = (e > 0.f) ? e : 0.2f * e;
        float a = expf(e - m);
        g_alpha[p * 4 + hh] = a;
        den += a;
    }
    float inv = 1.f / den;
    for (int p = p0; p < p1; p++) g_alpha[p * 4 + hh] *= inv;
}

// ---------------- weighted aggregation (float4) ------------------------------
// MODE 0: concat heads + bias + ELU, write bf16 hi/lo split (next GEMM input).
// MODE 1: mean over 2 heads + bias, write fp32.
template <int HC, int MODE>
__global__ void aggregate_kernel(const float* __restrict__ hmat,
                                 const float* __restrict__ bias,
                                 float* __restrict__ outF,
                                 __nv_bfloat16* __restrict__ outH,
                                 __nv_bfloat16* __restrict__ outL) {
    constexpr int PT = HC / 1024;
    int i = blockIdx.x;
    int t = threadIdx.x;
    int hsel = t >> 7;
    float4 acc[PT];
#pragma unroll
    for (int k = 0; k < PT; k++) acc[k] = make_float4(0.f, 0.f, 0.f, 0.f);

    int p0 = g_rowptr[i], p1 = g_rowptr[i + 1];
    for (int p = p0; p < p1; p++) {
        int s = g_csrsrc[p];
        float4 a4 = *(const float4*)(g_alpha + p * 4);
        const float* al = (const float*)&a4;
        const float4* hr = (const float4*)(hmat + (size_t)s * HC);
#pragma unroll
        for (int k = 0; k < PT; k++) {
            float av = al[2 * k + hsel];
            float4 h = hr[t + k * 256];
            acc[k].x += av * h.x;
            acc[k].y += av * h.y;
            acc[k].z += av * h.z;
            acc[k].w += av * h.w;
        }
    }

    if (MODE == 0) {
#pragma unroll
        for (int k = 0; k < PT; k++) {
            int col4 = t + k * 256;
            float4 b = *(const float4*)(bias + col4 * 4);
            float4 v = acc[k];
            v.x += b.x; v.y += b.y; v.z += b.z; v.w += b.w;
            v.x = (v.x > 0.f) ? v.x : (expf(v.x) - 1.f);
            v.y = (v.y > 0.f) ? v.y : (expf(v.y) - 1.f);
            v.z = (v.z > 0.f) ? v.z : (expf(v.z) - 1.f);
            v.w = (v.w > 0.f) ? v.w : (expf(v.w) - 1.f);
            __nv_bfloat16 h0 = __float2bfloat16(v.x), h1 = __float2bfloat16(v.y);
            __nv_bfloat16 h2 = __float2bfloat16(v.z), h3 = __float2bfloat16(v.w);
            size_t o2 = ((size_t)i * HC + col4 * 4) >> 1;
            ((__nv_bfloat162*)outH)[o2]     = __nv_bfloat162(h0, h1);
            ((__nv_bfloat162*)outH)[o2 + 1] = __nv_bfloat162(h2, h3);
            ((__nv_bfloat162*)outL)[o2] = __nv_bfloat162(
                __float2bfloat16(v.x - __bfloat162float(h0)),
                __float2bfloat16(v.y - __bfloat162float(h1)));
            ((__nv_bfloat162*)outL)[o2 + 1] = __nv_bfloat162(
                __float2bfloat16(v.z - __bfloat162float(h2)),
                __float2bfloat16(v.w - __bfloat162float(h3)));
        }
    } else {
        __shared__ float4 sh[256];
        sh[t] = acc[0];
        __syncthreads();
        if (t < 128) {
            float4 v0 = sh[t], v1 = sh[t + 128];
            float4 b = ((const float4*)bias)[t];
            float4 r;
            r.x = 0.5f * (v0.x + v1.x) + b.x;
            r.y = 0.5f * (v0.y + v1.y) + b.y;
            r.z = 0.5f * (v0.z + v1.z) + b.z;
            r.w = 0.5f * (v0.w + v1.w) + b.w;
            ((float4*)outF)[(size_t)i * 128 + t] = r;
        }
    }
}

// ---------------- host launch helpers ----------------------------------------
static void run_gemm_f32(const __nv_bfloat16* ah, const __nv_bfloat16* al,
                         const __nv_bfloat16* wh, const __nv_bfloat16* wl,
                         const float* bias, float* C, int M, int N, int K) {
    dim3 grid(N / 128, (M + 127) / 128);
    gemm_mma_kernel<0><<<grid, 512, GSMEM>>>(ah, al, wh, wl, bias, C, nullptr, nullptr, M, N, K);
}
static void run_gemm_split(const __nv_bfloat16* ah, const __nv_bfloat16* al,
                           const __nv_bfloat16* wh, const __nv_bfloat16* wl,
                           const float* bias, __nv_bfloat16* ch, __nv_bfloat16* cl,
                           int M, int N, int K) {
    dim3 grid(N / 128, (M + 127) / 128);
    gemm_mma_kernel<1><<<grid, 512, GSMEM>>>(ah, al, wh, wl, bias, nullptr, ch, cl, M, N, K);
}

extern "C" void kernel_launch(void* const* d_in, const int* in_sizes, int n_in,
                              void* d_out, int out_size) {
    const float* x      = (const float*)d_in[0];
    const void*  ei     = d_in[1];
    const float* proj_w = (const float*)d_in[2];
    const float* proj_b = (const float*)d_in[3];
    const float* w1  = (const float*)d_in[4];
    const float* as1 = (const float*)d_in[5];
    const float* ad1 = (const float*)d_in[6];
    const float* b1  = (const float*)d_in[7];
    const float* w2  = (const float*)d_in[8];
    const float* as2 = (const float*)d_in[9];
    const float* ad2 = (const float*)d_in[10];
    const float* b2  = (const float*)d_in[11];
    const float* w3  = (const float*)d_in[12];
    const float* as3 = (const float*)d_in[13];
    const float* ad3 = (const float*)d_in[14];
    const float* b3  = (const float*)d_in[15];
    float* out = (float*)d_out;

    float* hmat;
    __nv_bfloat16 *P0h, *P0l, *P1h, *P1l, *Wh, *Wl;
    cudaGetSymbolAddress((void**)&hmat, g_hmat);
    cudaGetSymbolAddress((void**)&P0h, g_P0h);
    cudaGetSymbolAddress((void**)&P0l, g_P0l);
    cudaGetSymbolAddress((void**)&P1h, g_P1h);
    cudaGetSymbolAddress((void**)&P1l, g_P1l);
    cudaGetSymbolAddress((void**)&Wh, g_Wh);
    cudaGetSymbolAddress((void**)&Wl, g_Wl);

    static bool attr_set = false;
    if (!attr_set) {
        cudaFuncSetAttribute((const void*)gemm_mma_kernel<0>,
                             cudaFuncAttributeMaxDynamicSharedMemorySize, GSMEM);
        cudaFuncSetAttribute((const void*)gemm_mma_kernel<1>,
                             cudaFuncAttributeMaxDynamicSharedMemorySize, GSMEM);
        attr_set = true;
    }

    // our idx 0-2: input split, proj_w transpose, detect/init
    cvt_split_kernel<<<(NN * 256 / 4 + 255) / 256, 256>>>(x, P0h, P0l, NN * 256 / 4);
    cvt_transpose_kernel<<<dim3(512 / 32, 256 / 32), dim3(32, 8)>>>(proj_w, Wh, Wl, 256, 512);
    detect_init_kernel<<<(NN + 255) / 256, 256>>>((const unsigned int*)ei);
    // our idx 3: proj GEMM  <-- ncu -s 5 -c 1 profiles this launch
    run_gemm_split(P0h, P0l, Wh, Wl, proj_b, P1h, P1l, NN, 512, 256);
    // CSR build (independent of GEMM chain)
    count_kernel<<<(EE + 255) / 256, 256>>>(ei);
    scan_fillself_kernel<<<1, 1024>>>();
    filledges_kernel<<<(EE + 255) / 256, 256>>>(ei);

    // ---- GAT layer 1 (H=4, C=512, concat, ELU): N=2048, K=512 ----
    cvt_transpose_kernel<<<dim3(2048 / 32, 512 / 32), dim3(32, 8)>>>(w1, Wh, Wl, 512, 2048);
    run_gemm_f32(P1h, P1l, Wh, Wl, nullptr, hmat, NN, 2048, 512);
    attn_kernel<<<NN, 128>>>(hmat, as1, ad1, 4);
    softmax_kernel<<<(NN * 4 + 255) / 256, 256>>>(4);
    aggregate_kernel<2048, 0><<<NN, 256>>>(hmat, b1, nullptr, P0h, P0l);

    // ---- GAT layer 2 (H=4, C=512, concat, ELU): N=2048, K=2048 ----
    cvt_transpose_kernel<<<dim3(2048 / 32, 2048 / 32), dim3(32, 8)>>>(w2, Wh, Wl, 2048, 2048);
    run_gemm_f32(P0h, P0l, Wh, Wl, nullptr, hmat, NN, 2048, 2048);
    attn_kernel<<<NN, 128>>>(hmat, as2, ad2, 4);
    softmax_kernel<<<(NN * 4 + 255) / 256, 256>>>(4);
    aggregate_kernel<2048, 0><<<NN, 256>>>(hmat, b2, nullptr, P1h, P1l);

    // ---- GAT layer 3 (H=2, C=512, mean): N=1024, K=2048 ----
    cvt_transpose_kernel<<<dim3(1024 / 32, 2048 / 32), dim3(32, 8)>>>(w3, Wh, Wl, 2048, 1024);
    run_gemm_f32(P1h, P1l, Wh, Wl, nullptr, hmat, NN, 1024, 2048);
    attn_kernel<<<NN, 64>>>(hmat, as3, ad3, 2);
    softmax_kernel<<<(NN * 2 + 255) / 256, 256>>>(2);
    aggregate_kernel<1024, 1><<<NN, 256>>>(hmat, b3, out, nullptr, nullptr);
}

// round 8
// speedup vs baseline: 1.5166x; 1.2072x over previous
#include <cuda_runtime.h>
#include <cuda_bf16.h>
#include <cuda_fp16.h>
#include <math.h>
#include <stdint.h>

#define NN 10000
#define EE 160000
#define ET 170000   // edges + self loops

// ---------------- scratch (device globals; no allocations allowed) ----------
__device__ float g_hmat[NN * 2048];
__device__ float g_es  [NN * 4];
__device__ float g_ed  [NN * 4];
__device__ float g_alpha[ET * 4];
__device__ int   g_counts [NN];
__device__ int   g_rowptr [NN + 1];
__device__ int   g_fillpos[NN];
__device__ int   g_csrsrc [ET];
__device__ int   g_is64;
// 16-bit hi/lo activation pairs (ping-pong) + weight pair (bf16 or fp16 views)
__device__ __align__(16) uint16_t g_P0h[NN * 2048];
__device__ __align__(16) uint16_t g_P0l[NN * 2048];
__device__ __align__(16) uint16_t g_P1h[NN * 2048];
__device__ __align__(16) uint16_t g_P1l[NN * 2048];
__device__ __align__(16) uint16_t g_Wh[2048 * 2048];
__device__ __align__(16) uint16_t g_Wl[2048 * 2048];

#define LO_SCALE 4096.0f
#define LO_INV   (1.0f / 4096.0f)

// ============================ PTX helpers (baseline, sm_80+) =================
__device__ __forceinline__ uint32_t smem_to_u32(const void* p) {
    uint32_t a;
    asm("{ .reg .u64 t; cvta.to.shared.u64 t, %1; cvt.u32.u64 %0, t; }" : "=r"(a) : "l"(p));
    return a;
}

__device__ __forceinline__ void cp16(uint32_t dst, const void* src, bool v) {
    int sz = v ? 16 : 0;
    asm volatile("cp.async.cg.shared.global [%0], [%1], 16, %2;\n"
                 :: "r"(dst), "l"(src), "r"(sz) : "memory");
}
#define CP_COMMIT() asm volatile("cp.async.commit_group;" ::: "memory")
#define CP_WAIT1()  asm volatile("cp.async.wait_group 1;" ::: "memory")

__device__ __forceinline__ void ldsm4(uint32_t* r, uint32_t addr) {
    asm volatile("ldmatrix.sync.aligned.m8n8.x4.shared.b16 {%0,%1,%2,%3}, [%4];"
                 : "=r"(r[0]), "=r"(r[1]), "=r"(r[2]), "=r"(r[3]) : "r"(addr));
}

__device__ __forceinline__ void mma_bf16(float* c, const uint32_t* a, const uint32_t* b) {
    asm volatile(
        "mma.sync.aligned.m16n8k16.row.col.f32.bf16.bf16.f32 "
        "{%0,%1,%2,%3}, {%4,%5,%6,%7}, {%8,%9}, {%0,%1,%2,%3};"
        : "+f"(c[0]), "+f"(c[1]), "+f"(c[2]), "+f"(c[3])
        : "r"(a[0]), "r"(a[1]), "r"(a[2]), "r"(a[3]), "r"(b[0]), "r"(b[1]));
}
__device__ __forceinline__ void mma_fp16(float* c, const uint32_t* a, const uint32_t* b) {
    asm volatile(
        "mma.sync.aligned.m16n8k16.row.col.f32.f16.f16.f32 "
        "{%0,%1,%2,%3}, {%4,%5,%6,%7}, {%8,%9}, {%0,%1,%2,%3};"
        : "+f"(c[0]), "+f"(c[1]), "+f"(c[2]), "+f"(c[3])
        : "r"(a[0]), "r"(a[1]), "r"(a[2]), "r"(a[3]), "r"(b[0]), "r"(b[1]));
}

__device__ __forceinline__ int edge_at(const void* ei, long long idx) {
    if (g_is64) return (int)((const long long*)ei)[idx];
    return ((const int*)ei)[idx];
}

// ---------------- CSR build ---------------------------------------------------
__global__ void detect_init_kernel(const unsigned int* p) {
    int i = blockIdx.x * blockDim.x + threadIdx.x;
    if (i < NN) g_counts[i] = 1;           // self loop pre-counted
    if (i == 0) {
        int is64 = 1;
        for (int j = 0; j < 128; j++)
            if (p[2 * j + 1] != 0u) { is64 = 0; break; }
        g_is64 = is64;
    }
}
__global__ void count_kernel(const void* ei) {
    int e = blockIdx.x * blockDim.x + threadIdx.x;
    if (e < EE) atomicAdd(&g_counts[edge_at(ei, (long long)EE + e)], 1);
}
__global__ void scan_fillself_kernel() {
    __shared__ int sh[1024];
    int t = threadIdx.x;
    const int chunk = (NN + 1023) >> 10;
    int base = t * chunk;
    int s = 0;
    for (int j = 0; j < chunk; j++) { int idx = base + j; if (idx < NN) s += g_counts[idx]; }
    sh[t] = s;
    __syncthreads();
    for (int off = 1; off < 1024; off <<= 1) {
        int v = (t >= off) ? sh[t - off] : 0;
        __syncthreads();
        sh[t] += v;
        __syncthreads();
    }
    int prefix = (t > 0) ? sh[t - 1] : 0;
    for (int j = 0; j < chunk; j++) {
        int idx = base + j;
        if (idx < NN) { g_rowptr[idx] = prefix; prefix += g_counts[idx]; }
    }
    if (t == 0) g_rowptr[NN] = sh[1023];
    __syncthreads();
    for (int idx = t; idx < NN; idx += 1024) {
        int r = g_rowptr[idx];
        g_csrsrc[r] = idx;
        g_fillpos[idx] = r + 1;
    }
}
__global__ void filledges_kernel(const void* ei) {
    int e = blockIdx.x * blockDim.x + threadIdx.x;
    if (e < EE) {
        int s = edge_at(ei, e);
        int d = edge_at(ei, (long long)EE + e);
        g_csrsrc[atomicAdd(&g_fillpos[d], 1)] = s;
    }
}

// ---------------- fp32 -> bf16 hi/lo split (input x only) --------------------
__global__ void cvt_split_kernel(const float* __restrict__ x,
                                 uint16_t* __restrict__ hi,
                                 uint16_t* __restrict__ lo, int n4) {
    int i = blockIdx.x * blockDim.x + threadIdx.x;
    if (i >= n4) return;
    float4 v = ((const float4*)x)[i];
    __nv_bfloat16 h0 = __float2bfloat16(v.x);
    __nv_bfloat16 h1 = __float2bfloat16(v.y);
    __nv_bfloat16 h2 = __float2bfloat16(v.z);
    __nv_bfloat16 h3 = __float2bfloat16(v.w);
    __nv_bfloat16 l0 = __float2bfloat16(v.x - __bfloat162float(h0));
    __nv_bfloat16 l1 = __float2bfloat16(v.y - __bfloat162float(h1));
    __nv_bfloat16 l2 = __float2bfloat16(v.z - __bfloat162float(h2));
    __nv_bfloat16 l3 = __float2bfloat16(v.w - __bfloat162float(h3));
    ((__nv_bfloat162*)hi)[2 * i]     = __nv_bfloat162(h0, h1);
    ((__nv_bfloat162*)hi)[2 * i + 1] = __nv_bfloat162(h2, h3);
    ((__nv_bfloat162*)lo)[2 * i]     = __nv_bfloat162(l0, l1);
    ((__nv_bfloat162*)lo)[2 * i + 1] = __nv_bfloat162(l2, l3);
}

// ---------------- weight transpose: W[K,N] -> Wt[N,K] ------------------------
__global__ void cvt_transpose_bf16_kernel(const float* __restrict__ W,
                                          uint16_t* __restrict__ th,
                                          uint16_t* __restrict__ tl, int K, int N) {
    __shared__ float tile[32][33];
    int n0 = blockIdx.x * 32, k0 = blockIdx.y * 32;
    int tx = threadIdx.x, ty = threadIdx.y;   // 32 x 8
    for (int r = ty; r < 32; r += 8)
        tile[r][tx] = W[(size_t)(k0 + r) * N + n0 + tx];
    __syncthreads();
    for (int r = ty; r < 32; r += 8) {
        float v = tile[tx][r];
        __nv_bfloat16 h = __float2bfloat16(v);
        size_t o = (size_t)(n0 + r) * K + k0 + tx;
        ((__nv_bfloat16*)th)[o] = h;
        ((__nv_bfloat16*)tl)[o] = __float2bfloat16(v - __bfloat162float(h));
    }
}
__global__ void cvt_transpose_f16_kernel(const float* __restrict__ W,
                                         uint16_t* __restrict__ th, int K, int N) {
    __shared__ float tile[32][33];
    int n0 = blockIdx.x * 32, k0 = blockIdx.y * 32;
    int tx = threadIdx.x, ty = threadIdx.y;
    for (int r = ty; r < 32; r += 8)
        tile[r][tx] = W[(size_t)(k0 + r) * N + n0 + tx];
    __syncthreads();
    for (int r = ty; r < 32; r += 8)
        ((__half*)th)[(size_t)(n0 + r) * K + k0 + tx] = __float2half(tile[tx][r]);
}

__device__ __forceinline__ uint32_t swz(uint32_t base, int row, int kelem) {
    return base + row * 128 + ((((kelem >> 3) ^ row) & 7) << 4);
}

// ---------------- bf16 3-pass GEMM (proj + layer 1) --------------------------
// CTA 128x128, BK=64, 3-stage, 512 threads / 16 warps, warp tile 32x32.
// EPI 0: fp32 out (+bias). EPI 1: bf16 hi/lo split out (+bias).
#define GT 16384
#define GSTAGE (4 * GT)
#define GSMEM  (3 * GSTAGE)           // 196608

template <int EPI>
__global__ void __launch_bounds__(512, 1) gemm_mma_kernel(
    const __nv_bfloat16* __restrict__ Ah, const __nv_bfloat16* __restrict__ Al,
    const __nv_bfloat16* __restrict__ Bh, const __nv_bfloat16* __restrict__ Bl,
    const float* __restrict__ bias, float* __restrict__ Cf,
    __nv_bfloat16* __restrict__ Ch, __nv_bfloat16* __restrict__ Cl,
    int M, int N, int K)
{
    extern __shared__ char smem[];
    const uint32_t sb = smem_to_u32(smem);
    const int tid = threadIdx.x;
    const int lane = tid & 31, wid = tid >> 5;
    const int m0 = blockIdx.y * 128, n0 = blockIdx.x * 128;
    const int nk = K >> 6;

    auto load_stage = [&](int s, int j) {
        const uint32_t sbase = sb + (uint32_t)s * GSTAGE;
        const int lchk = tid & 7;
        const int lrow = tid >> 3;          // 0..63
        const bool jv = (j < nk);
        const long long k0 = jv ? ((long long)j << 6) : 0;
#pragma unroll
        for (int it = 0; it < 2; it++) {
            int row = lrow + it * 64;
            bool av = jv && (m0 + row < M);
            int gr = (m0 + row < M) ? (m0 + row) : 0;
            size_t aoff = (size_t)gr * K + k0 + lchk * 8;
            size_t boff = (size_t)(n0 + row) * K + k0 + lchk * 8;
            uint32_t d = swz(sbase, row, lchk * 8);
            cp16(d,      Ah + aoff, av);
            cp16(d + GT, Al + aoff, av);
            uint32_t db = swz(sbase + 2 * GT, row, lchk * 8);
            cp16(db,      Bh + boff, jv);
            cp16(db + GT, Bl + boff, jv);
        }
    };

    float acc[2][4][4];
#pragma unroll
    for (int a = 0; a < 2; a++)
#pragma unroll
        for (int b = 0; b < 4; b++)
#pragma unroll
            for (int c = 0; c < 4; c++) acc[a][b][c] = 0.f;

    load_stage(0, 0);
    CP_COMMIT();
    load_stage(1, 1);
    CP_COMMIT();

    const int mw = (wid & 3) * 32;
    const int nw = (wid >> 2) * 32;
    const int rsel = lane & 15;
    const int khalf = (lane >> 4) * 8;

    for (int i = 0; i < nk; i++) {
        CP_WAIT1();
        __syncthreads();
        load_stage((i + 2) % 3, i + 2);
        CP_COMMIT();

        const uint32_t sA = sb + (uint32_t)(i % 3) * GSTAGE;
        const uint32_t sB = sA + 2 * GT;
#pragma unroll
        for (int ks = 0; ks < 4; ks++) {
            const int ke = ks * 16 + khalf;
            uint32_t ah[2][4], al[2][4], bh[2][4], bl[2][4];
#pragma unroll
            for (int mi = 0; mi < 2; mi++) {
                uint32_t ad = swz(sA, mw + mi * 16 + rsel, ke);
                ldsm4(ah[mi], ad);
                ldsm4(al[mi], ad + GT);
            }
#pragma unroll
            for (int bi = 0; bi < 2; bi++) {
                uint32_t bd = swz(sB, nw + bi * 16 + rsel, ke);
                ldsm4(bh[bi], bd);
                ldsm4(bl[bi], bd + GT);
            }
#pragma unroll
            for (int mi = 0; mi < 2; mi++)
#pragma unroll
                for (int nj = 0; nj < 4; nj++) {
                    uint32_t b2[2] = { bh[nj >> 1][nj & 1], bh[nj >> 1][(nj & 1) + 2] };
                    mma_bf16(acc[mi][nj], ah[mi], b2);
                }
#pragma unroll
            for (int mi = 0; mi < 2; mi++)
#pragma unroll
                for (int nj = 0; nj < 4; nj++) {
                    uint32_t b2[2] = { bl[nj >> 1][nj & 1], bl[nj >> 1][(nj & 1) + 2] };
                    mma_bf16(acc[mi][nj], ah[mi], b2);
                }
#pragma unroll
            for (int mi = 0; mi < 2; mi++)
#pragma unroll
                for (int nj = 0; nj < 4; nj++) {
                    uint32_t b2[2] = { bh[nj >> 1][nj & 1], bh[nj >> 1][(nj & 1) + 2] };
                    mma_bf16(acc[mi][nj], al[mi], b2);
                }
        }
    }

#pragma unroll
    for (int mi = 0; mi < 2; mi++) {
#pragma unroll
        for (int nj = 0; nj < 4; nj++) {
            int col = n0 + nw + nj * 8 + (lane & 3) * 2;
            float bx = 0.f, by = 0.f;
            if (bias) { bx = bias[col]; by = bias[col + 1]; }
            int r0 = m0 + mw + mi * 16 + (lane >> 2);
            int r1 = r0 + 8;
            if (EPI == 0) {
                if (r0 < M)
                    *(float2*)(Cf + (size_t)r0 * N + col) =
                        make_float2(acc[mi][nj][0] + bx, acc[mi][nj][1] + by);
                if (r1 < M)
                    *(float2*)(Cf + (size_t)r1 * N + col) =
                        make_float2(acc[mi][nj][2] + bx, acc[mi][nj][3] + by);
            } else {
                if (r0 < M) {
                    float v0 = acc[mi][nj][0] + bx, v1 = acc[mi][nj][1] + by;
                    __nv_bfloat16 h0 = __float2bfloat16(v0), h1 = __float2bfloat16(v1);
                    size_t o = ((size_t)r0 * N + col) >> 1;
                    ((__nv_bfloat162*)Ch)[o] = __nv_bfloat162(h0, h1);
                    ((__nv_bfloat162*)Cl)[o] = __nv_bfloat162(
                        __float2bfloat16(v0 - __bfloat162float(h0)),
                        __float2bfloat16(v1 - __bfloat162float(h1)));
                }
                if (r1 < M) {
                    float v0 = acc[mi][nj][2] + bx, v1 = acc[mi][nj][3] + by;
                    __nv_bfloat16 h0 = __float2bfloat16(v0), h1 = __float2bfloat16(v1);
                    size_t o = ((size_t)r1 * N + col) >> 1;
                    ((__nv_bfloat162*)Ch)[o] = __nv_bfloat162(h0, h1);
                    ((__nv_bfloat162*)Cl)[o] = __nv_bfloat162(
                        __float2bfloat16(v0 - __bfloat162float(h0)),
                        __float2bfloat16(v1 - __bfloat162float(h1)));
                }
            }
        }
    }
}

// ---------------- fp16 1-pass GEMM (layers 2/3; two launches: hi then lo) ----
// CTA 128x128, BK=64, 3-stage, 256 threads / 8 warps (4x2), warp tile 32x64.
// smem 96KB -> 2 CTAs/SM. FIRST: C = acc. else: C += acc * LO_INV.
#define HT 16384
#define HSTAGE (2 * HT)
#define HSMEM  (3 * HSTAGE)           // 98304

template <int FIRST>
__global__ void __launch_bounds__(256, 2) gemm16_kernel(
    const __half* __restrict__ A, const __half* __restrict__ B,
    float* __restrict__ C, int M, int N, int K)
{
    extern __shared__ char smem[];
    const uint32_t sb = smem_to_u32(smem);
    const int tid = threadIdx.x;
    const int lane = tid & 31, wid = tid >> 5;
    const int m0 = blockIdx.y * 128, n0 = blockIdx.x * 128;
    const int nk = K >> 6;

    auto load_stage = [&](int s, int j) {
        const uint32_t sbase = sb + (uint32_t)s * HSTAGE;
        const int lchk = tid & 7;
        const int lrow = tid >> 3;        // 0..31
        const bool jv = (j < nk);
        const long long k0 = jv ? ((long long)j << 6) : 0;
#pragma unroll
        for (int it = 0; it < 4; it++) {
            int row = lrow + it * 32;
            bool av = jv && (m0 + row < M);
            int gr = (m0 + row < M) ? (m0 + row) : 0;
            cp16(swz(sbase, row, lchk * 8),
                 A + (size_t)gr * K + k0 + lchk * 8, av);
            cp16(swz(sbase + HT, row, lchk * 8),
                 B + (size_t)(n0 + row) * K + k0 + lchk * 8, jv);
        }
    };

    float acc[2][8][4];
#pragma unroll
    for (int a = 0; a < 2; a++)
#pragma unroll
        for (int b = 0; b < 8; b++)
#pragma unroll
            for (int c = 0; c < 4; c++) acc[a][b][c] = 0.f;

    load_stage(0, 0);
    CP_COMMIT();
    load_stage(1, 1);
    CP_COMMIT();

    const int mw = (wid & 3) * 32;      // 4 warp rows
    const int nw = (wid >> 2) * 64;     // 2 warp cols
    const int rsel = lane & 15;
    const int khalf = (lane >> 4) * 8;

    for (int i = 0; i < nk; i++) {
        CP_WAIT1();
        __syncthreads();
        load_stage((i + 2) % 3, i + 2);
        CP_COMMIT();

        const uint32_t sA = sb + (uint32_t)(i % 3) * HSTAGE;
        const uint32_t sB = sA + HT;
#pragma unroll
        for (int ks = 0; ks < 4; ks++) {
            const int ke = ks * 16 + khalf;
            uint32_t a[2][4], b[4][4];
#pragma unroll
            for (int mi = 0; mi < 2; mi++)
                ldsm4(a[mi], swz(sA, mw + mi * 16 + rsel, ke));
#pragma unroll
            for (int bi = 0; bi < 4; bi++)
                ldsm4(b[bi], swz(sB, nw + bi * 16 + rsel, ke));
#pragma unroll
            for (int mi = 0; mi < 2; mi++)
#pragma unroll
                for (int nj = 0; nj < 8; nj++) {
                    uint32_t b2[2] = { b[nj >> 1][nj & 1], b[nj >> 1][(nj & 1) + 2] };
                    mma_fp16(acc[mi][nj], a[mi], b2);
                }
        }
    }

#pragma unroll
    for (int mi = 0; mi < 2; mi++) {
#pragma unroll
        for (int nj = 0; nj < 8; nj++) {
            int col = n0 + nw + nj * 8 + (lane & 3) * 2;
            int r0 = m0 + mw + mi * 16 + (lane >> 2);
            int r1 = r0 + 8;
            if (FIRST) {
                if (r0 < M)
                    *(float2*)(C + (size_t)r0 * N + col) =
                        make_float2(acc[mi][nj][0], acc[mi][nj][1]);
                if (r1 < M)
                    *(float2*)(C + (size_t)r1 * N + col) =
                        make_float2(acc[mi][nj][2], acc[mi][nj][3]);
            } else {
                if (r0 < M) {
                    float2 v = *(float2*)(C + (size_t)r0 * N + col);
                    v.x += acc[mi][nj][0] * LO_INV;
                    v.y += acc[mi][nj][1] * LO_INV;
                    *(float2*)(C + (size_t)r0 * N + col) = v;
                }
                if (r1 < M) {
                    float2 v = *(float2*)(C + (size_t)r1 * N + col);
                    v.x += acc[mi][nj][2] * LO_INV;
                    v.y += acc[mi][nj][3] * LO_INV;
                    *(float2*)(C + (size_t)r1 * N + col) = v;
                }
            }
        }
    }
}

// ---------------- per-node attention coefficients es/ed ----------------------
__global__ void attn_kernel(const float* __restrict__ hmat,
                            const float* __restrict__ a_src,
                            const float* __restrict__ a_dst, int H) {
    const int C = 512;
    int i = blockIdx.x;
    int hh = threadIdx.x >> 5;
    int lane = threadIdx.x & 31;
    const float* hr = hmat + (size_t)i * H * C + hh * C;
    float s = 0.f, d = 0.f;
    for (int c = lane; c < C; c += 32) {
        float v = hr[c];
        s += v * a_src[hh * C + c];
        d += v * a_dst[hh * C + c];
    }
#pragma unroll
    for (int o = 16; o > 0; o >>= 1) {
        s += __shfl_xor_sync(0xffffffffu, s, o);
        d += __shfl_xor_sync(0xffffffffu, d, o);
    }
    if (lane == 0) { g_es[i * H + hh] = s; g_ed[i * H + hh] = d; }
}

// ---------------- segment softmax over dst-CSR rows --------------------------
__global__ void softmax_kernel(int H) {
    int idx = blockIdx.x * blockDim.x + threadIdx.x;
    if (idx >= NN * H) return;
    int i = idx % NN;
    int hh = idx / NN;
    float edi = g_ed[i * H + hh];
    int p0 = g_rowptr[i], p1 = g_rowptr[i + 1];
    float m = -1e30f;
    for (int p = p0; p < p1; p++) {
        float e = g_es[g_csrsrc[p] * H + hh] + edi;
        e = (e > 0.f) ? e : 0.2f * e;
        m = fmaxf(m, e);
    }
    float den = 0.f;
    for (int p = p0; p < p1; p++) {
        float e = g_es[g_csrsrc[p] * H + hh] + edi;
        e = (e > 0.f) ? e : 0.2f * e;
        float a = expf(e - m);
        g_alpha[p * 4 + hh] = a;
        den += a;
    }
    float inv = 1.f / den;
    for (int p = p0; p < p1; p++) g_alpha[p * 4 + hh] *= inv;
}

// ---------------- weighted aggregation (float4) ------------------------------
// MODE 0: concat heads + bias + ELU, write fp16 hi + scaled-lo split.
// MODE 1: mean over 2 heads + bias, write fp32.
template <int HC, int MODE>
__global__ void aggregate_kernel(const float* __restrict__ hmat,
                                 const float* __restrict__ bias,
                                 float* __restrict__ outF,
                                 uint16_t* __restrict__ outH,
                                 uint16_t* __restrict__ outL) {
    constexpr int PT = HC / 1024;
    int i = blockIdx.x;
    int t = threadIdx.x;
    int hsel = t >> 7;
    float4 acc[PT];
#pragma unroll
    for (int k = 0; k < PT; k++) acc[k] = make_float4(0.f, 0.f, 0.f, 0.f);

    int p0 = g_rowptr[i], p1 = g_rowptr[i + 1];
    for (int p = p0; p < p1; p++) {
        int s = g_csrsrc[p];
        float4 a4 = *(const float4*)(g_alpha + p * 4);
        const float* al = (const float*)&a4;
        const float4* hr = (const float4*)(hmat + (size_t)s * HC);
#pragma unroll
        for (int k = 0; k < PT; k++) {
            float av = al[2 * k + hsel];
            float4 h = hr[t + k * 256];
            acc[k].x += av * h.x;
            acc[k].y += av * h.y;
            acc[k].z += av * h.z;
            acc[k].w += av * h.w;
        }
    }

    if (MODE == 0) {
#pragma unroll
        for (int k = 0; k < PT; k++) {
            int col4 = t + k * 256;
            float4 b = *(const float4*)(bias + col4 * 4);
            float4 v = acc[k];
            v.x += b.x; v.y += b.y; v.z += b.z; v.w += b.w;
            v.x = (v.x > 0.f) ? v.x : (expf(v.x) - 1.f);
            v.y = (v.y > 0.f) ? v.y : (expf(v.y) - 1.f);
            v.z = (v.z > 0.f) ? v.z : (expf(v.z) - 1.f);
            v.w = (v.w > 0.f) ? v.w : (expf(v.w) - 1.f);
            __half h0 = __float2half(v.x), h1 = __float2half(v.y);
            __half h2 = __float2half(v.z), h3 = __float2half(v.w);
            size_t o2 = ((size_t)i * HC + col4 * 4) >> 1;
            ((__half2*)outH)[o2]     = __halves2half2(h0, h1);
            ((__half2*)outH)[o2 + 1] = __halves2half2(h2, h3);
            ((__half2*)outL)[o2] = __halves2half2(
                __float2half((v.x - __half2float(h0)) * LO_SCALE),
                __float2half((v.y - __half2float(h1)) * LO_SCALE));
            ((__half2*)outL)[o2 + 1] = __halves2half2(
                __float2half((v.z - __half2float(h2)) * LO_SCALE),
                __float2half((v.w - __half2float(h3)) * LO_SCALE));
        }
    } else {
        __shared__ float4 sh[256];
        sh[t] = acc[0];
        __syncthreads();
        if (t < 128) {
            float4 v0 = sh[t], v1 = sh[t + 128];
            float4 b = ((const float4*)bias)[t];
            float4 r;
            r.x = 0.5f * (v0.x + v1.x) + b.x;
            r.y = 0.5f * (v0.y + v1.y) + b.y;
            r.z = 0.5f * (v0.z + v1.z) + b.z;
            r.w = 0.5f * (v0.w + v1.w) + b.w;
            ((float4*)outF)[(size_t)i * 128 + t] = r;
        }
    }
}

// ---------------- host launch helpers ----------------------------------------
static void run_gemm_f32(const uint16_t* ah, const uint16_t* al,
                         const uint16_t* wh, const uint16_t* wl,
                         const float* bias, float* C, int M, int N, int K) {
    dim3 grid(N / 128, (M + 127) / 128);
    gemm_mma_kernel<0><<<grid, 512, GSMEM>>>(
        (const __nv_bfloat16*)ah, (const __nv_bfloat16*)al,
        (const __nv_bfloat16*)wh, (const __nv_bfloat16*)wl,
        bias, C, nullptr, nullptr, M, N, K);
}
static void run_gemm_split(const uint16_t* ah, const uint16_t* al,
                           const uint16_t* wh, const uint16_t* wl,
                           const float* bias, uint16_t* ch, uint16_t* cl,
                           int M, int N, int K) {
    dim3 grid(N / 128, (M + 127) / 128);
    gemm_mma_kernel<1><<<grid, 512, GSMEM>>>(
        (const __nv_bfloat16*)ah, (const __nv_bfloat16*)al,
        (const __nv_bfloat16*)wh, (const __nv_bfloat16*)wl,
        bias, nullptr, (__nv_bfloat16*)ch, (__nv_bfloat16*)cl, M, N, K);
}
static void run_gemm16(const uint16_t* ah, const uint16_t* al,
                       const uint16_t* wh, float* C, int M, int N, int K) {
    dim3 grid(N / 128, (M + 127) / 128);
    gemm16_kernel<1><<<grid, 256, HSMEM>>>(
        (const __half*)ah, (const __half*)wh, C, M, N, K);
    gemm16_kernel<0><<<grid, 256, HSMEM>>>(
        (const __half*)al, (const __half*)wh, C, M, N, K);
}

extern "C" void kernel_launch(void* const* d_in, const int* in_sizes, int n_in,
                              void* d_out, int out_size) {
    const float* x      = (const float*)d_in[0];
    const void*  ei     = d_in[1];
    const float* proj_w = (const float*)d_in[2];
    const float* proj_b = (const float*)d_in[3];
    const float* w1  = (const float*)d_in[4];
    const float* as1 = (const float*)d_in[5];
    const float* ad1 = (const float*)d_in[6];
    const float* b1  = (const float*)d_in[7];
    const float* w2  = (const float*)d_in[8];
    const float* as2 = (const float*)d_in[9];
    const float* ad2 = (const float*)d_in[10];
    const float* b2  = (const float*)d_in[11];
    const float* w3  = (const float*)d_in[12];
    const float* as3 = (const float*)d_in[13];
    const float* ad3 = (const float*)d_in[14];
    const float* b3  = (const float*)d_in[15];
    float* out = (float*)d_out;

    float* hmat;
    uint16_t *P0h, *P0l, *P1h, *P1l, *Wh, *Wl;
    cudaGetSymbolAddress((void**)&hmat, g_hmat);
    cudaGetSymbolAddress((void**)&P0h, g_P0h);
    cudaGetSymbolAddress((void**)&P0l, g_P0l);
    cudaGetSymbolAddress((void**)&P1h, g_P1h);
    cudaGetSymbolAddress((void**)&P1l, g_P1l);
    cudaGetSymbolAddress((void**)&Wh, g_Wh);
    cudaGetSymbolAddress((void**)&Wl, g_Wl);

    static bool attr_set = false;
    if (!attr_set) {
        cudaFuncSetAttribute((const void*)gemm_mma_kernel<0>,
                             cudaFuncAttributeMaxDynamicSharedMemorySize, GSMEM);
        cudaFuncSetAttribute((const void*)gemm_mma_kernel<1>,
                             cudaFuncAttributeMaxDynamicSharedMemorySize, GSMEM);
        cudaFuncSetAttribute((const void*)gemm16_kernel<0>,
                             cudaFuncAttributeMaxDynamicSharedMemorySize, HSMEM);
        cudaFuncSetAttribute((const void*)gemm16_kernel<1>,
                             cudaFuncAttributeMaxDynamicSharedMemorySize, HSMEM);
        attr_set = true;
    }

    // our idx 0-2: input split, proj_w transpose, detect/init
    cvt_split_kernel<<<(NN * 256 / 4 + 255) / 256, 256>>>(x, P0h, P0l, NN * 256 / 4);
    cvt_transpose_bf16_kernel<<<dim3(512 / 32, 256 / 32), dim3(32, 8)>>>(proj_w, Wh, Wl, 256, 512);
    detect_init_kernel<<<(NN + 255) / 256, 256>>>((const unsigned int*)ei);
    // our idx 3: proj GEMM (bf16 3-pass)
    run_gemm_split(P0h, P0l, Wh, Wl, proj_b, P1h, P1l, NN, 512, 256);
    // CSR build
    count_kernel<<<(EE + 255) / 256, 256>>>(ei);
    scan_fillself_kernel<<<1, 1024>>>();
    filledges_kernel<<<(EE + 255) / 256, 256>>>(ei);

    // ---- GAT layer 1 (H=4, C=512, concat, ELU): bf16 3-pass, N=2048, K=512 ----
    cvt_transpose_bf16_kernel<<<dim3(2048 / 32, 512 / 32), dim3(32, 8)>>>(w1, Wh, Wl, 512, 2048);
    run_gemm_f32(P1h, P1l, Wh, Wl, nullptr, hmat, NN, 2048, 512);
    attn_kernel<<<NN, 128>>>(hmat, as1, ad1, 4);
    softmax_kernel<<<(NN * 4 + 255) / 256, 256>>>(4);
    aggregate_kernel<2048, 0><<<NN, 256>>>(hmat, b1, nullptr, P0h, P0l);

    // ---- GAT layer 2 (H=4, C=512, concat, ELU): fp16 2x1-pass, N=2048, K=2048 ----
    cvt_transpose_f16_kernel<<<dim3(2048 / 32, 2048 / 32), dim3(32, 8)>>>(w2, Wh, 2048, 2048);
    run_gemm16(P0h, P0l, Wh, hmat, NN, 2048, 2048);
    attn_kernel<<<NN, 128>>>(hmat, as2, ad2, 4);
    softmax_kernel<<<(NN * 4 + 255) / 256, 256>>>(4);
    aggregate_kernel<2048, 0><<<NN, 256>>>(hmat, b2, nullptr, P1h, P1l);

    // ---- GAT layer 3 (H=2, C=512, mean): fp16 2x1-pass, N=1024, K=2048 ----
    cvt_transpose_f16_kernel<<<dim3(1024 / 32, 2048 / 32), dim3(32, 8)>>>(w3, Wh, 2048, 1024);
    run_gemm16(P1h, P1l, Wh, hmat, NN, 1024, 2048);
    attn_kernel<<<NN, 64>>>(hmat, as3, ad3, 2);
    softmax_kernel<<<(NN * 2 + 255) / 256, 256>>>(2);
    aggregate_kernel<1024, 1><<<NN, 256>>>(hmat, b3, out, nullptr, nullptr);
}

// round 9
// speedup vs baseline: 2.3881x; 1.5747x over previous
#include <cuda_runtime.h>
#include <cuda_bf16.h>
#include <cuda_fp16.h>
#include <math.h>
#include <stdint.h>

#define NN 10000
#define EE 160000
#define ET 170000   // edges + self loops

// ---------------- scratch (device globals; no allocations allowed) ----------
__device__ float g_hmat[NN * 2048];
__device__ float g_es  [NN * 4];
__device__ float g_ed  [NN * 4];
__device__ float g_alpha[ET * 4];
__device__ int   g_counts [NN];
__device__ int   g_rowptr [NN + 1];
__device__ int   g_fillpos[NN];
__device__ int   g_csrsrc [ET];
__device__ int   g_is64;
// 16-bit activation buffers (ping-pong; bf16 or fp16 views) + weight buffers
__device__ __align__(16) uint16_t g_P0h[NN * 2048];
__device__ __align__(16) uint16_t g_P0l[NN * 2048];   // only used for proj input x (bf16 lo)
__device__ __align__(16) uint16_t g_P1h[NN * 2048];
__device__ __align__(16) uint16_t g_Wh[2048 * 2048];
__device__ __align__(16) uint16_t g_Wl[2048 * 2048];  // only used for proj weights (bf16 lo)

// ============================ PTX helpers (baseline, sm_80+) =================
__device__ __forceinline__ uint32_t smem_to_u32(const void* p) {
    uint32_t a;
    asm("{ .reg .u64 t; cvta.to.shared.u64 t, %1; cvt.u32.u64 %0, t; }" : "=r"(a) : "l"(p));
    return a;
}

__device__ __forceinline__ void cp16(uint32_t dst, const void* src, bool v) {
    int sz = v ? 16 : 0;
    asm volatile("cp.async.cg.shared.global [%0], [%1], 16, %2;\n"
                 :: "r"(dst), "l"(src), "r"(sz) : "memory");
}
#define CP_COMMIT() asm volatile("cp.async.commit_group;" ::: "memory")
#define CP_WAIT1()  asm volatile("cp.async.wait_group 1;" ::: "memory")

__device__ __forceinline__ void ldsm4(uint32_t* r, uint32_t addr) {
    asm volatile("ldmatrix.sync.aligned.m8n8.x4.shared.b16 {%0,%1,%2,%3}, [%4];"
                 : "=r"(r[0]), "=r"(r[1]), "=r"(r[2]), "=r"(r[3]) : "r"(addr));
}

__device__ __forceinline__ void mma_bf16(float* c, const uint32_t* a, const uint32_t* b) {
    asm volatile(
        "mma.sync.aligned.m16n8k16.row.col.f32.bf16.bf16.f32 "
        "{%0,%1,%2,%3}, {%4,%5,%6,%7}, {%8,%9}, {%0,%1,%2,%3};"
        : "+f"(c[0]), "+f"(c[1]), "+f"(c[2]), "+f"(c[3])
        : "r"(a[0]), "r"(a[1]), "r"(a[2]), "r"(a[3]), "r"(b[0]), "r"(b[1]));
}
__device__ __forceinline__ void mma_fp16(float* c, const uint32_t* a, const uint32_t* b) {
    asm volatile(
        "mma.sync.aligned.m16n8k16.row.col.f32.f16.f16.f32 "
        "{%0,%1,%2,%3}, {%4,%5,%6,%7}, {%8,%9}, {%0,%1,%2,%3};"
        : "+f"(c[0]), "+f"(c[1]), "+f"(c[2]), "+f"(c[3])
        : "r"(a[0]), "r"(a[1]), "r"(a[2]), "r"(a[3]), "r"(b[0]), "r"(b[1]));
}

__device__ __forceinline__ int edge_at(const void* ei, long long idx) {
    if (g_is64) return (int)((const long long*)ei)[idx];
    return ((const int*)ei)[idx];
}

// ---------------- CSR build ---------------------------------------------------
__global__ void detect_init_kernel(const unsigned int* p) {
    int i = blockIdx.x * blockDim.x + threadIdx.x;
    if (i < NN) g_counts[i] = 1;           // self loop pre-counted
    if (i == 0) {
        int is64 = 1;
        for (int j = 0; j < 128; j++)
            if (p[2 * j + 1] != 0u) { is64 = 0; break; }
        g_is64 = is64;
    }
}
__global__ void count_kernel(const void* ei) {
    int e = blockIdx.x * blockDim.x + threadIdx.x;
    if (e < EE) atomicAdd(&g_counts[edge_at(ei, (long long)EE + e)], 1);
}
__global__ void scan_fillself_kernel() {
    __shared__ int sh[1024];
    int t = threadIdx.x;
    const int chunk = (NN + 1023) >> 10;
    int base = t * chunk;
    int s = 0;
    for (int j = 0; j < chunk; j++) { int idx = base + j; if (idx < NN) s += g_counts[idx]; }
    sh[t] = s;
    __syncthreads();
    for (int off = 1; off < 1024; off <<= 1) {
        int v = (t >= off) ? sh[t - off] : 0;
        __syncthreads();
        sh[t] += v;
        __syncthreads();
    }
    int prefix = (t > 0) ? sh[t - 1] : 0;
    for (int j = 0; j < chunk; j++) {
        int idx = base + j;
        if (idx < NN) { g_rowptr[idx] = prefix; prefix += g_counts[idx]; }
    }
    if (t == 0) g_rowptr[NN] = sh[1023];
    __syncthreads();
    for (int idx = t; idx < NN; idx += 1024) {
        int r = g_rowptr[idx];
        g_csrsrc[r] = idx;
        g_fillpos[idx] = r + 1;
    }
}
__global__ void filledges_kernel(const void* ei) {
    int e = blockIdx.x * blockDim.x + threadIdx.x;
    if (e < EE) {
        int s = edge_at(ei, e);
        int d = edge_at(ei, (long long)EE + e);
        g_csrsrc[atomicAdd(&g_fillpos[d], 1)] = s;
    }
}

// ---------------- fp32 -> bf16 hi/lo split (input x only) --------------------
__global__ void cvt_split_kernel(const float* __restrict__ x,
                                 uint16_t* __restrict__ hi,
                                 uint16_t* __restrict__ lo, int n4) {
    int i = blockIdx.x * blockDim.x + threadIdx.x;
    if (i >= n4) return;
    float4 v = ((const float4*)x)[i];
    __nv_bfloat16 h0 = __float2bfloat16(v.x);
    __nv_bfloat16 h1 = __float2bfloat16(v.y);
    __nv_bfloat16 h2 = __float2bfloat16(v.z);
    __nv_bfloat16 h3 = __float2bfloat16(v.w);
    __nv_bfloat16 l0 = __float2bfloat16(v.x - __bfloat162float(h0));
    __nv_bfloat16 l1 = __float2bfloat16(v.y - __bfloat162float(h1));
    __nv_bfloat16 l2 = __float2bfloat16(v.z - __bfloat162float(h2));
    __nv_bfloat16 l3 = __float2bfloat16(v.w - __bfloat162float(h3));
    ((__nv_bfloat162*)hi)[2 * i]     = __nv_bfloat162(h0, h1);
    ((__nv_bfloat162*)hi)[2 * i + 1] = __nv_bfloat162(h2, h3);
    ((__nv_bfloat162*)lo)[2 * i]     = __nv_bfloat162(l0, l1);
    ((__nv_bfloat162*)lo)[2 * i + 1] = __nv_bfloat162(l2, l3);
}

// ---------------- weight transpose: W[K,N] -> Wt[N,K] ------------------------
__global__ void cvt_transpose_bf16_kernel(const float* __restrict__ W,
                                          uint16_t* __restrict__ th,
                                          uint16_t* __restrict__ tl, int K, int N) {
    __shared__ float tile[32][33];
    int n0 = blockIdx.x * 32, k0 = blockIdx.y * 32;
    int tx = threadIdx.x, ty = threadIdx.y;   // 32 x 8
    for (int r = ty; r < 32; r += 8)
        tile[r][tx] = W[(size_t)(k0 + r) * N + n0 + tx];
    __syncthreads();
    for (int r = ty; r < 32; r += 8) {
        float v = tile[tx][r];
        __nv_bfloat16 h = __float2bfloat16(v);
        size_t o = (size_t)(n0 + r) * K + k0 + tx;
        ((__nv_bfloat16*)th)[o] = h;
        ((__nv_bfloat16*)tl)[o] = __float2bfloat16(v - __bfloat162float(h));
    }
}
__global__ void cvt_transpose_f16_kernel(const float* __restrict__ W,
                                         uint16_t* __restrict__ th, int K, int N) {
    __shared__ float tile[32][33];
    int n0 = blockIdx.x * 32, k0 = blockIdx.y * 32;
    int tx = threadIdx.x, ty = threadIdx.y;
    for (int r = ty; r < 32; r += 8)
        tile[r][tx] = W[(size_t)(k0 + r) * N + n0 + tx];
    __syncthreads();
    for (int r = ty; r < 32; r += 8)
        ((__half*)th)[(size_t)(n0 + r) * K + k0 + tx] = __float2half(tile[tx][r]);
}

__device__ __forceinline__ uint32_t swz(uint32_t base, int row, int kelem) {
    return base + row * 128 + ((((kelem >> 3) ^ row) & 7) << 4);
}

// ---------------- bf16 3-pass GEMM (proj only) --------------------------------
// CTA 128x128, BK=64, 3-stage, 512 threads / 16 warps, warp tile 32x32.
// Epilogue: fp16 out (+bias).
#define GT 16384
#define GSTAGE (4 * GT)
#define GSMEM  (3 * GSTAGE)           // 196608

__global__ void __launch_bounds__(512, 1) gemm_mma_kernel(
    const __nv_bfloat16* __restrict__ Ah, const __nv_bfloat16* __restrict__ Al,
    const __nv_bfloat16* __restrict__ Bh, const __nv_bfloat16* __restrict__ Bl,
    const float* __restrict__ bias, __half* __restrict__ Ch,
    int M, int N, int K)
{
    extern __shared__ char smem[];
    const uint32_t sb = smem_to_u32(smem);
    const int tid = threadIdx.x;
    const int lane = tid & 31, wid = tid >> 5;
    const int m0 = blockIdx.y * 128, n0 = blockIdx.x * 128;
    const int nk = K >> 6;

    auto load_stage = [&](int s, int j) {
        const uint32_t sbase = sb + (uint32_t)s * GSTAGE;
        const int lchk = tid & 7;
        const int lrow = tid >> 3;          // 0..63
        const bool jv = (j < nk);
        const long long k0 = jv ? ((long long)j << 6) : 0;
#pragma unroll
        for (int it = 0; it < 2; it++) {
            int row = lrow + it * 64;
            bool av = jv && (m0 + row < M);
            int gr = (m0 + row < M) ? (m0 + row) : 0;
            size_t aoff = (size_t)gr * K + k0 + lchk * 8;
            size_t boff = (size_t)(n0 + row) * K + k0 + lchk * 8;
            uint32_t d = swz(sbase, row, lchk * 8);
            cp16(d,      Ah + aoff, av);
            cp16(d + GT, Al + aoff, av);
            uint32_t db = swz(sbase + 2 * GT, row, lchk * 8);
            cp16(db,      Bh + boff, jv);
            cp16(db + GT, Bl + boff, jv);
        }
    };

    float acc[2][4][4];
#pragma unroll
    for (int a = 0; a < 2; a++)
#pragma unroll
        for (int b = 0; b < 4; b++)
#pragma unroll
            for (int c = 0; c < 4; c++) acc[a][b][c] = 0.f;

    load_stage(0, 0);
    CP_COMMIT();
    load_stage(1, 1);
    CP_COMMIT();

    const int mw = (wid & 3) * 32;
    const int nw = (wid >> 2) * 32;
    const int rsel = lane & 15;
    const int khalf = (lane >> 4) * 8;

    for (int i = 0; i < nk; i++) {
        CP_WAIT1();
        __syncthreads();
        load_stage((i + 2) % 3, i + 2);
        CP_COMMIT();

        const uint32_t sA = sb + (uint32_t)(i % 3) * GSTAGE;
        const uint32_t sB = sA + 2 * GT;
#pragma unroll
        for (int ks = 0; ks < 4; ks++) {
            const int ke = ks * 16 + khalf;
            uint32_t ah[2][4], al[2][4], bh[2][4], bl[2][4];
#pragma unroll
            for (int mi = 0; mi < 2; mi++) {
                uint32_t ad = swz(sA, mw + mi * 16 + rsel, ke);
                ldsm4(ah[mi], ad);
                ldsm4(al[mi], ad + GT);
            }
#pragma unroll
            for (int bi = 0; bi < 2; bi++) {
                uint32_t bd = swz(sB, nw + bi * 16 + rsel, ke);
                ldsm4(bh[bi], bd);
                ldsm4(bl[bi], bd + GT);
            }
#pragma unroll
            for (int mi = 0; mi < 2; mi++)
#pragma unroll
                for (int nj = 0; nj < 4; nj++) {
                    uint32_t b2[2] = { bh[nj >> 1][nj & 1], bh[nj >> 1][(nj & 1) + 2] };
                    mma_bf16(acc[mi][nj], ah[mi], b2);
                }
#pragma unroll
            for (int mi = 0; mi < 2; mi++)
#pragma unroll
                for (int nj = 0; nj < 4; nj++) {
                    uint32_t b2[2] = { bl[nj >> 1][nj & 1], bl[nj >> 1][(nj & 1) + 2] };
                    mma_bf16(acc[mi][nj], ah[mi], b2);
                }
#pragma unroll
            for (int mi = 0; mi < 2; mi++)
#pragma unroll
                for (int nj = 0; nj < 4; nj++) {
                    uint32_t b2[2] = { bh[nj >> 1][nj & 1], bh[nj >> 1][(nj & 1) + 2] };
                    mma_bf16(acc[mi][nj], al[mi], b2);
                }
        }
    }

#pragma unroll
    for (int mi = 0; mi < 2; mi++) {
#pragma unroll
        for (int nj = 0; nj < 4; nj++) {
            int col = n0 + nw + nj * 8 + (lane & 3) * 2;
            float bx = bias ? bias[col] : 0.f;
            float by = bias ? bias[col + 1] : 0.f;
            int r0 = m0 + mw + mi * 16 + (lane >> 2);
            int r1 = r0 + 8;
            if (r0 < M) {
                ((__half2*)Ch)[((size_t)r0 * N + col) >> 1] =
                    __halves2half2(__float2half(acc[mi][nj][0] + bx),
                                   __float2half(acc[mi][nj][1] + by));
            }
            if (r1 < M) {
                ((__half2*)Ch)[((size_t)r1 * N + col) >> 1] =
                    __halves2half2(__float2half(acc[mi][nj][2] + bx),
                                   __float2half(acc[mi][nj][3] + by));
            }
        }
    }
}

// ---------------- fp16 single-pass GEMM (layers 1/2/3) -----------------------
// CTA 128x128, BK=64, 3-stage, 256 threads / 8 warps (4x2), warp tile 32x64.
// smem 96KB -> 2 CTAs/SM. C = A @ B^T (fp32 out, no bias).
#define HT 16384
#define HSTAGE (2 * HT)
#define HSMEM  (3 * HSTAGE)           // 98304

__global__ void __launch_bounds__(256, 2) gemm16_kernel(
    const __half* __restrict__ A, const __half* __restrict__ B,
    float* __restrict__ C, int M, int N, int K)
{
    extern __shared__ char smem[];
    const uint32_t sb = smem_to_u32(smem);
    const int tid = threadIdx.x;
    const int lane = tid & 31, wid = tid >> 5;
    const int m0 = blockIdx.y * 128, n0 = blockIdx.x * 128;
    const int nk = K >> 6;

    auto load_stage = [&](int s, int j) {
        const uint32_t sbase = sb + (uint32_t)s * HSTAGE;
        const int lchk = tid & 7;
        const int lrow = tid >> 3;        // 0..31
        const bool jv = (j < nk);
        const long long k0 = jv ? ((long long)j << 6) : 0;
#pragma unroll
        for (int it = 0; it < 4; it++) {
            int row = lrow + it * 32;
            bool av = jv && (m0 + row < M);
            int gr = (m0 + row < M) ? (m0 + row) : 0;
            cp16(swz(sbase, row, lchk * 8),
                 A + (size_t)gr * K + k0 + lchk * 8, av);
            cp16(swz(sbase + HT, row, lchk * 8),
                 B + (size_t)(n0 + row) * K + k0 + lchk * 8, jv);
        }
    };

    float acc[2][8][4];
#pragma unroll
    for (int a = 0; a < 2; a++)
#pragma unroll
        for (int b = 0; b < 8; b++)
#pragma unroll
            for (int c = 0; c < 4; c++) acc[a][b][c] = 0.f;

    load_stage(0, 0);
    CP_COMMIT();
    load_stage(1, 1);
    CP_COMMIT();

    const int mw = (wid & 3) * 32;      // 4 warp rows
    const int nw = (wid >> 2) * 64;     // 2 warp cols
    const int rsel = lane & 15;
    const int khalf = (lane >> 4) * 8;

    for (int i = 0; i < nk; i++) {
        CP_WAIT1();
        __syncthreads();
        load_stage((i + 2) % 3, i + 2);
        CP_COMMIT();

        const uint32_t sA = sb + (uint32_t)(i % 3) * HSTAGE;
        const uint32_t sB = sA + HT;
#pragma unroll
        for (int ks = 0; ks < 4; ks++) {
            const int ke = ks * 16 + khalf;
            uint32_t a[2][4], b[4][4];
#pragma unroll
            for (int mi = 0; mi < 2; mi++)
                ldsm4(a[mi], swz(sA, mw + mi * 16 + rsel, ke));
#pragma unroll
            for (int bi = 0; bi < 4; bi++)
                ldsm4(b[bi], swz(sB, nw + bi * 16 + rsel, ke));
#pragma unroll
            for (int mi = 0; mi < 2; mi++)
#pragma unroll
                for (int nj = 0; nj < 8; nj++) {
                    uint32_t b2[2] = { b[nj >> 1][nj & 1], b[nj >> 1][(nj & 1) + 2] };
                    mma_fp16(acc[mi][nj], a[mi], b2);
                }
        }
    }

#pragma unroll
    for (int mi = 0; mi < 2; mi++) {
#pragma unroll
        for (int nj = 0; nj < 8; nj++) {
            int col = n0 + nw + nj * 8 + (lane & 3) * 2;
            int r0 = m0 + mw + mi * 16 + (lane >> 2);
            int r1 = r0 + 8;
            if (r0 < M)
                *(float2*)(C + (size_t)r0 * N + col) =
                    make_float2(acc[mi][nj][0], acc[mi][nj][1]);
            if (r1 < M)
                *(float2*)(C + (size_t)r1 * N + col) =
                    make_float2(acc[mi][nj][2], acc[mi][nj][3]);
        }
    }
}

// ---------------- per-node attention coefficients es/ed ----------------------
__global__ void attn_kernel(const float* __restrict__ hmat,
                            const float* __restrict__ a_src,
                            const float* __restrict__ a_dst, int H) {
    const int C = 512;
    int i = blockIdx.x;
    int hh = threadIdx.x >> 5;
    int lane = threadIdx.x & 31;
    const float* hr = hmat + (size_t)i * H * C + hh * C;
    float s = 0.f, d = 0.f;
    for (int c = lane; c < C; c += 32) {
        float v = hr[c];
        s += v * a_src[hh * C + c];
        d += v * a_dst[hh * C + c];
    }
#pragma unroll
    for (int o = 16; o > 0; o >>= 1) {
        s += __shfl_xor_sync(0xffffffffu, s, o);
        d += __shfl_xor_sync(0xffffffffu, d, o);
    }
    if (lane == 0) { g_es[i * H + hh] = s; g_ed[i * H + hh] = d; }
}

// ---------------- segment softmax over dst-CSR rows --------------------------
__global__ void softmax_kernel(int H) {
    int idx = blockIdx.x * blockDim.x + threadIdx.x;
    if (idx >= NN * H) return;
    int i = idx % NN;
    int hh = idx / NN;
    float edi = g_ed[i * H + hh];
    int p0 = g_rowptr[i], p1 = g_rowptr[i + 1];
    float m = -1e30f;
    for (int p = p0; p < p1; p++) {
        float e = g_es[g_csrsrc[p] * H + hh] + edi;
        e = (e > 0.f) ? e : 0.2f * e;
        m = fmaxf(m, e);
    }
    float den = 0.f;
    for (int p = p0; p < p1; p++) {
        float e = g_es[g_csrsrc[p] * H + hh] + edi;
        e = (e > 0.f) ? e : 0.2f * e;
        float a = expf(e - m);
        g_alpha[p * 4 + hh] = a;
        den += a;
    }
    float inv = 1.f / den;
    for (int p = p0; p < p1; p++) g_alpha[p * 4 + hh] *= inv;
}

// ---------------- weighted aggregation (float4) ------------------------------
// MODE 0: concat heads + bias + ELU, write fp16 (next GEMM input).
// MODE 1: mean over 2 heads + bias, write fp32.
template <int HC, int MODE>
__global__ void aggregate_kernel(const float* __restrict__ hmat,
                                 const float* __restrict__ bias,
                                 float* __restrict__ outF,
                                 uint16_t* __restrict__ outH) {
    constexpr int PT = HC / 1024;
    int i = blockIdx.x;
    int t = threadIdx.x;
    int hsel = t >> 7;
    float4 acc[PT];
#pragma unroll
    for (int k = 0; k < PT; k++) acc[k] = make_float4(0.f, 0.f, 0.f, 0.f);

    int p0 = g_rowptr[i], p1 = g_rowptr[i + 1];
    for (int p = p0; p < p1; p++) {
        int s = g_csrsrc[p];
        float4 a4 = *(const float4*)(g_alpha + p * 4);
        const float* al = (const float*)&a4;
        const float4* hr = (const float4*)(hmat + (size_t)s * HC);
#pragma unroll
        for (int k = 0; k < PT; k++) {
            float av = al[2 * k + hsel];
            float4 h = hr[t + k * 256];
            acc[k].x += av * h.x;
            acc[k].y += av * h.y;
            acc[k].z += av * h.z;
            acc[k].w += av * h.w;
        }
    }

    if (MODE == 0) {
#pragma unroll
        for (int k = 0; k < PT; k++) {
            int col4 = t + k * 256;
            float4 b = *(const float4*)(bias + col4 * 4);
            float4 v = acc[k];
            v.x += b.x; v.y += b.y; v.z += b.z; v.w += b.w;
            v.x = (v.x > 0.f) ? v.x : (expf(v.x) - 1.f);
            v.y = (v.y > 0.f) ? v.y : (expf(v.y) - 1.f);
            v.z = (v.z > 0.f) ? v.z : (expf(v.z) - 1.f);
            v.w = (v.w > 0.f) ? v.w : (expf(v.w) - 1.f);
            size_t o2 = ((size_t)i * HC + col4 * 4) >> 1;
            ((__half2*)outH)[o2]     = __halves2half2(__float2half(v.x), __float2half(v.y));
            ((__half2*)outH)[o2 + 1] = __halves2half2(__float2half(v.z), __float2half(v.w));
        }
    } else {
        __shared__ float4 sh[256];
        sh[t] = acc[0];
        __syncthreads();
        if (t < 128) {
            float4 v0 = sh[t], v1 = sh[t + 128];
            float4 b = ((const float4*)bias)[t];
            float4 r;
            r.x = 0.5f * (v0.x + v1.x) + b.x;
            r.y = 0.5f * (v0.y + v1.y) + b.y;
            r.z = 0.5f * (v0.z + v1.z) + b.z;
            r.w = 0.5f * (v0.w + v1.w) + b.w;
            ((float4*)outF)[(size_t)i * 128 + t] = r;
        }
    }
}

// ---------------- host launch helpers ----------------------------------------
static void run_proj(const uint16_t* ah, const uint16_t* al,
                     const uint16_t* wh, const uint16_t* wl,
                     const float* bias, uint16_t* ch, int M, int N, int K) {
    dim3 grid(N / 128, (M + 127) / 128);
    gemm_mma_kernel<<<grid, 512, GSMEM>>>(
        (const __nv_bfloat16*)ah, (const __nv_bfloat16*)al,
        (const __nv_bfloat16*)wh, (const __nv_bfloat16*)wl,
        bias, (__half*)ch, M, N, K);
}
static void run_gemm16(const uint16_t* a, const uint16_t* w,
                       float* C, int M, int N, int K) {
    dim3 grid(N / 128, (M + 127) / 128);
    gemm16_kernel<<<grid, 256, HSMEM>>>((const __half*)a, (const __half*)w, C, M, N, K);
}

extern "C" void kernel_launch(void* const* d_in, const int* in_sizes, int n_in,
                              void* d_out, int out_size) {
    const float* x      = (const float*)d_in[0];
    const void*  ei     = d_in[1];
    const float* proj_w = (const float*)d_in[2];
    const float* proj_b = (const float*)d_in[3];
    const float* w1  = (const float*)d_in[4];
    const float* as1 = (const float*)d_in[5];
    const float* ad1 = (const float*)d_in[6];
    const float* b1  = (const float*)d_in[7];
    const float* w2  = (const float*)d_in[8];
    const float* as2 = (const float*)d_in[9];
    const float* ad2 = (const float*)d_in[10];
    const float* b2  = (const float*)d_in[11];
    const float* w3  = (const float*)d_in[12];
    const float* as3 = (const float*)d_in[13];
    const float* ad3 = (const float*)d_in[14];
    const float* b3  = (const float*)d_in[15];
    float* out = (float*)d_out;

    float* hmat;
    uint16_t *P0h, *P0l, *P1h, *Wh, *Wl;
    cudaGetSymbolAddress((void**)&hmat, g_hmat);
    cudaGetSymbolAddress((void**)&P0h, g_P0h);
    cudaGetSymbolAddress((void**)&P0l, g_P0l);
    cudaGetSymbolAddress((void**)&P1h, g_P1h);
    cudaGetSymbolAddress((void**)&Wh, g_Wh);
    cudaGetSymbolAddress((void**)&Wl, g_Wl);

    static bool attr_set = false;
    if (!attr_set) {
        cudaFuncSetAttribute((const void*)gemm_mma_kernel,
                             cudaFuncAttributeMaxDynamicSharedMemorySize, GSMEM);
        cudaFuncSetAttribute((const void*)gemm16_kernel,
                             cudaFuncAttributeMaxDynamicSharedMemorySize, HSMEM);
        attr_set = true;
    }

    // our idx 0-2: input split, proj_w transpose, detect/init
    cvt_split_kernel<<<(NN * 256 / 4 + 255) / 256, 256>>>(x, P0h, P0l, NN * 256 / 4);
    cvt_transpose_bf16_kernel<<<dim3(512 / 32, 256 / 32), dim3(32, 8)>>>(proj_w, Wh, Wl, 256, 512);
    detect_init_kernel<<<(NN + 255) / 256, 256>>>((const unsigned int*)ei);
    // our idx 3: proj GEMM (bf16 3-pass, fp16 out)
    run_proj(P0h, P0l, Wh, Wl, proj_b, P1h, NN, 512, 256);
    // CSR build
    count_kernel<<<(EE + 255) / 256, 256>>>(ei);
    scan_fillself_kernel<<<1, 1024>>>();
    filledges_kernel<<<(EE + 255) / 256, 256>>>(ei);

    // ---- GAT layer 1 (H=4, C=512, concat, ELU): fp16 1-pass, N=2048, K=512 ----
    cvt_transpose_f16_kernel<<<dim3(2048 / 32, 512 / 32), dim3(32, 8)>>>(w1, Wh, 512, 2048);
    run_gemm16(P1h, Wh, hmat, NN, 2048, 512);
    attn_kernel<<<NN, 128>>>(hmat, as1, ad1, 4);
    softmax_kernel<<<(NN * 4 + 255) / 256, 256>>>(4);
    aggregate_kernel<2048, 0><<<NN, 256>>>(hmat, b1, nullptr, P0h);

    // ---- GAT layer 2 (H=4, C=512, concat, ELU): fp16 1-pass, N=2048, K=2048 ----
    cvt_transpose_f16_kernel<<<dim3(2048 / 32, 2048 / 32), dim3(32, 8)>>>(w2, Wh, 2048, 2048);
    run_gemm16(P0h, Wh, hmat, NN, 2048, 2048);
    attn_kernel<<<NN, 128>>>(hmat, as2, ad2, 4);
    softmax_kernel<<<(NN * 4 + 255) / 256, 256>>>(4);
    aggregate_kernel<2048, 0><<<NN, 256>>>(hmat, b2, nullptr, P1h);

    // ---- GAT layer 3 (H=2, C=512, mean): fp16 1-pass, N=1024, K=2048 ----
    cvt_transpose_f16_kernel<<<dim3(1024 / 32, 2048 / 32), dim3(32, 8)>>>(w3, Wh, 2048, 1024);
    run_gemm16(P1h, Wh, hmat, NN, 1024, 2048);
    attn_kernel<<<NN, 64>>>(hmat, as3, ad3, 2);
    softmax_kernel<<<(NN * 2 + 255) / 256, 256>>>(2);
    aggregate_kernel<1024, 1><<<NN, 256>>>(hmat, b3, out, nullptr);
}

// round 10
// speedup vs baseline: 2.8165x; 1.1794x over previous
#include <cuda_runtime.h>
#include <cuda_bf16.h>
#include <cuda_fp16.h>
#include <math.h>
#include <stdint.h>

#define NN 10000
#define EE 160000
#define ET 170000   // edges + self loops

// ---------------- scratch (device globals; no allocations allowed) ----------
__device__ __align__(16) __half g_hmat[NN * 2048];   // fp16 GEMM output
__device__ float g_es  [NN * 4];
__device__ float g_ed  [NN * 4];
__device__ float g_alpha[ET * 4];
__device__ int   g_counts [NN];
__device__ int   g_rowptr [NN + 1];
__device__ int   g_fillpos[NN];
__device__ int   g_csrsrc [ET];
__device__ int   g_is64;
// 16-bit activation buffers (ping-pong) + weight buffers
__device__ __align__(16) uint16_t g_P0h[NN * 2048];
__device__ __align__(16) uint16_t g_P0l[NN * 2048];   // proj input x bf16-lo only
__device__ __align__(16) uint16_t g_P1h[NN * 2048];
__device__ __align__(16) uint16_t g_Wh[2048 * 2048];
__device__ __align__(16) uint16_t g_Wl[2048 * 2048];  // proj weights bf16-lo only

// ============================ PTX helpers (baseline, sm_80+) =================
__device__ __forceinline__ uint32_t smem_to_u32(const void* p) {
    uint32_t a;
    asm("{ .reg .u64 t; cvta.to.shared.u64 t, %1; cvt.u32.u64 %0, t; }" : "=r"(a) : "l"(p));
    return a;
}

__device__ __forceinline__ void cp16(uint32_t dst, const void* src, bool v) {
    int sz = v ? 16 : 0;
    asm volatile("cp.async.cg.shared.global [%0], [%1], 16, %2;\n"
                 :: "r"(dst), "l"(src), "r"(sz) : "memory");
}
#define CP_COMMIT() asm volatile("cp.async.commit_group;" ::: "memory")
#define CP_WAIT1()  asm volatile("cp.async.wait_group 1;" ::: "memory")

__device__ __forceinline__ void ldsm4(uint32_t* r, uint32_t addr) {
    asm volatile("ldmatrix.sync.aligned.m8n8.x4.shared.b16 {%0,%1,%2,%3}, [%4];"
                 : "=r"(r[0]), "=r"(r[1]), "=r"(r[2]), "=r"(r[3]) : "r"(addr));
}

__device__ __forceinline__ void mma_bf16(float* c, const uint32_t* a, const uint32_t* b) {
    asm volatile(
        "mma.sync.aligned.m16n8k16.row.col.f32.bf16.bf16.f32 "
        "{%0,%1,%2,%3}, {%4,%5,%6,%7}, {%8,%9}, {%0,%1,%2,%3};"
        : "+f"(c[0]), "+f"(c[1]), "+f"(c[2]), "+f"(c[3])
        : "r"(a[0]), "r"(a[1]), "r"(a[2]), "r"(a[3]), "r"(b[0]), "r"(b[1]));
}
__device__ __forceinline__ void mma_fp16(float* c, const uint32_t* a, const uint32_t* b) {
    asm volatile(
        "mma.sync.aligned.m16n8k16.row.col.f32.f16.f16.f32 "
        "{%0,%1,%2,%3}, {%4,%5,%6,%7}, {%8,%9}, {%0,%1,%2,%3};"
        : "+f"(c[0]), "+f"(c[1]), "+f"(c[2]), "+f"(c[3])
        : "r"(a[0]), "r"(a[1]), "r"(a[2]), "r"(a[3]), "r"(b[0]), "r"(b[1]));
}

__device__ __forceinline__ int edge_at(const void* ei, long long idx) {
    if (g_is64) return (int)((const long long*)ei)[idx];
    return ((const int*)ei)[idx];
}

// ---------------- CSR build ---------------------------------------------------
__global__ void detect_init_kernel(const unsigned int* p) {
    int i = blockIdx.x * blockDim.x + threadIdx.x;
    if (i < NN) g_counts[i] = 1;           // self loop pre-counted
    if (i == 0) {
        int is64 = 1;
        for (int j = 0; j < 128; j++)
            if (p[2 * j + 1] != 0u) { is64 = 0; break; }
        g_is64 = is64;
    }
}
__global__ void count_kernel(const void* ei) {
    int e = blockIdx.x * blockDim.x + threadIdx.x;
    if (e < EE) atomicAdd(&g_counts[edge_at(ei, (long long)EE + e)], 1);
}
__global__ void scan_fillself_kernel() {
    __shared__ int sh[1024];
    int t = threadIdx.x;
    const int chunk = (NN + 1023) >> 10;
    int base = t * chunk;
    int s = 0;
    for (int j = 0; j < chunk; j++) { int idx = base + j; if (idx < NN) s += g_counts[idx]; }
    sh[t] = s;
    __syncthreads();
    for (int off = 1; off < 1024; off <<= 1) {
        int v = (t >= off) ? sh[t - off] : 0;
        __syncthreads();
        sh[t] += v;
        __syncthreads();
    }
    int prefix = (t > 0) ? sh[t - 1] : 0;
    for (int j = 0; j < chunk; j++) {
        int idx = base + j;
        if (idx < NN) { g_rowptr[idx] = prefix; prefix += g_counts[idx]; }
    }
    if (t == 0) g_rowptr[NN] = sh[1023];
    __syncthreads();
    for (int idx = t; idx < NN; idx += 1024) {
        int r = g_rowptr[idx];
        g_csrsrc[r] = idx;
        g_fillpos[idx] = r + 1;
    }
}
__global__ void filledges_kernel(const void* ei) {
    int e = blockIdx.x * blockDim.x + threadIdx.x;
    if (e < EE) {
        int s = edge_at(ei, e);
        int d = edge_at(ei, (long long)EE + e);
        g_csrsrc[atomicAdd(&g_fillpos[d], 1)] = s;
    }
}

// ---------------- fp32 -> bf16 hi/lo split (input x only) --------------------
__global__ void cvt_split_kernel(const float* __restrict__ x,
                                 uint16_t* __restrict__ hi,
                                 uint16_t* __restrict__ lo, int n4) {
    int i = blockIdx.x * blockDim.x + threadIdx.x;
    if (i >= n4) return;
    float4 v = ((const float4*)x)[i];
    __nv_bfloat16 h0 = __float2bfloat16(v.x);
    __nv_bfloat16 h1 = __float2bfloat16(v.y);
    __nv_bfloat16 h2 = __float2bfloat16(v.z);
    __nv_bfloat16 h3 = __float2bfloat16(v.w);
    __nv_bfloat16 l0 = __float2bfloat16(v.x - __bfloat162float(h0));
    __nv_bfloat16 l1 = __float2bfloat16(v.y - __bfloat162float(h1));
    __nv_bfloat16 l2 = __float2bfloat16(v.z - __bfloat162float(h2));
    __nv_bfloat16 l3 = __float2bfloat16(v.w - __bfloat162float(h3));
    ((__nv_bfloat162*)hi)[2 * i]     = __nv_bfloat162(h0, h1);
    ((__nv_bfloat162*)hi)[2 * i + 1] = __nv_bfloat162(h2, h3);
    ((__nv_bfloat162*)lo)[2 * i]     = __nv_bfloat162(l0, l1);
    ((__nv_bfloat162*)lo)[2 * i + 1] = __nv_bfloat162(l2, l3);
}

// ---------------- weight transpose: W[K,N] -> Wt[N,K] ------------------------
__global__ void cvt_transpose_bf16_kernel(const float* __restrict__ W,
                                          uint16_t* __restrict__ th,
                                          uint16_t* __restrict__ tl, int K, int N) {
    __shared__ float tile[32][33];
    int n0 = blockIdx.x * 32, k0 = blockIdx.y * 32;
    int tx = threadIdx.x, ty = threadIdx.y;   // 32 x 8
    for (int r = ty; r < 32; r += 8)
        tile[r][tx] = W[(size_t)(k0 + r) * N + n0 + tx];
    __syncthreads();
    for (int r = ty; r < 32; r += 8) {
        float v = tile[tx][r];
        __nv_bfloat16 h = __float2bfloat16(v);
        size_t o = (size_t)(n0 + r) * K + k0 + tx;
        ((__nv_bfloat16*)th)[o] = h;
        ((__nv_bfloat16*)tl)[o] = __float2bfloat16(v - __bfloat162float(h));
    }
}
__global__ void cvt_transpose_f16_kernel(const float* __restrict__ W,
                                         uint16_t* __restrict__ th, int K, int N) {
    __shared__ float tile[32][33];
    int n0 = blockIdx.x * 32, k0 = blockIdx.y * 32;
    int tx = threadIdx.x, ty = threadIdx.y;
    for (int r = ty; r < 32; r += 8)
        tile[r][tx] = W[(size_t)(k0 + r) * N + n0 + tx];
    __syncthreads();
    for (int r = ty; r < 32; r += 8)
        ((__half*)th)[(size_t)(n0 + r) * K + k0 + tx] = __float2half(tile[tx][r]);
}

__device__ __forceinline__ uint32_t swz(uint32_t base, int row, int kelem) {
    return base + row * 128 + ((((kelem >> 3) ^ row) & 7) << 4);
}

// ---------------- bf16 3-pass GEMM (proj only) --------------------------------
#define GT 16384
#define GSTAGE (4 * GT)
#define GSMEM  (3 * GSTAGE)           // 196608

__global__ void __launch_bounds__(512, 1) gemm_mma_kernel(
    const __nv_bfloat16* __restrict__ Ah, const __nv_bfloat16* __restrict__ Al,
    const __nv_bfloat16* __restrict__ Bh, const __nv_bfloat16* __restrict__ Bl,
    const float* __restrict__ bias, __half* __restrict__ Ch,
    int M, int N, int K)
{
    extern __shared__ char smem[];
    const uint32_t sb = smem_to_u32(smem);
    const int tid = threadIdx.x;
    const int lane = tid & 31, wid = tid >> 5;
    const int m0 = blockIdx.y * 128, n0 = blockIdx.x * 128;
    const int nk = K >> 6;

    auto load_stage = [&](int s, int j) {
        const uint32_t sbase = sb + (uint32_t)s * GSTAGE;
        const int lchk = tid & 7;
        const int lrow = tid >> 3;          // 0..63
        const bool jv = (j < nk);
        const long long k0 = jv ? ((long long)j << 6) : 0;
#pragma unroll
        for (int it = 0; it < 2; it++) {
            int row = lrow + it * 64;
            bool av = jv && (m0 + row < M);
            int gr = (m0 + row < M) ? (m0 + row) : 0;
            size_t aoff = (size_t)gr * K + k0 + lchk * 8;
            size_t boff = (size_t)(n0 + row) * K + k0 + lchk * 8;
            uint32_t d = swz(sbase, row, lchk * 8);
            cp16(d,      Ah + aoff, av);
            cp16(d + GT, Al + aoff, av);
            uint32_t db = swz(sbase + 2 * GT, row, lchk * 8);
            cp16(db,      Bh + boff, jv);
            cp16(db + GT, Bl + boff, jv);
        }
    };

    float acc[2][4][4];
#pragma unroll
    for (int a = 0; a < 2; a++)
#pragma unroll
        for (int b = 0; b < 4; b++)
#pragma unroll
            for (int c = 0; c < 4; c++) acc[a][b][c] = 0.f;

    load_stage(0, 0);
    CP_COMMIT();
    load_stage(1, 1);
    CP_COMMIT();

    const int mw = (wid & 3) * 32;
    const int nw = (wid >> 2) * 32;
    const int rsel = lane & 15;
    const int khalf = (lane >> 4) * 8;

    for (int i = 0; i < nk; i++) {
        CP_WAIT1();
        __syncthreads();
        load_stage((i + 2) % 3, i + 2);
        CP_COMMIT();

        const uint32_t sA = sb + (uint32_t)(i % 3) * GSTAGE;
        const uint32_t sB = sA + 2 * GT;
#pragma unroll
        for (int ks = 0; ks < 4; ks++) {
            const int ke = ks * 16 + khalf;
            uint32_t ah[2][4], al[2][4], bh[2][4], bl[2][4];
#pragma unroll
            for (int mi = 0; mi < 2; mi++) {
                uint32_t ad = swz(sA, mw + mi * 16 + rsel, ke);
                ldsm4(ah[mi], ad);
                ldsm4(al[mi], ad + GT);
            }
#pragma unroll
            for (int bi = 0; bi < 2; bi++) {
                uint32_t bd = swz(sB, nw + bi * 16 + rsel, ke);
                ldsm4(bh[bi], bd);
                ldsm4(bl[bi], bd + GT);
            }
#pragma unroll
            for (int mi = 0; mi < 2; mi++)
#pragma unroll
                for (int nj = 0; nj < 4; nj++) {
                    uint32_t b2[2] = { bh[nj >> 1][nj & 1], bh[nj >> 1][(nj & 1) + 2] };
                    mma_bf16(acc[mi][nj], ah[mi], b2);
                }
#pragma unroll
            for (int mi = 0; mi < 2; mi++)
#pragma unroll
                for (int nj = 0; nj < 4; nj++) {
                    uint32_t b2[2] = { bl[nj >> 1][nj & 1], bl[nj >> 1][(nj & 1) + 2] };
                    mma_bf16(acc[mi][nj], ah[mi], b2);
                }
#pragma unroll
            for (int mi = 0; mi < 2; mi++)
#pragma unroll
                for (int nj = 0; nj < 4; nj++) {
                    uint32_t b2[2] = { bh[nj >> 1][nj & 1], bh[nj >> 1][(nj & 1) + 2] };
                    mma_bf16(acc[mi][nj], al[mi], b2);
                }
        }
    }

#pragma unroll
    for (int mi = 0; mi < 2; mi++) {
#pragma unroll
        for (int nj = 0; nj < 4; nj++) {
            int col = n0 + nw + nj * 8 + (lane & 3) * 2;
            float bx = bias ? bias[col] : 0.f;
            float by = bias ? bias[col + 1] : 0.f;
            int r0 = m0 + mw + mi * 16 + (lane >> 2);
            int r1 = r0 + 8;
            if (r0 < M)
                ((__half2*)Ch)[((size_t)r0 * N + col) >> 1] =
                    __halves2half2(__float2half(acc[mi][nj][0] + bx),
                                   __float2half(acc[mi][nj][1] + by));
            if (r1 < M)
                ((__half2*)Ch)[((size_t)r1 * N + col) >> 1] =
                    __halves2half2(__float2half(acc[mi][nj][2] + bx),
                                   __float2half(acc[mi][nj][3] + by));
        }
    }
}

// ---------------- fp16 single-pass GEMM (layers 1/2/3), fp16 out -------------
#define HT 16384
#define HSTAGE (2 * HT)
#define HSMEM  (3 * HSTAGE)           // 98304

__global__ void __launch_bounds__(256, 2) gemm16_kernel(
    const __half* __restrict__ A, const __half* __restrict__ B,
    __half* __restrict__ C, int M, int N, int K)
{
    extern __shared__ char smem[];
    const uint32_t sb = smem_to_u32(smem);
    const int tid = threadIdx.x;
    const int lane = tid & 31, wid = tid >> 5;
    const int m0 = blockIdx.y * 128, n0 = blockIdx.x * 128;
    const int nk = K >> 6;

    auto load_stage = [&](int s, int j) {
        const uint32_t sbase = sb + (uint32_t)s * HSTAGE;
        const int lchk = tid & 7;
        const int lrow = tid >> 3;        // 0..31
        const bool jv = (j < nk);
        const long long k0 = jv ? ((long long)j << 6) : 0;
#pragma unroll
        for (int it = 0; it < 4; it++) {
            int row = lrow + it * 32;
            bool av = jv && (m0 + row < M);
            int gr = (m0 + row < M) ? (m0 + row) : 0;
            cp16(swz(sbase, row, lchk * 8),
                 A + (size_t)gr * K + k0 + lchk * 8, av);
            cp16(swz(sbase + HT, row, lchk * 8),
                 B + (size_t)(n0 + row) * K + k0 + lchk * 8, jv);
        }
    };

    float acc[2][8][4];
#pragma unroll
    for (int a = 0; a < 2; a++)
#pragma unroll
        for (int b = 0; b < 8; b++)
#pragma unroll
            for (int c = 0; c < 4; c++) acc[a][b][c] = 0.f;

    load_stage(0, 0);
    CP_COMMIT();
    load_stage(1, 1);
    CP_COMMIT();

    const int mw = (wid & 3) * 32;      // 4 warp rows
    const int nw = (wid >> 2) * 64;     // 2 warp cols
    const int rsel = lane & 15;
    const int khalf = (lane >> 4) * 8;

    for (int i = 0; i < nk; i++) {
        CP_WAIT1();
        __syncthreads();
        load_stage((i + 2) % 3, i + 2);
        CP_COMMIT();

        const uint32_t sA = sb + (uint32_t)(i % 3) * HSTAGE;
        const uint32_t sB = sA + HT;
#pragma unroll
        for (int ks = 0; ks < 4; ks++) {
            const int ke = ks * 16 + khalf;
            uint32_t a[2][4], b[4][4];
#pragma unroll
            for (int mi = 0; mi < 2; mi++)
                ldsm4(a[mi], swz(sA, mw + mi * 16 + rsel, ke));
#pragma unroll
            for (int bi = 0; bi < 4; bi++)
                ldsm4(b[bi], swz(sB, nw + bi * 16 + rsel, ke));
#pragma unroll
            for (int mi = 0; mi < 2; mi++)
#pragma unroll
                for (int nj = 0; nj < 8; nj++) {
                    uint32_t b2[2] = { b[nj >> 1][nj & 1], b[nj >> 1][(nj & 1) + 2] };
                    mma_fp16(acc[mi][nj], a[mi], b2);
                }
        }
    }

#pragma unroll
    for (int mi = 0; mi < 2; mi++) {
#pragma unroll
        for (int nj = 0; nj < 8; nj++) {
            int col = n0 + nw + nj * 8 + (lane & 3) * 2;
            int r0 = m0 + mw + mi * 16 + (lane >> 2);
            int r1 = r0 + 8;
            if (r0 < M)
                ((__half2*)C)[((size_t)r0 * N + col) >> 1] =
                    __halves2half2(__float2half(acc[mi][nj][0]),
                                   __float2half(acc[mi][nj][1]));
            if (r1 < M)
                ((__half2*)C)[((size_t)r1 * N + col) >> 1] =
                    __halves2half2(__float2half(acc[mi][nj][2]),
                                   __float2half(acc[mi][nj][3]));
        }
    }
}

// ---------------- per-node attention coefficients es/ed (fp16 hmat) ----------
__global__ void attn_kernel(const __half* __restrict__ hmat,
                            const float* __restrict__ a_src,
                            const float* __restrict__ a_dst, int H) {
    const int C = 512;
    int i = blockIdx.x;
    int hh = threadIdx.x >> 5;
    int lane = threadIdx.x & 31;
    const __half2* hr = (const __half2*)(hmat + (size_t)i * H * C + hh * C);
    float s = 0.f, d = 0.f;
    for (int c2 = lane; c2 < C / 2; c2 += 32) {
        float2 f = __half22float2(hr[c2]);
        s += f.x * a_src[hh * C + 2 * c2]     + f.y * a_src[hh * C + 2 * c2 + 1];
        d += f.x * a_dst[hh * C + 2 * c2]     + f.y * a_dst[hh * C + 2 * c2 + 1];
    }
#pragma unroll
    for (int o = 16; o > 0; o >>= 1) {
        s += __shfl_xor_sync(0xffffffffu, s, o);
        d += __shfl_xor_sync(0xffffffffu, d, o);
    }
    if (lane == 0) { g_es[i * H + hh] = s; g_ed[i * H + hh] = d; }
}

// ---------------- segment softmax over dst-CSR rows --------------------------
__global__ void softmax_kernel(int H) {
    int idx = blockIdx.x * blockDim.x + threadIdx.x;
    if (idx >= NN * H) return;
    int i = idx % NN;
    int hh = idx / NN;
    float edi = g_ed[i * H + hh];
    int p0 = g_rowptr[i], p1 = g_rowptr[i + 1];
    float m = -1e30f;
    for (int p = p0; p < p1; p++) {
        float e = g_es[g_csrsrc[p] * H + hh] + edi;
        e = (e > 0.f) ? e : 0.2f * e;
        m = fmaxf(m, e);
    }
    float den = 0.f;
    for (int p = p0; p < p1; p++) {
        float e = g_es[g_csrsrc[p] * H + hh] + edi;
        e = (e > 0.f) ? e : 0.2f * e;
        float a = expf(e - m);
        g_alpha[p * 4 + hh] = a;
        den += a;
    }
    float inv = 1.f / den;
    for (int p = p0; p < p1; p++) g_alpha[p * 4 + hh] *= inv;
}

// ---------------- weighted aggregation over fp16 hmat ------------------------
// MODE 0 (HC=2048): 8 cols/thread (uint4/edge), ELU+bias, fp16 out.
// MODE 1 (HC=1024): 4 cols/thread (uint2/edge), mean 2 heads + bias, fp32 out.
template <int HC, int MODE>
__global__ void aggregate_kernel(const __half* __restrict__ hmat,
                                 const float* __restrict__ bias,
                                 float* __restrict__ outF,
                                 uint16_t* __restrict__ outH) {
    int i = blockIdx.x;
    int t = threadIdx.x;
    int p0 = g_rowptr[i], p1 = g_rowptr[i + 1];

    if (MODE == 0) {
        const int base = t * 8;             // cols [8t, 8t+8)
        const int hd = t >> 6;              // 8t / 512
        float acc[8];
#pragma unroll
        for (int k = 0; k < 8; k++) acc[k] = 0.f;

        for (int p = p0; p < p1; p++) {
            int s = g_csrsrc[p];
            float av = g_alpha[p * 4 + hd];
            uint4 rv = *(const uint4*)(hmat + (size_t)s * HC + base);
            float2 f0 = __half22float2(*(__half2*)&rv.x);
            float2 f1 = __half22float2(*(__half2*)&rv.y);
            float2 f2 = __half22float2(*(__half2*)&rv.z);
            float2 f3 = __half22float2(*(__half2*)&rv.w);
            acc[0] += av * f0.x; acc[1] += av * f0.y;
            acc[2] += av * f1.x; acc[3] += av * f1.y;
            acc[4] += av * f2.x; acc[5] += av * f2.y;
            acc[6] += av * f3.x; acc[7] += av * f3.y;
        }

        float4 b0 = *(const float4*)(bias + base);
        float4 b1 = *(const float4*)(bias + base + 4);
        float v[8] = { acc[0] + b0.x, acc[1] + b0.y, acc[2] + b0.z, acc[3] + b0.w,
                       acc[4] + b1.x, acc[5] + b1.y, acc[6] + b1.z, acc[7] + b1.w };
        __half h[8];
#pragma unroll
        for (int k = 0; k < 8; k++) {
            float e = (v[k] > 0.f) ? v[k] : (expf(v[k]) - 1.f);
            h[k] = __float2half(e);
        }
        uint4 ov;
        ov.x = *(uint32_t*)&h[0]; ov.y = *(uint32_t*)&h[2];
        ov.z = *(uint32_t*)&h[4]; ov.w = *(uint32_t*)&h[6];
        *(uint4*)((__half*)outH + (size_t)i * HC + base) = ov;
    } else {
        const int base = t * 4;             // cols [4t, 4t+4)
        const int hd = t >> 7;              // 4t / 512
        float4 acc = make_float4(0.f, 0.f, 0.f, 0.f);

        for (int p = p0; p < p1; p++) {
            int s = g_csrsrc[p];
            float av = g_alpha[p * 4 + hd];
            uint2 rv = *(const uint2*)(hmat + (size_t)s * HC + base);
            float2 f0 = __half22float2(*(__half2*)&rv.x);
            float2 f1 = __half22float2(*(__half2*)&rv.y);
            acc.x += av * f0.x; acc.y += av * f0.y;
            acc.z += av * f1.x; acc.w += av * f1.y;
        }

        __shared__ float4 sh[256];
        sh[t] = acc;
        __syncthreads();
        if (t < 128) {
            float4 v0 = sh[t], v1 = sh[t + 128];
            float4 b = ((const float4*)bias)[t];
            float4 r;
            r.x = 0.5f * (v0.x + v1.x) + b.x;
            r.y = 0.5f * (v0.y + v1.y) + b.y;
            r.z = 0.5f * (v0.z + v1.z) + b.z;
            r.w = 0.5f * (v0.w + v1.w) + b.w;
            ((float4*)outF)[(size_t)i * 128 + t] = r;
        }
    }
}

// ---------------- host launch helpers ----------------------------------------
static void run_proj(const uint16_t* ah, const uint16_t* al,
                     const uint16_t* wh, const uint16_t* wl,
                     const float* bias, uint16_t* ch, int M, int N, int K) {
    dim3 grid(N / 128, (M + 127) / 128);
    gemm_mma_kernel<<<grid, 512, GSMEM>>>(
        (const __nv_bfloat16*)ah, (const __nv_bfloat16*)al,
        (const __nv_bfloat16*)wh, (const __nv_bfloat16*)wl,
        bias, (__half*)ch, M, N, K);
}
static void run_gemm16(const uint16_t* a, const uint16_t* w,
                       __half* C, int M, int N, int K) {
    dim3 grid(N / 128, (M + 127) / 128);
    gemm16_kernel<<<grid, 256, HSMEM>>>((const __half*)a, (const __half*)w, C, M, N, K);
}

extern "C" void kernel_launch(void* const* d_in, const int* in_sizes, int n_in,
                              void* d_out, int out_size) {
    const float* x      = (const float*)d_in[0];
    const void*  ei     = d_in[1];
    const float* proj_w = (const float*)d_in[2];
    const float* proj_b = (const float*)d_in[3];
    const float* w1  = (const float*)d_in[4];
    const float* as1 = (const float*)d_in[5];
    const float* ad1 = (const float*)d_in[6];
    const float* b1  = (const float*)d_in[7];
    const float* w2  = (const float*)d_in[8];
    const float* as2 = (const float*)d_in[9];
    const float* ad2 = (const float*)d_in[10];
    const float* b2  = (const float*)d_in[11];
    const float* w3  = (const float*)d_in[12];
    const float* as3 = (const float*)d_in[13];
    const float* ad3 = (const float*)d_in[14];
    const float* b3  = (const float*)d_in[15];
    float* out = (float*)d_out;

    __half* hmat;
    uint16_t *P0h, *P0l, *P1h, *Wh, *Wl;
    cudaGetSymbolAddress((void**)&hmat, g_hmat);
    cudaGetSymbolAddress((void**)&P0h, g_P0h);
    cudaGetSymbolAddress((void**)&P0l, g_P0l);
    cudaGetSymbolAddress((void**)&P1h, g_P1h);
    cudaGetSymbolAddress((void**)&Wh, g_Wh);
    cudaGetSymbolAddress((void**)&Wl, g_Wl);

    static bool attr_set = false;
    if (!attr_set) {
        cudaFuncSetAttribute((const void*)gemm_mma_kernel,
                             cudaFuncAttributeMaxDynamicSharedMemorySize, GSMEM);
        cudaFuncSetAttribute((const void*)gemm16_kernel,
                             cudaFuncAttributeMaxDynamicSharedMemorySize, HSMEM);
        attr_set = true;
    }

    // our idx 0-2: input split, proj_w transpose, detect/init
    cvt_split_kernel<<<(NN * 256 / 4 + 255) / 256, 256>>>(x, P0h, P0l, NN * 256 / 4);
    cvt_transpose_bf16_kernel<<<dim3(512 / 32, 256 / 32), dim3(32, 8)>>>(proj_w, Wh, Wl, 256, 512);
    detect_init_kernel<<<(NN + 255) / 256, 256>>>((const unsigned int*)ei);
    // our idx 3: proj GEMM (bf16 3-pass, fp16 out)
    run_proj(P0h, P0l, Wh, Wl, proj_b, P1h, NN, 512, 256);
    // CSR build
    count_kernel<<<(EE + 255) / 256, 256>>>(ei);
    scan_fillself_kernel<<<1, 1024>>>();
    filledges_kernel<<<(EE + 255) / 256, 256>>>(ei);

    // ---- GAT layer 1 (H=4, C=512, concat, ELU): fp16 1-pass, N=2048, K=512 ----
    cvt_transpose_f16_kernel<<<dim3(2048 / 32, 512 / 32), dim3(32, 8)>>>(w1, Wh, 512, 2048);
    run_gemm16(P1h, Wh, hmat, NN, 2048, 512);
    attn_kernel<<<NN, 128>>>(hmat, as1, ad1, 4);
    softmax_kernel<<<(NN * 4 + 255) / 256, 256>>>(4);
    aggregate_kernel<2048, 0><<<NN, 256>>>(hmat, b1, nullptr, P0h);

    // ---- GAT layer 2 (H=4, C=512, concat, ELU): fp16 1-pass, N=2048, K=2048 ----
    cvt_transpose_f16_kernel<<<dim3(2048 / 32, 2048 / 32), dim3(32, 8)>>>(w2, Wh, 2048, 2048);
    run_gemm16(P0h, Wh, hmat, NN, 2048, 2048);
    attn_kernel<<<NN, 128>>>(hmat, as2, ad2, 4);
    softmax_kernel<<<(NN * 4 + 255) / 256, 256>>>(4);
    aggregate_kernel<2048, 0><<<NN, 256>>>(hmat, b2, nullptr, P1h);

    // ---- GAT layer 3 (H=2, C=512, mean): fp16 1-pass, N=1024, K=2048 ----
    cvt_transpose_f16_kernel<<<dim3(1024 / 32, 2048 / 32), dim3(32, 8)>>>(w3, Wh, 2048, 1024);
    run_gemm16(P1h, Wh, hmat, NN, 1024, 2048);
    attn_kernel<<<NN, 64>>>(hmat, as3, ad3, 2);
    softmax_kernel<<<(NN * 2 + 255) / 256, 256>>>(2);
    aggregate_kernel<1024, 1><<<NN, 256>>>(hmat, b3, out, nullptr);
}

// round 11
// speedup vs baseline: 3.0943x; 1.0986x over previous
#include <cuda_runtime.h>
#include <cuda_fp16.h>
#include <math.h>
#include <stdint.h>

#define NN 10000
#define EE 160000
#define ET 170000   // edges + self loops

// ---------------- scratch (device globals; no allocations allowed) ----------
__device__ __align__(16) __half g_hmat[NN * 2048];   // fp16 GEMM output
__device__ float g_es  [NN * 4];
__device__ float g_ed  [NN * 4];
__device__ int   g_counts [NN];
__device__ int   g_rowptr [NN + 1];
__device__ int   g_fillpos[NN];
__device__ int   g_csrsrc [ET];
__device__ int   g_is64;
// fp16 activation ping-pong + weight buffer
__device__ __align__(16) __half g_P0[NN * 2048];
__device__ __align__(16) __half g_P1[NN * 2048];
__device__ __align__(16) __half g_Wt[2048 * 2048];

// ============================ PTX helpers (baseline, sm_80+) =================
__device__ __forceinline__ uint32_t smem_to_u32(const void* p) {
    uint32_t a;
    asm("{ .reg .u64 t; cvta.to.shared.u64 t, %1; cvt.u32.u64 %0, t; }" : "=r"(a) : "l"(p));
    return a;
}

__device__ __forceinline__ void cp16(uint32_t dst, const void* src, bool v) {
    int sz = v ? 16 : 0;
    asm volatile("cp.async.cg.shared.global [%0], [%1], 16, %2;\n"
                 :: "r"(dst), "l"(src), "r"(sz) : "memory");
}
#define CP_COMMIT() asm volatile("cp.async.commit_group;" ::: "memory")
#define CP_WAIT1()  asm volatile("cp.async.wait_group 1;" ::: "memory")

__device__ __forceinline__ void ldsm4(uint32_t* r, uint32_t addr) {
    asm volatile("ldmatrix.sync.aligned.m8n8.x4.shared.b16 {%0,%1,%2,%3}, [%4];"
                 : "=r"(r[0]), "=r"(r[1]), "=r"(r[2]), "=r"(r[3]) : "r"(addr));
}

__device__ __forceinline__ void mma_fp16(float* c, const uint32_t* a, const uint32_t* b) {
    asm volatile(
        "mma.sync.aligned.m16n8k16.row.col.f32.f16.f16.f32 "
        "{%0,%1,%2,%3}, {%4,%5,%6,%7}, {%8,%9}, {%0,%1,%2,%3};"
        : "+f"(c[0]), "+f"(c[1]), "+f"(c[2]), "+f"(c[3])
        : "r"(a[0]), "r"(a[1]), "r"(a[2]), "r"(a[3]), "r"(b[0]), "r"(b[1]));
}

__device__ __forceinline__ int edge_at(const void* ei, long long idx) {
    if (g_is64) return (int)((const long long*)ei)[idx];
    return ((const int*)ei)[idx];
}

// ---------------- CSR build ---------------------------------------------------
__global__ void detect_init_kernel(const unsigned int* p) {
    int i = blockIdx.x * blockDim.x + threadIdx.x;
    if (i < NN) g_counts[i] = 1;           // self loop pre-counted
    if (i == 0) {
        int is64 = 1;
        for (int j = 0; j < 128; j++)
            if (p[2 * j + 1] != 0u) { is64 = 0; break; }
        g_is64 = is64;
    }
}
__global__ void count_kernel(const void* ei) {
    int e = blockIdx.x * blockDim.x + threadIdx.x;
    if (e < EE) atomicAdd(&g_counts[edge_at(ei, (long long)EE + e)], 1);
}
__global__ void scan_fillself_kernel() {
    __shared__ int sh[1024];
    int t = threadIdx.x;
    const int chunk = (NN + 1023) >> 10;
    int base = t * chunk;
    int s = 0;
    for (int j = 0; j < chunk; j++) { int idx = base + j; if (idx < NN) s += g_counts[idx]; }
    sh[t] = s;
    __syncthreads();
    for (int off = 1; off < 1024; off <<= 1) {
        int v = (t >= off) ? sh[t - off] : 0;
        __syncthreads();
        sh[t] += v;
        __syncthreads();
    }
    int prefix = (t > 0) ? sh[t - 1] : 0;
    for (int j = 0; j < chunk; j++) {
        int idx = base + j;
        if (idx < NN) { g_rowptr[idx] = prefix; prefix += g_counts[idx]; }
    }
    if (t == 0) g_rowptr[NN] = sh[1023];
    __syncthreads();
    for (int idx = t; idx < NN; idx += 1024) {
        int r = g_rowptr[idx];
        g_csrsrc[r] = idx;
        g_fillpos[idx] = r + 1;
    }
}
__global__ void filledges_kernel(const void* ei) {
    int e = blockIdx.x * blockDim.x + threadIdx.x;
    if (e < EE) {
        int s = edge_at(ei, e);
        int d = edge_at(ei, (long long)EE + e);
        g_csrsrc[atomicAdd(&g_fillpos[d], 1)] = s;
    }
}

// ---------------- fp32 -> fp16 convert (input x) ------------------------------
__global__ void cvt_f16_kernel(const float* __restrict__ x,
                               __half* __restrict__ o, int n4) {
    int i = blockIdx.x * blockDim.x + threadIdx.x;
    if (i >= n4) return;
    float4 v = ((const float4*)x)[i];
    ((__half2*)o)[2 * i]     = __halves2half2(__float2half(v.x), __float2half(v.y));
    ((__half2*)o)[2 * i + 1] = __halves2half2(__float2half(v.z), __float2half(v.w));
}

// ---------------- weight transpose: W[K,N] -> Wt[N,K] fp16 -------------------
__global__ void cvt_transpose_f16_kernel(const float* __restrict__ W,
                                         __half* __restrict__ th, int K, int N) {
    __shared__ float tile[32][33];
    int n0 = blockIdx.x * 32, k0 = blockIdx.y * 32;
    int tx = threadIdx.x, ty = threadIdx.y;   // 32 x 8
    for (int r = ty; r < 32; r += 8)
        tile[r][tx] = W[(size_t)(k0 + r) * N + n0 + tx];
    __syncthreads();
    for (int r = ty; r < 32; r += 8)
        th[(size_t)(n0 + r) * K + k0 + tx] = __float2half(tile[tx][r]);
}

__device__ __forceinline__ uint32_t swz(uint32_t base, int row, int kelem) {
    return base + row * 128 + ((((kelem >> 3) ^ row) & 7) << 4);
}

// ---------------- fp16 single-pass GEMM (all 4 GEMMs), fp16 out (+bias) ------
// CTA 128x128, BK=64, 3-stage, 256 threads / 8 warps (4x2), warp tile 32x64.
// smem 96KB -> 2 CTAs/SM.
#define HT 16384
#define HSTAGE (2 * HT)
#define HSMEM  (3 * HSTAGE)           // 98304

__global__ void __launch_bounds__(256, 2) gemm16_kernel(
    const __half* __restrict__ A, const __half* __restrict__ B,
    const float* __restrict__ bias, __half* __restrict__ C,
    int M, int N, int K)
{
    extern __shared__ char smem[];
    const uint32_t sb = smem_to_u32(smem);
    const int tid = threadIdx.x;
    const int lane = tid & 31, wid = tid >> 5;
    const int m0 = blockIdx.y * 128, n0 = blockIdx.x * 128;
    const int nk = K >> 6;

    auto load_stage = [&](int s, int j) {
        const uint32_t sbase = sb + (uint32_t)s * HSTAGE;
        const int lchk = tid & 7;
        const int lrow = tid >> 3;        // 0..31
        const bool jv = (j < nk);
        const long long k0 = jv ? ((long long)j << 6) : 0;
#pragma unroll
        for (int it = 0; it < 4; it++) {
            int row = lrow + it * 32;
            bool av = jv && (m0 + row < M);
            int gr = (m0 + row < M) ? (m0 + row) : 0;
            cp16(swz(sbase, row, lchk * 8),
                 A + (size_t)gr * K + k0 + lchk * 8, av);
            cp16(swz(sbase + HT, row, lchk * 8),
                 B + (size_t)(n0 + row) * K + k0 + lchk * 8, jv);
        }
    };

    float acc[2][8][4];
#pragma unroll
    for (int a = 0; a < 2; a++)
#pragma unroll
        for (int b = 0; b < 8; b++)
#pragma unroll
            for (int c = 0; c < 4; c++) acc[a][b][c] = 0.f;

    load_stage(0, 0);
    CP_COMMIT();
    load_stage(1, 1);
    CP_COMMIT();

    const int mw = (wid & 3) * 32;      // 4 warp rows
    const int nw = (wid >> 2) * 64;     // 2 warp cols
    const int rsel = lane & 15;
    const int khalf = (lane >> 4) * 8;

    for (int i = 0; i < nk; i++) {
        CP_WAIT1();
        __syncthreads();
        load_stage((i + 2) % 3, i + 2);
        CP_COMMIT();

        const uint32_t sA = sb + (uint32_t)(i % 3) * HSTAGE;
        const uint32_t sB = sA + HT;
#pragma unroll
        for (int ks = 0; ks < 4; ks++) {
            const int ke = ks * 16 + khalf;
            uint32_t a[2][4], b[4][4];
#pragma unroll
            for (int mi = 0; mi < 2; mi++)
                ldsm4(a[mi], swz(sA, mw + mi * 16 + rsel, ke));
#pragma unroll
            for (int bi = 0; bi < 4; bi++)
                ldsm4(b[bi], swz(sB, nw + bi * 16 + rsel, ke));
#pragma unroll
            for (int mi = 0; mi < 2; mi++)
#pragma unroll
                for (int nj = 0; nj < 8; nj++) {
                    uint32_t b2[2] = { b[nj >> 1][nj & 1], b[nj >> 1][(nj & 1) + 2] };
                    mma_fp16(acc[mi][nj], a[mi], b2);
                }
        }
    }

#pragma unroll
    for (int mi = 0; mi < 2; mi++) {
#pragma unroll
        for (int nj = 0; nj < 8; nj++) {
            int col = n0 + nw + nj * 8 + (lane & 3) * 2;
            float bx = 0.f, by = 0.f;
            if (bias) { bx = bias[col]; by = bias[col + 1]; }
            int r0 = m0 + mw + mi * 16 + (lane >> 2);
            int r1 = r0 + 8;
            if (r0 < M)
                ((__half2*)C)[((size_t)r0 * N + col) >> 1] =
                    __halves2half2(__float2half(acc[mi][nj][0] + bx),
                                   __float2half(acc[mi][nj][1] + by));
            if (r1 < M)
                ((__half2*)C)[((size_t)r1 * N + col) >> 1] =
                    __halves2half2(__float2half(acc[mi][nj][2] + bx),
                                   __float2half(acc[mi][nj][3] + by));
        }
    }
}

// ---------------- per-node attention coefficients es/ed (fp16 hmat) ----------
__global__ void attn_kernel(const __half* __restrict__ hmat,
                            const float* __restrict__ a_src,
                            const float* __restrict__ a_dst, int H) {
    const int C = 512;
    int i = blockIdx.x;
    int hh = threadIdx.x >> 5;
    int lane = threadIdx.x & 31;
    const __half2* hr = (const __half2*)(hmat + (size_t)i * H * C + hh * C);
    float s = 0.f, d = 0.f;
    for (int c2 = lane; c2 < C / 2; c2 += 32) {
        float2 f = __half22float2(hr[c2]);
        s += f.x * a_src[hh * C + 2 * c2] + f.y * a_src[hh * C + 2 * c2 + 1];
        d += f.x * a_dst[hh * C + 2 * c2] + f.y * a_dst[hh * C + 2 * c2 + 1];
    }
#pragma unroll
    for (int o = 16; o > 0; o >>= 1) {
        s += __shfl_xor_sync(0xffffffffu, s, o);
        d += __shfl_xor_sync(0xffffffffu, d, o);
    }
    if (lane == 0) { g_es[i * H + hh] = s; g_ed[i * H + hh] = d; }
}

// ---------------- fused softmax + weighted aggregation -----------------------
// Per-block (dst node): warp-per-head softmax stats from es/ed + CSR,
// alphas materialized in smem chunks, then gather fp16 hmat rows.
// MODE 0 (HC=2048, H=4): 8 cols/thread, ELU+bias, fp16 out.
// MODE 1 (HC=1024, H=2): 4 cols/thread, mean 2 heads + bias, fp32 out.
#define CAP 128

template <int HC, int H, int MODE>
__global__ void aggregate_kernel(const __half* __restrict__ hmat,
                                 const float* __restrict__ bias,
                                 float* __restrict__ outF,
                                 __half* __restrict__ outH) {
    __shared__ float sm_alpha[CAP * H];
    __shared__ int   sm_srcs[CAP];
    __shared__ float sm_m[H], sm_inv[H];
    __shared__ float4 sm_red[MODE == 1 ? 256 : 1];

    int i = blockIdx.x;
    int t = threadIdx.x;
    int lane = t & 31, wid = t >> 5;
    int p0 = g_rowptr[i], p1 = g_rowptr[i + 1];

    // --- softmax stats: warp per head ---
    if (wid < H) {
        float edi = g_ed[i * H + wid];
        float m = -1e30f;
        for (int p = p0 + lane; p < p1; p += 32) {
            float e = g_es[g_csrsrc[p] * H + wid] + edi;
            e = (e > 0.f) ? e : 0.2f * e;
            m = fmaxf(m, e);
        }
#pragma unroll
        for (int o = 16; o > 0; o >>= 1) m = fmaxf(m, __shfl_xor_sync(0xffffffffu, m, o));
        float den = 0.f;
        for (int p = p0 + lane; p < p1; p += 32) {
            float e = g_es[g_csrsrc[p] * H + wid] + edi;
            e = (e > 0.f) ? e : 0.2f * e;
            den += expf(e - m);
        }
#pragma unroll
        for (int o = 16; o > 0; o >>= 1) den += __shfl_xor_sync(0xffffffffu, den, o);
        if (lane == 0) { sm_m[wid] = m; sm_inv[wid] = 1.f / den; }
    }
    __syncthreads();

    if (MODE == 0) {
        const int base = t * 8;
        const int hd = t >> 6;          // head of col block (8t/512)
        float acc[8];
#pragma unroll
        for (int k = 0; k < 8; k++) acc[k] = 0.f;

        for (int c0 = p0; c0 < p1; c0 += CAP) {
            int n = min(p1 - c0, CAP);
            for (int idx = t; idx < n * H; idx += 256) {
                int j = idx >> 2, h = idx & (H - 1);
                int s = g_csrsrc[c0 + j];
                if (h == 0) sm_srcs[j] = s;
                float e = g_es[s * H + h] + g_ed[i * H + h];
                e = (e > 0.f) ? e : 0.2f * e;
                sm_alpha[j * H + h] = expf(e - sm_m[h]) * sm_inv[h];
            }
            __syncthreads();
            for (int j = 0; j < n; j++) {
                int s = sm_srcs[j];
                float av = sm_alpha[j * H + hd];
                uint4 rv = *(const uint4*)(hmat + (size_t)s * HC + base);
                float2 f0 = __half22float2(*(__half2*)&rv.x);
                float2 f1 = __half22float2(*(__half2*)&rv.y);
                float2 f2 = __half22float2(*(__half2*)&rv.z);
                float2 f3 = __half22float2(*(__half2*)&rv.w);
                acc[0] += av * f0.x; acc[1] += av * f0.y;
                acc[2] += av * f1.x; acc[3] += av * f1.y;
                acc[4] += av * f2.x; acc[5] += av * f2.y;
                acc[6] += av * f3.x; acc[7] += av * f3.y;
            }
            __syncthreads();
        }

        float4 b0 = *(const float4*)(bias + base);
        float4 b1 = *(const float4*)(bias + base + 4);
        float v[8] = { acc[0] + b0.x, acc[1] + b0.y, acc[2] + b0.z, acc[3] + b0.w,
                       acc[4] + b1.x, acc[5] + b1.y, acc[6] + b1.z, acc[7] + b1.w };
        __half h[8];
#pragma unroll
        for (int k = 0; k < 8; k++) {
            float e = (v[k] > 0.f) ? v[k] : (expf(v[k]) - 1.f);
            h[k] = __float2half(e);
        }
        uint4 ov;
        ov.x = *(uint32_t*)&h[0]; ov.y = *(uint32_t*)&h[2];
        ov.z = *(uint32_t*)&h[4]; ov.w = *(uint32_t*)&h[6];
        *(uint4*)(outH + (size_t)i * HC + base) = ov;
    } else {
        const int base = t * 4;
        const int hd = t >> 7;          // head of col block (4t/512)
        float4 acc = make_float4(0.f, 0.f, 0.f, 0.f);

        for (int c0 = p0; c0 < p1; c0 += CAP) {
            int n = min(p1 - c0, CAP);
            for (int idx = t; idx < n * H; idx += 256) {
                int j = idx >> 1, h = idx & (H - 1);
                int s = g_csrsrc[c0 + j];
                if (h == 0) sm_srcs[j] = s;
                float e = g_es[s * H + h] + g_ed[i * H + h];
                e = (e > 0.f) ? e : 0.2f * e;
                sm_alpha[j * H + h] = expf(e - sm_m[h]) * sm_inv[h];
            }
            __syncthreads();
            for (int j = 0; j < n; j++) {
                int s = sm_srcs[j];
                float av = sm_alpha[j * H + hd];
                uint2 rv = *(const uint2*)(hmat + (size_t)s * HC + base);
                float2 f0 = __half22float2(*(__half2*)&rv.x);
                float2 f1 = __half22float2(*(__half2*)&rv.y);
                acc.x += av * f0.x; acc.y += av * f0.y;
                acc.z += av * f1.x; acc.w += av * f1.y;
            }
            __syncthreads();
        }

        sm_red[t] = acc;
        __syncthreads();
        if (t < 128) {
            float4 v0 = sm_red[t], v1 = sm_red[t + 128];
            float4 b = ((const float4*)bias)[t];
            float4 r;
            r.x = 0.5f * (v0.x + v1.x) + b.x;
            r.y = 0.5f * (v0.y + v1.y) + b.y;
            r.z = 0.5f * (v0.z + v1.z) + b.z;
            r.w = 0.5f * (v0.w + v1.w) + b.w;
            ((float4*)outF)[(size_t)i * 128 + t] = r;
        }
    }
}

// ---------------- host launch helpers ----------------------------------------
static void run_gemm16(const __half* a, const __half* w, const float* bias,
                       __half* C, int M, int N, int K) {
    dim3 grid(N / 128, (M + 127) / 128);
    gemm16_kernel<<<grid, 256, HSMEM>>>(a, w, bias, C, M, N, K);
}

extern "C" void kernel_launch(void* const* d_in, const int* in_sizes, int n_in,
                              void* d_out, int out_size) {
    const float* x      = (const float*)d_in[0];
    const void*  ei     = d_in[1];
    const float* proj_w = (const float*)d_in[2];
    const float* proj_b = (const float*)d_in[3];
    const float* w1  = (const float*)d_in[4];
    const float* as1 = (const float*)d_in[5];
    const float* ad1 = (const float*)d_in[6];
    const float* b1  = (const float*)d_in[7];
    const float* w2  = (const float*)d_in[8];
    const float* as2 = (const float*)d_in[9];
    const float* ad2 = (const float*)d_in[10];
    const float* b2  = (const float*)d_in[11];
    const float* w3  = (const float*)d_in[12];
    const float* as3 = (const float*)d_in[13];
    const float* ad3 = (const float*)d_in[14];
    const float* b3  = (const float*)d_in[15];
    float* out = (float*)d_out;

    __half *hmat, *P0, *P1, *Wt;
    cudaGetSymbolAddress((void**)&hmat, g_hmat);
    cudaGetSymbolAddress((void**)&P0, g_P0);
    cudaGetSymbolAddress((void**)&P1, g_P1);
    cudaGetSymbolAddress((void**)&Wt, g_Wt);

    static bool attr_set = false;
    if (!attr_set) {
        cudaFuncSetAttribute((const void*)gemm16_kernel,
                             cudaFuncAttributeMaxDynamicSharedMemorySize, HSMEM);
        attr_set = true;
    }

    // idx 0-2: x convert, proj_w transpose, detect/init
    cvt_f16_kernel<<<(NN * 256 / 4 + 255) / 256, 256>>>(x, P0, NN * 256 / 4);
    cvt_transpose_f16_kernel<<<dim3(512 / 32, 256 / 32), dim3(32, 8)>>>(proj_w, Wt, 256, 512);
    detect_init_kernel<<<(NN + 255) / 256, 256>>>((const unsigned int*)ei);
    // idx 3: proj GEMM (fp16 1-pass, +bias)  <-- profiled launch
    run_gemm16(P0, Wt, proj_b, P1, NN, 512, 256);
    // CSR build
    count_kernel<<<(EE + 255) / 256, 256>>>(ei);
    scan_fillself_kernel<<<1, 1024>>>();
    filledges_kernel<<<(EE + 255) / 256, 256>>>(ei);

    // ---- GAT layer 1 (H=4, C=512, concat, ELU): N=2048, K=512 ----
    cvt_transpose_f16_kernel<<<dim3(2048 / 32, 512 / 32), dim3(32, 8)>>>(w1, Wt, 512, 2048);
    run_gemm16(P1, Wt, nullptr, hmat, NN, 2048, 512);
    attn_kernel<<<NN, 128>>>(hmat, as1, ad1, 4);
    aggregate_kernel<2048, 4, 0><<<NN, 256>>>(hmat, b1, nullptr, P0);

    // ---- GAT layer 2 (H=4, C=512, concat, ELU): N=2048, K=2048 ----
    cvt_transpose_f16_kernel<<<dim3(2048 / 32, 2048 / 32), dim3(32, 8)>>>(w2, Wt, 2048, 2048);
    run_gemm16(P0, Wt, nullptr, hmat, NN, 2048, 2048);
    attn_kernel<<<NN, 128>>>(hmat, as2, ad2, 4);
    aggregate_kernel<2048, 4, 0><<<NN, 256>>>(hmat, b2, nullptr, P1);

    // ---- GAT layer 3 (H=2, C=512, mean): N=1024, K=2048 ----
    cvt_transpose_f16_kernel<<<dim3(1024 / 32, 2048 / 32), dim3(32, 8)>>>(w3, Wt, 2048, 1024);
    run_gemm16(P1, Wt, nullptr, hmat, NN, 1024, 2048);
    attn_kernel<<<NN, 64>>>(hmat, as3, ad3, 2);
    aggregate_kernel<1024, 2, 1><<<NN, 256>>>(hmat, b3, out, nullptr);
}

// round 12
// speedup vs baseline: 3.2694x; 1.0566x over previous
#include <cuda_runtime.h>
#include <cuda_fp16.h>
#include <math.h>
#include <stdint.h>

#define NN 10000
#define EE 160000
#define ET 170000   // edges + self loops

// ---------------- scratch (device globals; no allocations allowed) ----------
__device__ __align__(16) __half g_hmat[NN * 2048];   // fp16 GEMM output
__device__ float g_es  [NN * 4];
__device__ float g_ed  [NN * 4];
__device__ int   g_counts [NN];
__device__ int   g_rowptr [NN + 1];
__device__ int   g_fillpos[NN];
__device__ int   g_csrsrc [ET];
__device__ int   g_is64;
// fp16 activation ping-pong + per-layer weight buffers
__device__ __align__(16) __half g_P0[NN * 2048];
__device__ __align__(16) __half g_P1[NN * 2048];
__device__ __align__(16) __half g_WtP[512 * 256];
__device__ __align__(16) __half g_Wt1[2048 * 512];
__device__ __align__(16) __half g_Wt2[2048 * 2048];
__device__ __align__(16) __half g_Wt3[1024 * 2048];

// ============================ PTX helpers (baseline, sm_80+) =================
__device__ __forceinline__ uint32_t smem_to_u32(const void* p) {
    uint32_t a;
    asm("{ .reg .u64 t; cvta.to.shared.u64 t, %1; cvt.u32.u64 %0, t; }" : "=r"(a) : "l"(p));
    return a;
}

__device__ __forceinline__ void cp16(uint32_t dst, const void* src, bool v) {
    int sz = v ? 16 : 0;
    asm volatile("cp.async.cg.shared.global [%0], [%1], 16, %2;\n"
                 :: "r"(dst), "l"(src), "r"(sz) : "memory");
}
#define CP_COMMIT() asm volatile("cp.async.commit_group;" ::: "memory")
#define CP_WAIT1()  asm volatile("cp.async.wait_group 1;" ::: "memory")

__device__ __forceinline__ void ldsm4(uint32_t* r, uint32_t addr) {
    asm volatile("ldmatrix.sync.aligned.m8n8.x4.shared.b16 {%0,%1,%2,%3}, [%4];"
                 : "=r"(r[0]), "=r"(r[1]), "=r"(r[2]), "=r"(r[3]) : "r"(addr));
}

__device__ __forceinline__ void mma_fp16(float* c, const uint32_t* a, const uint32_t* b) {
    asm volatile(
        "mma.sync.aligned.m16n8k16.row.col.f32.f16.f16.f32 "
        "{%0,%1,%2,%3}, {%4,%5,%6,%7}, {%8,%9}, {%0,%1,%2,%3};"
        : "+f"(c[0]), "+f"(c[1]), "+f"(c[2]), "+f"(c[3])
        : "r"(a[0]), "r"(a[1]), "r"(a[2]), "r"(a[3]), "r"(b[0]), "r"(b[1]));
}

__device__ __forceinline__ int edge_at(const void* ei, long long idx) {
    if (g_is64) return (int)((const long long*)ei)[idx];
    return ((const int*)ei)[idx];
}

// ---------------- CSR build ---------------------------------------------------
__global__ void detect_init_kernel(const unsigned int* p) {
    int i = blockIdx.x * blockDim.x + threadIdx.x;
    if (i < NN) g_counts[i] = 1;           // self loop pre-counted
    if (i == 0) {
        int is64 = 1;
        for (int j = 0; j < 128; j++)
            if (p[2 * j + 1] != 0u) { is64 = 0; break; }
        g_is64 = is64;
    }
}
__global__ void count_kernel(const void* ei) {
    int e = blockIdx.x * blockDim.x + threadIdx.x;
    if (e < EE) atomicAdd(&g_counts[edge_at(ei, (long long)EE + e)], 1);
}
__global__ void scan_fillself_kernel() {
    __shared__ int sh[1024];
    int t = threadIdx.x;
    const int chunk = (NN + 1023) >> 10;
    int base = t * chunk;
    int s = 0;
    for (int j = 0; j < chunk; j++) { int idx = base + j; if (idx < NN) s += g_counts[idx]; }
    sh[t] = s;
    __syncthreads();
    for (int off = 1; off < 1024; off <<= 1) {
        int v = (t >= off) ? sh[t - off] : 0;
        __syncthreads();
        sh[t] += v;
        __syncthreads();
    }
    int prefix = (t > 0) ? sh[t - 1] : 0;
    for (int j = 0; j < chunk; j++) {
        int idx = base + j;
        if (idx < NN) { g_rowptr[idx] = prefix; prefix += g_counts[idx]; }
    }
    if (t == 0) g_rowptr[NN] = sh[1023];
    __syncthreads();
    for (int idx = t; idx < NN; idx += 1024) {
        int r = g_rowptr[idx];
        g_csrsrc[r] = idx;
        g_fillpos[idx] = r + 1;
    }
}
__global__ void filledges_kernel(const void* ei) {
    int e = blockIdx.x * blockDim.x + threadIdx.x;
    if (e < EE) {
        int s = edge_at(ei, e);
        int d = edge_at(ei, (long long)EE + e);
        g_csrsrc[atomicAdd(&g_fillpos[d], 1)] = s;
    }
}

// ---------------- fp32 -> fp16 convert (input x) ------------------------------
__global__ void cvt_f16_kernel(const float* __restrict__ x,
                               __half* __restrict__ o, int n4) {
    int i = blockIdx.x * blockDim.x + threadIdx.x;
    if (i >= n4) return;
    float4 v = ((const float4*)x)[i];
    ((__half2*)o)[2 * i]     = __halves2half2(__float2half(v.x), __float2half(v.y));
    ((__half2*)o)[2 * i + 1] = __halves2half2(__float2half(v.z), __float2half(v.w));
}

// ---------------- weight transpose: W[K,N] -> Wt[N,K] fp16 -------------------
__global__ void cvt_transpose_f16_kernel(const float* __restrict__ W,
                                         __half* __restrict__ th, int K, int N) {
    __shared__ float tile[32][33];
    int n0 = blockIdx.x * 32, k0 = blockIdx.y * 32;
    int tx = threadIdx.x, ty = threadIdx.y;   // 32 x 8
    for (int r = ty; r < 32; r += 8)
        tile[r][tx] = W[(size_t)(k0 + r) * N + n0 + tx];
    __syncthreads();
    for (int r = ty; r < 32; r += 8)
        th[(size_t)(n0 + r) * K + k0 + tx] = __float2half(tile[tx][r]);
}

__device__ __forceinline__ uint32_t swz(uint32_t base, int row, int kelem) {
    return base + row * 128 + ((((kelem >> 3) ^ row) & 7) << 4);
}

// ---------------- fp16 single-pass GEMM (all 4 GEMMs), fp16 out (+bias) ------
// CTA 128x128, BK=64, 3-stage, 256 threads / 8 warps (4x2), warp tile 32x64.
#define HT 16384
#define HSTAGE (2 * HT)
#define HSMEM  (3 * HSTAGE)           // 98304

__global__ void __launch_bounds__(256, 2) gemm16_kernel(
    const __half* __restrict__ A, const __half* __restrict__ B,
    const float* __restrict__ bias, __half* __restrict__ C,
    int M, int N, int K)
{
    extern __shared__ char smem[];
    const uint32_t sb = smem_to_u32(smem);
    const int tid = threadIdx.x;
    const int lane = tid & 31, wid = tid >> 5;
    const int m0 = blockIdx.y * 128, n0 = blockIdx.x * 128;
    const int nk = K >> 6;

    auto load_stage = [&](int s, int j) {
        const uint32_t sbase = sb + (uint32_t)s * HSTAGE;
        const int lchk = tid & 7;
        const int lrow = tid >> 3;        // 0..31
        const bool jv = (j < nk);
        const long long k0 = jv ? ((long long)j << 6) : 0;
#pragma unroll
        for (int it = 0; it < 4; it++) {
            int row = lrow + it * 32;
            bool av = jv && (m0 + row < M);
            int gr = (m0 + row < M) ? (m0 + row) : 0;
            cp16(swz(sbase, row, lchk * 8),
                 A + (size_t)gr * K + k0 + lchk * 8, av);
            cp16(swz(sbase + HT, row, lchk * 8),
                 B + (size_t)(n0 + row) * K + k0 + lchk * 8, jv);
        }
    };

    float acc[2][8][4];
#pragma unroll
    for (int a = 0; a < 2; a++)
#pragma unroll
        for (int b = 0; b < 8; b++)
#pragma unroll
            for (int c = 0; c < 4; c++) acc[a][b][c] = 0.f;

    load_stage(0, 0);
    CP_COMMIT();
    load_stage(1, 1);
    CP_COMMIT();

    const int mw = (wid & 3) * 32;      // 4 warp rows
    const int nw = (wid >> 2) * 64;     // 2 warp cols
    const int rsel = lane & 15;
    const int khalf = (lane >> 4) * 8;

    for (int i = 0; i < nk; i++) {
        CP_WAIT1();
        __syncthreads();
        load_stage((i + 2) % 3, i + 2);
        CP_COMMIT();

        const uint32_t sA = sb + (uint32_t)(i % 3) * HSTAGE;
        const uint32_t sB = sA + HT;
#pragma unroll
        for (int ks = 0; ks < 4; ks++) {
            const int ke = ks * 16 + khalf;
            uint32_t a[2][4], b[4][4];
#pragma unroll
            for (int mi = 0; mi < 2; mi++)
                ldsm4(a[mi], swz(sA, mw + mi * 16 + rsel, ke));
#pragma unroll
            for (int bi = 0; bi < 4; bi++)
                ldsm4(b[bi], swz(sB, nw + bi * 16 + rsel, ke));
#pragma unroll
            for (int mi = 0; mi < 2; mi++)
#pragma unroll
                for (int nj = 0; nj < 8; nj++) {
                    uint32_t b2[2] = { b[nj >> 1][nj & 1], b[nj >> 1][(nj & 1) + 2] };
                    mma_fp16(acc[mi][nj], a[mi], b2);
                }
        }
    }

#pragma unroll
    for (int mi = 0; mi < 2; mi++) {
#pragma unroll
        for (int nj = 0; nj < 8; nj++) {
            int col = n0 + nw + nj * 8 + (lane & 3) * 2;
            float bx = 0.f, by = 0.f;
            if (bias) { bx = bias[col]; by = bias[col + 1]; }
            int r0 = m0 + mw + mi * 16 + (lane >> 2);
            int r1 = r0 + 8;
            if (r0 < M)
                ((__half2*)C)[((size_t)r0 * N + col) >> 1] =
                    __halves2half2(__float2half(acc[mi][nj][0] + bx),
                                   __float2half(acc[mi][nj][1] + by));
            if (r1 < M)
                ((__half2*)C)[((size_t)r1 * N + col) >> 1] =
                    __halves2half2(__float2half(acc[mi][nj][2] + bx),
                                   __float2half(acc[mi][nj][3] + by));
        }
    }
}

// ---------------- per-node attention coefficients es/ed (fp16 hmat) ----------
__global__ void attn_kernel(const __half* __restrict__ hmat,
                            const float* __restrict__ a_src,
                            const float* __restrict__ a_dst, int H) {
    const int C = 512;
    int i = blockIdx.x;
    int hh = threadIdx.x >> 5;
    int lane = threadIdx.x & 31;
    const __half2* hr = (const __half2*)(hmat + (size_t)i * H * C + hh * C);
    float s = 0.f, d = 0.f;
    for (int c2 = lane; c2 < C / 2; c2 += 32) {
        float2 f = __half22float2(hr[c2]);
        s += f.x * a_src[hh * C + 2 * c2] + f.y * a_src[hh * C + 2 * c2 + 1];
        d += f.x * a_dst[hh * C + 2 * c2] + f.y * a_dst[hh * C + 2 * c2 + 1];
    }
#pragma unroll
    for (int o = 16; o > 0; o >>= 1) {
        s += __shfl_xor_sync(0xffffffffu, s, o);
        d += __shfl_xor_sync(0xffffffffu, d, o);
    }
    if (lane == 0) { g_es[i * H + hh] = s; g_ed[i * H + hh] = d; }
}

// ---------------- fused softmax + weighted aggregation -----------------------
#define CAP 128

template <int HC, int H, int MODE>
__global__ void aggregate_kernel(const __half* __restrict__ hmat,
                                 const float* __restrict__ bias,
                                 float* __restrict__ outF,
                                 __half* __restrict__ outH) {
    __shared__ float sm_alpha[CAP * H];
    __shared__ int   sm_srcs[CAP];
    __shared__ float sm_m[H], sm_inv[H];
    __shared__ float4 sm_red[MODE == 1 ? 256 : 1];

    int i = blockIdx.x;
    int t = threadIdx.x;
    int lane = t & 31, wid = t >> 5;
    int p0 = g_rowptr[i], p1 = g_rowptr[i + 1];

    // --- softmax stats: warp per head ---
    if (wid < H) {
        float edi = g_ed[i * H + wid];
        float m = -1e30f;
        for (int p = p0 + lane; p < p1; p += 32) {
            float e = g_es[g_csrsrc[p] * H + wid] + edi;
            e = (e > 0.f) ? e : 0.2f * e;
            m = fmaxf(m, e);
        }
#pragma unroll
        for (int o = 16; o > 0; o >>= 1) m = fmaxf(m, __shfl_xor_sync(0xffffffffu, m, o));
        float den = 0.f;
        for (int p = p0 + lane; p < p1; p += 32) {
            float e = g_es[g_csrsrc[p] * H + wid] + edi;
            e = (e > 0.f) ? e : 0.2f * e;
            den += expf(e - m);
        }
#pragma unroll
        for (int o = 16; o > 0; o >>= 1) den += __shfl_xor_sync(0xffffffffu, den, o);
        if (lane == 0) { sm_m[wid] = m; sm_inv[wid] = 1.f / den; }
    }
    __syncthreads();

    if (MODE == 0) {
        const int base = t * 8;
        const int hd = t >> 6;          // head of col block (8t/512)
        float acc[8];
#pragma unroll
        for (int k = 0; k < 8; k++) acc[k] = 0.f;

        for (int c0 = p0; c0 < p1; c0 += CAP) {
            int n = min(p1 - c0, CAP);
            for (int idx = t; idx < n * H; idx += 256) {
                int j = idx >> 2, h = idx & (H - 1);
                int s = g_csrsrc[c0 + j];
                if (h == 0) sm_srcs[j] = s;
                float e = g_es[s * H + h] + g_ed[i * H + h];
                e = (e > 0.f) ? e : 0.2f * e;
                sm_alpha[j * H + h] = expf(e - sm_m[h]) * sm_inv[h];
            }
            __syncthreads();
            for (int j = 0; j < n; j++) {
                int s = sm_srcs[j];
                float av = sm_alpha[j * H + hd];
                uint4 rv = *(const uint4*)(hmat + (size_t)s * HC + base);
                float2 f0 = __half22float2(*(__half2*)&rv.x);
                float2 f1 = __half22float2(*(__half2*)&rv.y);
                float2 f2 = __half22float2(*(__half2*)&rv.z);
                float2 f3 = __half22float2(*(__half2*)&rv.w);
                acc[0] += av * f0.x; acc[1] += av * f0.y;
                acc[2] += av * f1.x; acc[3] += av * f1.y;
                acc[4] += av * f2.x; acc[5] += av * f2.y;
                acc[6] += av * f3.x; acc[7] += av * f3.y;
            }
            __syncthreads();
        }

        float4 b0 = *(const float4*)(bias + base);
        float4 b1 = *(const float4*)(bias + base + 4);
        float v[8] = { acc[0] + b0.x, acc[1] + b0.y, acc[2] + b0.z, acc[3] + b0.w,
                       acc[4] + b1.x, acc[5] + b1.y, acc[6] + b1.z, acc[7] + b1.w };
        __half h[8];
#pragma unroll
        for (int k = 0; k < 8; k++) {
            float e = (v[k] > 0.f) ? v[k] : (expf(v[k]) - 1.f);
            h[k] = __float2half(e);
        }
        uint4 ov;
        ov.x = *(uint32_t*)&h[0]; ov.y = *(uint32_t*)&h[2];
        ov.z = *(uint32_t*)&h[4]; ov.w = *(uint32_t*)&h[6];
        *(uint4*)(outH + (size_t)i * HC + base) = ov;
    } else {
        const int base = t * 4;
        const int hd = t >> 7;          // head of col block (4t/512)
        float4 acc = make_float4(0.f, 0.f, 0.f, 0.f);

        for (int c0 = p0; c0 < p1; c0 += CAP) {
            int n = min(p1 - c0, CAP);
            for (int idx = t; idx < n * H; idx += 256) {
                int j = idx >> 1, h = idx & (H - 1);
                int s = g_csrsrc[c0 + j];
                if (h == 0) sm_srcs[j] = s;
                float e = g_es[s * H + h] + g_ed[i * H + h];
                e = (e > 0.f) ? e : 0.2f * e;
                sm_alpha[j * H + h] = expf(e - sm_m[h]) * sm_inv[h];
            }
            __syncthreads();
            for (int j = 0; j < n; j++) {
                int s = sm_srcs[j];
                float av = sm_alpha[j * H + hd];
                uint2 rv = *(const uint2*)(hmat + (size_t)s * HC + base);
                float2 f0 = __half22float2(*(__half2*)&rv.x);
                float2 f1 = __half22float2(*(__half2*)&rv.y);
                acc.x += av * f0.x; acc.y += av * f0.y;
                acc.z += av * f1.x; acc.w += av * f1.y;
            }
            __syncthreads();
        }

        sm_red[t] = acc;
        __syncthreads();
        if (t < 128) {
            float4 v0 = sm_red[t], v1 = sm_red[t + 128];
            float4 b = ((const float4*)bias)[t];
            float4 r;
            r.x = 0.5f * (v0.x + v1.x) + b.x;
            r.y = 0.5f * (v0.y + v1.y) + b.y;
            r.z = 0.5f * (v0.z + v1.z) + b.z;
            r.w = 0.5f * (v0.w + v1.w) + b.w;
            ((float4*)outF)[(size_t)i * 128 + t] = r;
        }
    }
}

// ---------------- host launch helpers ----------------------------------------
static void run_gemm16(const __half* a, const __half* w, const float* bias,
                       __half* C, int M, int N, int K, cudaStream_t st) {
    dim3 grid(N / 128, (M + 127) / 128);
    gemm16_kernel<<<grid, 256, HSMEM, st>>>(a, w, bias, C, M, N, K);
}

extern "C" void kernel_launch(void* const* d_in, const int* in_sizes, int n_in,
                              void* d_out, int out_size) {
    const float* x      = (const float*)d_in[0];
    const void*  ei     = d_in[1];
    const float* proj_w = (const float*)d_in[2];
    const float* proj_b = (const float*)d_in[3];
    const float* w1  = (const float*)d_in[4];
    const float* as1 = (const float*)d_in[5];
    const float* ad1 = (const float*)d_in[6];
    const float* b1  = (const float*)d_in[7];
    const float* w2  = (const float*)d_in[8];
    const float* as2 = (const float*)d_in[9];
    const float* ad2 = (const float*)d_in[10];
    const float* b2  = (const float*)d_in[11];
    const float* w3  = (const float*)d_in[12];
    const float* as3 = (const float*)d_in[13];
    const float* ad3 = (const float*)d_in[14];
    const float* b3  = (const float*)d_in[15];
    float* out = (float*)d_out;

    __half *hmat, *P0, *P1, *WtP, *Wt1, *Wt2, *Wt3;
    cudaGetSymbolAddress((void**)&hmat, g_hmat);
    cudaGetSymbolAddress((void**)&P0, g_P0);
    cudaGetSymbolAddress((void**)&P1, g_P1);
    cudaGetSymbolAddress((void**)&WtP, g_WtP);
    cudaGetSymbolAddress((void**)&Wt1, g_Wt1);
    cudaGetSymbolAddress((void**)&Wt2, g_Wt2);
    cudaGetSymbolAddress((void**)&Wt3, g_Wt3);

    static cudaStream_t sW = nullptr, sC = nullptr;
    static cudaEvent_t evRoot, evWp, evW1, evW2, evW3, evCSR;
    if (!sW) {
        cudaFuncSetAttribute((const void*)gemm16_kernel,
                             cudaFuncAttributeMaxDynamicSharedMemorySize, HSMEM);
        cudaStreamCreateWithFlags(&sW, cudaStreamNonBlocking);
        cudaStreamCreateWithFlags(&sC, cudaStreamNonBlocking);
        cudaEventCreateWithFlags(&evRoot, cudaEventDisableTiming);
        cudaEventCreateWithFlags(&evWp,  cudaEventDisableTiming);
        cudaEventCreateWithFlags(&evW1,  cudaEventDisableTiming);
        cudaEventCreateWithFlags(&evW2,  cudaEventDisableTiming);
        cudaEventCreateWithFlags(&evW3,  cudaEventDisableTiming);
        cudaEventCreateWithFlags(&evCSR, cudaEventDisableTiming);
    }

    // ---- fork side streams off the capture-origin stream ----
    cudaEventRecord(evRoot, 0);
    cudaStreamWaitEvent(sW, evRoot, 0);
    cudaStreamWaitEvent(sC, evRoot, 0);

    // stream W: all weight transposes into separate buffers
    cvt_transpose_f16_kernel<<<dim3(512 / 32, 256 / 32), dim3(32, 8), 0, sW>>>(proj_w, WtP, 256, 512);
    cudaEventRecord(evWp, sW);
    cvt_transpose_f16_kernel<<<dim3(2048 / 32, 512 / 32), dim3(32, 8), 0, sW>>>(w1, Wt1, 512, 2048);
    cudaEventRecord(evW1, sW);
    cvt_transpose_f16_kernel<<<dim3(2048 / 32, 2048 / 32), dim3(32, 8), 0, sW>>>(w2, Wt2, 2048, 2048);
    cudaEventRecord(evW2, sW);
    cvt_transpose_f16_kernel<<<dim3(1024 / 32, 2048 / 32), dim3(32, 8), 0, sW>>>(w3, Wt3, 2048, 1024);
    cudaEventRecord(evW3, sW);

    // stream C: CSR build
    detect_init_kernel<<<(NN + 255) / 256, 256, 0, sC>>>((const unsigned int*)ei);
    count_kernel<<<(EE + 255) / 256, 256, 0, sC>>>(ei);
    scan_fillself_kernel<<<1, 1024, 0, sC>>>();
    filledges_kernel<<<(EE + 255) / 256, 256, 0, sC>>>(ei);
    cudaEventRecord(evCSR, sC);

    // ---- main stream ----
    cvt_f16_kernel<<<(NN * 256 / 4 + 255) / 256, 256>>>(x, P0, NN * 256 / 4);
    cudaStreamWaitEvent(0, evWp, 0);
    run_gemm16(P0, WtP, proj_b, P1, NN, 512, 256, 0);

    // ---- GAT layer 1 (H=4, C=512, concat, ELU): N=2048, K=512 ----
    cudaStreamWaitEvent(0, evW1, 0);
    run_gemm16(P1, Wt1, nullptr, hmat, NN, 2048, 512, 0);
    attn_kernel<<<NN, 128>>>(hmat, as1, ad1, 4);
    cudaStreamWaitEvent(0, evCSR, 0);
    aggregate_kernel<2048, 4, 0><<<NN, 256>>>(hmat, b1, nullptr, P0);

    // ---- GAT layer 2 (H=4, C=512, concat, ELU): N=2048, K=2048 ----
    cudaStreamWaitEvent(0, evW2, 0);
    run_gemm16(P0, Wt2, nullptr, hmat, NN, 2048, 2048, 0);
    attn_kernel<<<NN, 128>>>(hmat, as2, ad2, 4);
    aggregate_kernel<2048, 4, 0><<<NN, 256>>>(hmat, b2, nullptr, P1);

    // ---- GAT layer 3 (H=2, C=512, mean): N=1024, K=2048 ----
    cudaStreamWaitEvent(0, evW3, 0);
    run_gemm16(P1, Wt3, nullptr, hmat, NN, 1024, 2048, 0);
    attn_kernel<<<NN, 64>>>(hmat, as3, ad3, 2);
    aggregate_kernel<1024, 2, 1><<<NN, 256>>>(hmat, b3, out, nullptr);
}

// round 13
// speedup vs baseline: 3.3905x; 1.0370x over previous
#include <cuda_runtime.h>
#include <cuda_fp16.h>
#include <math.h>
#include <stdint.h>

#define NN 10000
#define EE 160000
#define ET 170000   // edges + self loops
#define MH1 5120    // node/row half split
#define MH2 (NN - MH1)

// ---------------- scratch (device globals; no allocations allowed) ----------
__device__ __align__(16) __half g_hmatA[NN * 2048];  // layers 1 and 3
__device__ __align__(16) __half g_hmatB[NN * 2048];  // layer 2
__device__ float g_esA[NN * 4], g_edA[NN * 4];       // layers 1 and 3
__device__ float g_esB[NN * 4], g_edB[NN * 4];       // layer 2
__device__ int   g_counts [NN];
__device__ int   g_rowptr [NN + 1];
__device__ int   g_fillpos[NN];
__device__ int   g_csrsrc [ET];
__device__ int   g_is64;
// fp16 activation ping-pong + per-layer weight buffers
__device__ __align__(16) __half g_P0[NN * 2048];
__device__ __align__(16) __half g_P1[NN * 2048];
__device__ __align__(16) __half g_WtP[512 * 256];
__device__ __align__(16) __half g_Wt1[2048 * 512];
__device__ __align__(16) __half g_Wt2[2048 * 2048];
__device__ __align__(16) __half g_Wt3[1024 * 2048];

// ============================ PTX helpers (baseline, sm_80+) =================
__device__ __forceinline__ uint32_t smem_to_u32(const void* p) {
    uint32_t a;
    asm("{ .reg .u64 t; cvta.to.shared.u64 t, %1; cvt.u32.u64 %0, t; }" : "=r"(a) : "l"(p));
    return a;
}

__device__ __forceinline__ void cp16(uint32_t dst, const void* src, bool v) {
    int sz = v ? 16 : 0;
    asm volatile("cp.async.cg.shared.global [%0], [%1], 16, %2;\n"
                 :: "r"(dst), "l"(src), "r"(sz) : "memory");
}
#define CP_COMMIT() asm volatile("cp.async.commit_group;" ::: "memory")
#define CP_WAIT1()  asm volatile("cp.async.wait_group 1;" ::: "memory")

__device__ __forceinline__ void ldsm4(uint32_t* r, uint32_t addr) {
    asm volatile("ldmatrix.sync.aligned.m8n8.x4.shared.b16 {%0,%1,%2,%3}, [%4];"
                 : "=r"(r[0]), "=r"(r[1]), "=r"(r[2]), "=r"(r[3]) : "r"(addr));
}

__device__ __forceinline__ void mma_fp16(float* c, const uint32_t* a, const uint32_t* b) {
    asm volatile(
        "mma.sync.aligned.m16n8k16.row.col.f32.f16.f16.f32 "
        "{%0,%1,%2,%3}, {%4,%5,%6,%7}, {%8,%9}, {%0,%1,%2,%3};"
        : "+f"(c[0]), "+f"(c[1]), "+f"(c[2]), "+f"(c[3])
        : "r"(a[0]), "r"(a[1]), "r"(a[2]), "r"(a[3]), "r"(b[0]), "r"(b[1]));
}

__device__ __forceinline__ int edge_at(const void* ei, long long idx) {
    if (g_is64) return (int)((const long long*)ei)[idx];
    return ((const int*)ei)[idx];
}

// ---------------- CSR build ---------------------------------------------------
__global__ void detect_init_kernel(const unsigned int* p) {
    int i = blockIdx.x * blockDim.x + threadIdx.x;
    if (i < NN) g_counts[i] = 1;           // self loop pre-counted
    if (i == 0) {
        int is64 = 1;
        for (int j = 0; j < 128; j++)
            if (p[2 * j + 1] != 0u) { is64 = 0; break; }
        g_is64 = is64;
    }
}
__global__ void count_kernel(const void* ei) {
    int e = blockIdx.x * blockDim.x + threadIdx.x;
    if (e < EE) atomicAdd(&g_counts[edge_at(ei, (long long)EE + e)], 1);
}
__global__ void scan_fillself_kernel() {
    __shared__ int sh[1024];
    int t = threadIdx.x;
    const int chunk = (NN + 1023) >> 10;
    int base = t * chunk;
    int s = 0;
    for (int j = 0; j < chunk; j++) { int idx = base + j; if (idx < NN) s += g_counts[idx]; }
    sh[t] = s;
    __syncthreads();
    for (int off = 1; off < 1024; off <<= 1) {
        int v = (t >= off) ? sh[t - off] : 0;
        __syncthreads();
        sh[t] += v;
        __syncthreads();
    }
    int prefix = (t > 0) ? sh[t - 1] : 0;
    for (int j = 0; j < chunk; j++) {
        int idx = base + j;
        if (idx < NN) { g_rowptr[idx] = prefix; prefix += g_counts[idx]; }
    }
    if (t == 0) g_rowptr[NN] = sh[1023];
    __syncthreads();
    for (int idx = t; idx < NN; idx += 1024) {
        int r = g_rowptr[idx];
        g_csrsrc[r] = idx;
        g_fillpos[idx] = r + 1;
    }
}
__global__ void filledges_kernel(const void* ei) {
    int e = blockIdx.x * blockDim.x + threadIdx.x;
    if (e < EE) {
        int s = edge_at(ei, e);
        int d = edge_at(ei, (long long)EE + e);
        g_csrsrc[atomicAdd(&g_fillpos[d], 1)] = s;
    }
}

// ---------------- fp32 -> fp16 convert (input x) ------------------------------
__global__ void cvt_f16_kernel(const float* __restrict__ x,
                               __half* __restrict__ o, int n4) {
    int i = blockIdx.x * blockDim.x + threadIdx.x;
    if (i >= n4) return;
    float4 v = ((const float4*)x)[i];
    ((__half2*)o)[2 * i]     = __halves2half2(__float2half(v.x), __float2half(v.y));
    ((__half2*)o)[2 * i + 1] = __halves2half2(__float2half(v.z), __float2half(v.w));
}

// ---------------- weight transpose: W[K,N] -> Wt[N,K] fp16 -------------------
__global__ void cvt_transpose_f16_kernel(const float* __restrict__ W,
                                         __half* __restrict__ th, int K, int N) {
    __shared__ float tile[32][33];
    int n0 = blockIdx.x * 32, k0 = blockIdx.y * 32;
    int tx = threadIdx.x, ty = threadIdx.y;   // 32 x 8
    for (int r = ty; r < 32; r += 8)
        tile[r][tx] = W[(size_t)(k0 + r) * N + n0 + tx];
    __syncthreads();
    for (int r = ty; r < 32; r += 8)
        th[(size_t)(n0 + r) * K + k0 + tx] = __float2half(tile[tx][r]);
}

__device__ __forceinline__ uint32_t swz(uint32_t base, int row, int kelem) {
    return base + row * 128 + ((((kelem >> 3) ^ row) & 7) << 4);
}

// ---------------- fp16 single-pass GEMM, fp16 out (+bias), row-offset --------
// CTA 128x128, BK=64, 3-stage, 256 threads / 8 warps (4x2), warp tile 32x64.
#define HT 16384
#define HSTAGE (2 * HT)
#define HSMEM  (3 * HSTAGE)           // 98304

__global__ void __launch_bounds__(256, 2) gemm16_kernel(
    const __half* __restrict__ A, const __half* __restrict__ B,
    const float* __restrict__ bias, __half* __restrict__ C,
    int M, int N, int K, int moff)
{
    extern __shared__ char smem[];
    const uint32_t sb = smem_to_u32(smem);
    const int tid = threadIdx.x;
    const int lane = tid & 31, wid = tid >> 5;
    const int m0 = blockIdx.y * 128 + moff, n0 = blockIdx.x * 128;
    const int nk = K >> 6;

    auto load_stage = [&](int s, int j) {
        const uint32_t sbase = sb + (uint32_t)s * HSTAGE;
        const int lchk = tid & 7;
        const int lrow = tid >> 3;        // 0..31
        const bool jv = (j < nk);
        const long long k0 = jv ? ((long long)j << 6) : 0;
#pragma unroll
        for (int it = 0; it < 4; it++) {
            int row = lrow + it * 32;
            bool av = jv && (m0 + row < M);
            int gr = (m0 + row < M) ? (m0 + row) : 0;
            cp16(swz(sbase, row, lchk * 8),
                 A + (size_t)gr * K + k0 + lchk * 8, av);
            cp16(swz(sbase + HT, row, lchk * 8),
                 B + (size_t)(n0 + row) * K + k0 + lchk * 8, jv);
        }
    };

    float acc[2][8][4];
#pragma unroll
    for (int a = 0; a < 2; a++)
#pragma unroll
        for (int b = 0; b < 8; b++)
#pragma unroll
            for (int c = 0; c < 4; c++) acc[a][b][c] = 0.f;

    load_stage(0, 0);
    CP_COMMIT();
    load_stage(1, 1);
    CP_COMMIT();

    const int mw = (wid & 3) * 32;      // 4 warp rows
    const int nw = (wid >> 2) * 64;     // 2 warp cols
    const int rsel = lane & 15;
    const int khalf = (lane >> 4) * 8;

    for (int i = 0; i < nk; i++) {
        CP_WAIT1();
        __syncthreads();
        load_stage((i + 2) % 3, i + 2);
        CP_COMMIT();

        const uint32_t sA = sb + (uint32_t)(i % 3) * HSTAGE;
        const uint32_t sB = sA + HT;
#pragma unroll
        for (int ks = 0; ks < 4; ks++) {
            const int ke = ks * 16 + khalf;
            uint32_t a[2][4], b[4][4];
#pragma unroll
            for (int mi = 0; mi < 2; mi++)
                ldsm4(a[mi], swz(sA, mw + mi * 16 + rsel, ke));
#pragma unroll
            for (int bi = 0; bi < 4; bi++)
                ldsm4(b[bi], swz(sB, nw + bi * 16 + rsel, ke));
#pragma unroll
            for (int mi = 0; mi < 2; mi++)
#pragma unroll
                for (int nj = 0; nj < 8; nj++) {
                    uint32_t b2[2] = { b[nj >> 1][nj & 1], b[nj >> 1][(nj & 1) + 2] };
                    mma_fp16(acc[mi][nj], a[mi], b2);
                }
        }
    }

#pragma unroll
    for (int mi = 0; mi < 2; mi++) {
#pragma unroll
        for (int nj = 0; nj < 8; nj++) {
            int col = n0 + nw + nj * 8 + (lane & 3) * 2;
            float bx = 0.f, by = 0.f;
            if (bias) { bx = bias[col]; by = bias[col + 1]; }
            int r0 = m0 + mw + mi * 16 + (lane >> 2);
            int r1 = r0 + 8;
            if (r0 < M)
                ((__half2*)C)[((size_t)r0 * N + col) >> 1] =
                    __halves2half2(__float2half(acc[mi][nj][0] + bx),
                                   __float2half(acc[mi][nj][1] + by));
            if (r1 < M)
                ((__half2*)C)[((size_t)r1 * N + col) >> 1] =
                    __halves2half2(__float2half(acc[mi][nj][2] + bx),
                                   __float2half(acc[mi][nj][3] + by));
        }
    }
}

// ---------------- per-node attention coefficients es/ed (fp16 hmat) ----------
__global__ void attn_kernel(const __half* __restrict__ hmat,
                            const float* __restrict__ a_src,
                            const float* __restrict__ a_dst,
                            float* __restrict__ es, float* __restrict__ ed,
                            int H, int off) {
    const int C = 512;
    int i = blockIdx.x + off;
    int hh = threadIdx.x >> 5;
    int lane = threadIdx.x & 31;
    const __half2* hr = (const __half2*)(hmat + (size_t)i * H * C + hh * C);
    float s = 0.f, d = 0.f;
    for (int c2 = lane; c2 < C / 2; c2 += 32) {
        float2 f = __half22float2(hr[c2]);
        s += f.x * a_src[hh * C + 2 * c2] + f.y * a_src[hh * C + 2 * c2 + 1];
        d += f.x * a_dst[hh * C + 2 * c2] + f.y * a_dst[hh * C + 2 * c2 + 1];
    }
#pragma unroll
    for (int o = 16; o > 0; o >>= 1) {
        s += __shfl_xor_sync(0xffffffffu, s, o);
        d += __shfl_xor_sync(0xffffffffu, d, o);
    }
    if (lane == 0) { es[i * H + hh] = s; ed[i * H + hh] = d; }
}

// ---------------- fused softmax + weighted aggregation -----------------------
#define CAP 128

template <int HC, int H, int MODE>
__global__ void aggregate_kernel(const __half* __restrict__ hmat,
                                 const float* __restrict__ es,
                                 const float* __restrict__ ed,
                                 const float* __restrict__ bias,
                                 float* __restrict__ outF,
                                 __half* __restrict__ outH, int off) {
    __shared__ float sm_alpha[CAP * H];
    __shared__ int   sm_srcs[CAP];
    __shared__ float sm_m[H], sm_inv[H];
    __shared__ float4 sm_red[MODE == 1 ? 256 : 1];

    int i = blockIdx.x + off;
    int t = threadIdx.x;
    int lane = t & 31, wid = t >> 5;
    int p0 = g_rowptr[i], p1 = g_rowptr[i + 1];

    // --- softmax stats: warp per head ---
    if (wid < H) {
        float edi = ed[i * H + wid];
        float m = -1e30f;
        for (int p = p0 + lane; p < p1; p += 32) {
            float e = es[g_csrsrc[p] * H + wid] + edi;
            e = (e > 0.f) ? e : 0.2f * e;
            m = fmaxf(m, e);
        }
#pragma unroll
        for (int o = 16; o > 0; o >>= 1) m = fmaxf(m, __shfl_xor_sync(0xffffffffu, m, o));
        float den = 0.f;
        for (int p = p0 + lane; p < p1; p += 32) {
            float e = es[g_csrsrc[p] * H + wid] + edi;
            e = (e > 0.f) ? e : 0.2f * e;
            den += expf(e - m);
        }
#pragma unroll
        for (int o = 16; o > 0; o >>= 1) den += __shfl_xor_sync(0xffffffffu, den, o);
        if (lane == 0) { sm_m[wid] = m; sm_inv[wid] = 1.f / den; }
    }
    __syncthreads();

    if (MODE == 0) {
        const int base = t * 8;
        const int hd = t >> 6;          // head of col block (8t/512)
        float acc[8];
#pragma unroll
        for (int k = 0; k < 8; k++) acc[k] = 0.f;

        for (int c0 = p0; c0 < p1; c0 += CAP) {
            int n = min(p1 - c0, CAP);
            for (int idx = t; idx < n * H; idx += 256) {
                int j = idx >> 2, h = idx & (H - 1);
                int s = g_csrsrc[c0 + j];
                if (h == 0) sm_srcs[j] = s;
                float e = es[s * H + h] + ed[i * H + h];
                e = (e > 0.f) ? e : 0.2f * e;
                sm_alpha[j * H + h] = expf(e - sm_m[h]) * sm_inv[h];
            }
            __syncthreads();
            for (int j = 0; j < n; j++) {
                int s = sm_srcs[j];
                float av = sm_alpha[j * H + hd];
                uint4 rv = *(const uint4*)(hmat + (size_t)s * HC + base);
                float2 f0 = __half22float2(*(__half2*)&rv.x);
                float2 f1 = __half22float2(*(__half2*)&rv.y);
                float2 f2 = __half22float2(*(__half2*)&rv.z);
                float2 f3 = __half22float2(*(__half2*)&rv.w);
                acc[0] += av * f0.x; acc[1] += av * f0.y;
                acc[2] += av * f1.x; acc[3] += av * f1.y;
                acc[4] += av * f2.x; acc[5] += av * f2.y;
                acc[6] += av * f3.x; acc[7] += av * f3.y;
            }
            __syncthreads();
        }

        float4 b0 = *(const float4*)(bias + base);
        float4 b1 = *(const float4*)(bias + base + 4);
        float v[8] = { acc[0] + b0.x, acc[1] + b0.y, acc[2] + b0.z, acc[3] + b0.w,
                       acc[4] + b1.x, acc[5] + b1.y, acc[6] + b1.z, acc[7] + b1.w };
        __half h[8];
#pragma unroll
        for (int k = 0; k < 8; k++) {
            float e = (v[k] > 0.f) ? v[k] : (expf(v[k]) - 1.f);
            h[k] = __float2half(e);
        }
        uint4 ov;
        ov.x = *(uint32_t*)&h[0]; ov.y = *(uint32_t*)&h[2];
        ov.z = *(uint32_t*)&h[4]; ov.w = *(uint32_t*)&h[6];
        *(uint4*)(outH + (size_t)i * HC + base) = ov;
    } else {
        const int base = t * 4;
        const int hd = t >> 7;          // head of col block (4t/512)
        float4 acc = make_float4(0.f, 0.f, 0.f, 0.f);

        for (int c0 = p0; c0 < p1; c0 += CAP) {
            int n = min(p1 - c0, CAP);
            for (int idx = t; idx < n * H; idx += 256) {
                int j = idx >> 1, h = idx & (H - 1);
                int s = g_csrsrc[c0 + j];
                if (h == 0) sm_srcs[j] = s;
                float e = es[s * H + h] + ed[i * H + h];
                e = (e > 0.f) ? e : 0.2f * e;
                sm_alpha[j * H + h] = expf(e - sm_m[h]) * sm_inv[h];
            }
            __syncthreads();
            for (int j = 0; j < n; j++) {
                int s = sm_srcs[j];
                float av = sm_alpha[j * H + hd];
                uint2 rv = *(const uint2*)(hmat + (size_t)s * HC + base);
                float2 f0 = __half22float2(*(__half2*)&rv.x);
                float2 f1 = __half22float2(*(__half2*)&rv.y);
                acc.x += av * f0.x; acc.y += av * f0.y;
                acc.z += av * f1.x; acc.w += av * f1.y;
            }
            __syncthreads();
        }

        sm_red[t] = acc;
        __syncthreads();
        if (t < 128) {
            float4 v0 = sm_red[t], v1 = sm_red[t + 128];
            float4 b = ((const float4*)bias)[t];
            float4 r;
            r.x = 0.5f * (v0.x + v1.x) + b.x;
            r.y = 0.5f * (v0.y + v1.y) + b.y;
            r.z = 0.5f * (v0.z + v1.z) + b.z;
            r.w = 0.5f * (v0.w + v1.w) + b.w;
            ((float4*)outF)[(size_t)i * 128 + t] = r;
        }
    }
}

// ---------------- host launch helpers ----------------------------------------
static void run_gemm16(const __half* a, const __half* w, const float* bias,
                       __half* C, int M, int N, int K, int moff, int rows,
                       cudaStream_t st) {
    dim3 grid(N / 128, (rows + 127) / 128);
    gemm16_kernel<<<grid, 256, HSMEM, st>>>(a, w, bias, C, M, N, K, moff);
}

extern "C" void kernel_launch(void* const* d_in, const int* in_sizes, int n_in,
                              void* d_out, int out_size) {
    const float* x      = (const float*)d_in[0];
    const void*  ei     = d_in[1];
    const float* proj_w = (const float*)d_in[2];
    const float* proj_b = (const float*)d_in[3];
    const float* w1  = (const float*)d_in[4];
    const float* as1 = (const float*)d_in[5];
    const float* ad1 = (const float*)d_in[6];
    const float* b1  = (const float*)d_in[7];
    const float* w2  = (const float*)d_in[8];
    const float* as2 = (const float*)d_in[9];
    const float* ad2 = (const float*)d_in[10];
    const float* b2  = (const float*)d_in[11];
    const float* w3  = (const float*)d_in[12];
    const float* as3 = (const float*)d_in[13];
    const float* ad3 = (const float*)d_in[14];
    const float* b3  = (const float*)d_in[15];
    float* out = (float*)d_out;

    __half *hmA, *hmB, *P0, *P1, *WtP, *Wt1, *Wt2, *Wt3;
    float *esA, *edA, *esB, *edB;
    cudaGetSymbolAddress((void**)&hmA, g_hmatA);
    cudaGetSymbolAddress((void**)&hmB, g_hmatB);
    cudaGetSymbolAddress((void**)&P0, g_P0);
    cudaGetSymbolAddress((void**)&P1, g_P1);
    cudaGetSymbolAddress((void**)&WtP, g_WtP);
    cudaGetSymbolAddress((void**)&Wt1, g_Wt1);
    cudaGetSymbolAddress((void**)&Wt2, g_Wt2);
    cudaGetSymbolAddress((void**)&Wt3, g_Wt3);
    cudaGetSymbolAddress((void**)&esA, g_esA);
    cudaGetSymbolAddress((void**)&edA, g_edA);
    cudaGetSymbolAddress((void**)&esB, g_esB);
    cudaGetSymbolAddress((void**)&edB, g_edB);

    static cudaStream_t s2 = nullptr, sW = nullptr, sC = nullptr;
    static cudaEvent_t evRoot, evWp, evW1, evW2, evW3, evCSR, evEnd2;
    static cudaEvent_t evT1[3], evT2[3];
    if (!s2) {
        cudaFuncSetAttribute((const void*)gemm16_kernel,
                             cudaFuncAttributeMaxDynamicSharedMemorySize, HSMEM);
        cudaStreamCreateWithFlags(&s2, cudaStreamNonBlocking);
        cudaStreamCreateWithFlags(&sW, cudaStreamNonBlocking);
        cudaStreamCreateWithFlags(&sC, cudaStreamNonBlocking);
        cudaEventCreateWithFlags(&evRoot, cudaEventDisableTiming);
        cudaEventCreateWithFlags(&evWp,  cudaEventDisableTiming);
        cudaEventCreateWithFlags(&evW1,  cudaEventDisableTiming);
        cudaEventCreateWithFlags(&evW2,  cudaEventDisableTiming);
        cudaEventCreateWithFlags(&evW3,  cudaEventDisableTiming);
        cudaEventCreateWithFlags(&evCSR, cudaEventDisableTiming);
        cudaEventCreateWithFlags(&evEnd2, cudaEventDisableTiming);
        for (int k = 0; k < 3; k++) {
            cudaEventCreateWithFlags(&evT1[k], cudaEventDisableTiming);
            cudaEventCreateWithFlags(&evT2[k], cudaEventDisableTiming);
        }
    }

    // ---- fork side streams off the capture-origin stream ----
    cudaEventRecord(evRoot, 0);
    cudaStreamWaitEvent(s2, evRoot, 0);
    cudaStreamWaitEvent(sW, evRoot, 0);
    cudaStreamWaitEvent(sC, evRoot, 0);

    // stream W: weight transposes
    cvt_transpose_f16_kernel<<<dim3(512 / 32, 256 / 32), dim3(32, 8), 0, sW>>>(proj_w, WtP, 256, 512);
    cudaEventRecord(evWp, sW);
    cvt_transpose_f16_kernel<<<dim3(2048 / 32, 512 / 32), dim3(32, 8), 0, sW>>>(w1, Wt1, 512, 2048);
    cudaEventRecord(evW1, sW);
    cvt_transpose_f16_kernel<<<dim3(2048 / 32, 2048 / 32), dim3(32, 8), 0, sW>>>(w2, Wt2, 2048, 2048);
    cudaEventRecord(evW2, sW);
    cvt_transpose_f16_kernel<<<dim3(1024 / 32, 2048 / 32), dim3(32, 8), 0, sW>>>(w3, Wt3, 2048, 1024);
    cudaEventRecord(evW3, sW);

    // stream C: CSR build
    detect_init_kernel<<<(NN + 255) / 256, 256, 0, sC>>>((const unsigned int*)ei);
    count_kernel<<<(EE + 255) / 256, 256, 0, sC>>>(ei);
    scan_fillself_kernel<<<1, 1024, 0, sC>>>();
    filledges_kernel<<<(EE + 255) / 256, 256, 0, sC>>>(ei);
    cudaEventRecord(evCSR, sC);

    // ---- half-pipelined main chain: s1 = stream 0 (rows [0,MH1)), s2 (rows [MH1,NN)) ----
    // x convert halves
    cvt_f16_kernel<<<(MH1 * 256 / 4 + 255) / 256, 256, 0, 0>>>(x, P0, MH1 * 256 / 4);
    cvt_f16_kernel<<<(MH2 * 256 / 4 + 255) / 256, 256, 0, s2>>>(
        x + (size_t)MH1 * 256, P0 + (size_t)MH1 * 256, MH2 * 256 / 4);

    // proj GEMM halves (fp16, +bias): P1 = P0 @ WtP^T
    cudaStreamWaitEvent(0, evWp, 0);
    run_gemm16(P0, WtP, proj_b, P1, NN, 512, 256, 0, MH1, 0);
    cudaStreamWaitEvent(s2, evWp, 0);
    run_gemm16(P0, WtP, proj_b, P1, NN, 512, 256, MH1, MH2, s2);

    struct Layer {
        const float *as, *ad, *bias;
        const __half* Win;
        cudaEvent_t evW;
        __half* hm;
        float *es, *ed;
    };

    // ---- layer 1: hmA = P1 @ Wt1^T ; agg -> P0 ----
    cudaStreamWaitEvent(0, evW1, 0);
    run_gemm16(P1, Wt1, nullptr, hmA, NN, 2048, 512, 0, MH1, 0);
    cudaStreamWaitEvent(s2, evW1, 0);
    run_gemm16(P1, Wt1, nullptr, hmA, NN, 2048, 512, MH1, MH2, s2);
    attn_kernel<<<MH1, 128, 0, 0>>>(hmA, as1, ad1, esA, edA, 4, 0);
    cudaEventRecord(evT1[0], 0);
    attn_kernel<<<MH2, 128, 0, s2>>>(hmA, as1, ad1, esA, edA, 4, MH1);
    cudaEventRecord(evT2[0], s2);
    cudaStreamWaitEvent(0, evT2[0], 0);
    cudaStreamWaitEvent(0, evCSR, 0);
    aggregate_kernel<2048, 4, 0><<<MH1, 256, 0, 0>>>(hmA, esA, edA, b1, nullptr, P0, 0);
    cudaStreamWaitEvent(s2, evT1[0], 0);
    cudaStreamWaitEvent(s2, evCSR, 0);
    aggregate_kernel<2048, 4, 0><<<MH2, 256, 0, s2>>>(hmA, esA, edA, b1, nullptr, P0, MH1);

    // ---- layer 2: hmB = P0 @ Wt2^T ; agg -> P1 ----
    cudaStreamWaitEvent(0, evW2, 0);
    run_gemm16(P0, Wt2, nullptr, hmB, NN, 2048, 2048, 0, MH1, 0);
    cudaStreamWaitEvent(s2, evW2, 0);
    run_gemm16(P0, Wt2, nullptr, hmB, NN, 2048, 2048, MH1, MH2, s2);
    attn_kernel<<<MH1, 128, 0, 0>>>(hmB, as2, ad2, esB, edB, 4, 0);
    cudaEventRecord(evT1[1], 0);
    attn_kernel<<<MH2, 128, 0, s2>>>(hmB, as2, ad2, esB, edB, 4, MH1);
    cudaEventRecord(evT2[1], s2);
    cudaStreamWaitEvent(0, evT2[1], 0);
    aggregate_kernel<2048, 4, 0><<<MH1, 256, 0, 0>>>(hmB, esB, edB, b2, nullptr, P1, 0);
    cudaStreamWaitEvent(s2, evT1[1], 0);
    aggregate_kernel<2048, 4, 0><<<MH2, 256, 0, s2>>>(hmB, esB, edB, b2, nullptr, P1, MH1);

    // ---- layer 3: hmA = P1 @ Wt3^T ; agg -> out (mean heads) ----
    cudaStreamWaitEvent(0, evW3, 0);
    run_gemm16(P1, Wt3, nullptr, hmA, NN, 1024, 2048, 0, MH1, 0);
    cudaStreamWaitEvent(s2, evW3, 0);
    run_gemm16(P1, Wt3, nullptr, hmA, NN, 1024, 2048, MH1, MH2, s2);
    attn_kernel<<<MH1, 64, 0, 0>>>(hmA, as3, ad3, esA, edA, 2, 0);
    cudaEventRecord(evT1[2], 0);
    attn_kernel<<<MH2, 64, 0, s2>>>(hmA, as3, ad3, esA, edA, 2, MH1);
    cudaEventRecord(evT2[2], s2);
    cudaStreamWaitEvent(0, evT2[2], 0);
    aggregate_kernel<1024, 2, 1><<<MH1, 256, 0, 0>>>(hmA, esA, edA, b3, out, nullptr, 0);
    cudaStreamWaitEvent(s2, evT1[2], 0);
    aggregate_kernel<1024, 2, 1><<<MH2, 256, 0, s2>>>(hmA, esA, edA, b3, out, nullptr, MH1);

    // ---- join s2 back into the origin stream ----
    cudaEventRecord(evEnd2, s2);
    cudaStreamWaitEvent(0, evEnd2, 0);
}

// round 16
// speedup vs baseline: 3.4806x; 1.0266x over previous
#include <cuda_runtime.h>
#include <cuda_fp16.h>
#include <math.h>
#include <stdint.h>

#define NN 10000
#define EE 160000
#define ET 170000   // edges + self loops
#define MH1 5120    // node/row half split
#define MH2 (NN - MH1)

// ---------------- scratch (device globals; no allocations allowed) ----------
__device__ __align__(16) __half g_hmatA[NN * 2048];  // layers 1 and 3
__device__ __align__(16) __half g_hmatB[NN * 2048];  // layer 2
__device__ float g_esA[NN * 4], g_edA[NN * 4];       // layers 1 and 3
__device__ float g_esB[NN * 4], g_edB[NN * 4];       // layer 2
__device__ int   g_counts [NN];
__device__ int   g_rowptr [NN + 1];
__device__ int   g_fillpos[NN];
__device__ int   g_csrsrc [ET];
__device__ int   g_is64;
// fp16 activation ping-pong + per-layer weight buffers
__device__ __align__(16) __half g_P0[NN * 2048];
__device__ __align__(16) __half g_P1[NN * 2048];
__device__ __align__(16) __half g_WtP[512 * 256];
__device__ __align__(16) __half g_Wt1[2048 * 512];
__device__ __align__(16) __half g_Wt2[2048 * 2048];
__device__ __align__(16) __half g_Wt3[1024 * 2048];

// ============================ PTX helpers (baseline, sm_80+) =================
__device__ __forceinline__ uint32_t smem_to_u32(const void* p) {
    uint32_t a;
    asm("{ .reg .u64 t; cvta.to.shared.u64 t, %1; cvt.u32.u64 %0, t; }" : "=r"(a) : "l"(p));
    return a;
}

__device__ __forceinline__ void cp16(uint32_t dst, const void* src, bool v) {
    int sz = v ? 16 : 0;
    asm volatile("cp.async.cg.shared.global [%0], [%1], 16, %2;\n"
                 :: "r"(dst), "l"(src), "r"(sz) : "memory");
}
#define CP_COMMIT() asm volatile("cp.async.commit_group;" ::: "memory")
#define CP_WAIT1()  asm volatile("cp.async.wait_group 1;" ::: "memory")

__device__ __forceinline__ void ldsm4(uint32_t* r, uint32_t addr) {
    asm volatile("ldmatrix.sync.aligned.m8n8.x4.shared.b16 {%0,%1,%2,%3}, [%4];"
                 : "=r"(r[0]), "=r"(r[1]), "=r"(r[2]), "=r"(r[3]) : "r"(addr));
}

__device__ __forceinline__ void mma_fp16(float* c, const uint32_t* a, const uint32_t* b) {
    asm volatile(
        "mma.sync.aligned.m16n8k16.row.col.f32.f16.f16.f32 "
        "{%0,%1,%2,%3}, {%4,%5,%6,%7}, {%8,%9}, {%0,%1,%2,%3};"
        : "+f"(c[0]), "+f"(c[1]), "+f"(c[2]), "+f"(c[3])
        : "r"(a[0]), "r"(a[1]), "r"(a[2]), "r"(a[3]), "r"(b[0]), "r"(b[1]));
}

__device__ __forceinline__ int edge_at(const void* ei, long long idx) {
    if (g_is64) return (int)((const long long*)ei)[idx];
    return ((const int*)ei)[idx];
}

// ---------------- CSR build ---------------------------------------------------
__global__ void detect_init_kernel(const unsigned int* p) {
    int i = blockIdx.x * blockDim.x + threadIdx.x;
    if (i < NN) g_counts[i] = 1;           // self loop pre-counted
    if (i == 0) {
        int is64 = 1;
        for (int j = 0; j < 128; j++)
            if (p[2 * j + 1] != 0u) { is64 = 0; break; }
        g_is64 = is64;
    }
}
__global__ void count_kernel(const void* ei) {
    int e = blockIdx.x * blockDim.x + threadIdx.x;
    if (e < EE) atomicAdd(&g_counts[edge_at(ei, (long long)EE + e)], 1);
}
__global__ void scan_fillself_kernel() {
    __shared__ int sh[1024];
    int t = threadIdx.x;
    const int chunk = (NN + 1023) >> 10;
    int base = t * chunk;
    int s = 0;
    for (int j = 0; j < chunk; j++) { int idx = base + j; if (idx < NN) s += g_counts[idx]; }
    sh[t] = s;
    __syncthreads();
    for (int off = 1; off < 1024; off <<= 1) {
        int v = (t >= off) ? sh[t - off] : 0;
        __syncthreads();
        sh[t] += v;
        __syncthreads();
    }
    int prefix = (t > 0) ? sh[t - 1] : 0;
    for (int j = 0; j < chunk; j++) {
        int idx = base + j;
        if (idx < NN) { g_rowptr[idx] = prefix; prefix += g_counts[idx]; }
    }
    if (t == 0) g_rowptr[NN] = sh[1023];
    __syncthreads();
    for (int idx = t; idx < NN; idx += 1024) {
        int r = g_rowptr[idx];
        g_csrsrc[r] = idx;
        g_fillpos[idx] = r + 1;
    }
}
__global__ void filledges_kernel(const void* ei) {
    int e = blockIdx.x * blockDim.x + threadIdx.x;
    if (e < EE) {
        int s = edge_at(ei, e);
        int d = edge_at(ei, (long long)EE + e);
        g_csrsrc[atomicAdd(&g_fillpos[d], 1)] = s;
    }
}

// ---------------- fp32 -> fp16 convert (input x) ------------------------------
__global__ void cvt_f16_kernel(const float* __restrict__ x,
                               __half* __restrict__ o, int n4) {
    int i = blockIdx.x * blockDim.x + threadIdx.x;
    if (i >= n4) return;
    float4 v = ((const float4*)x)[i];
    ((__half2*)o)[2 * i]     = __halves2half2(__float2half(v.x), __float2half(v.y));
    ((__half2*)o)[2 * i + 1] = __halves2half2(__float2half(v.z), __float2half(v.w));
}

// ---------------- weight transpose: W[K,N] -> Wt[N,K] fp16 -------------------
__global__ void cvt_transpose_f16_kernel(const float* __restrict__ W,
                                         __half* __restrict__ th, int K, int N) {
    __shared__ float tile[32][33];
    int n0 = blockIdx.x * 32, k0 = blockIdx.y * 32;
    int tx = threadIdx.x, ty = threadIdx.y;   // 32 x 8
    for (int r = ty; r < 32; r += 8)
        tile[r][tx] = W[(size_t)(k0 + r) * N + n0 + tx];
    __syncthreads();
    for (int r = ty; r < 32; r += 8)
        th[(size_t)(n0 + r) * K + k0 + tx] = __float2half(tile[tx][r]);
}

__device__ __forceinline__ uint32_t swz(uint32_t base, int row, int kelem) {
    return base + row * 128 + ((((kelem >> 3) ^ row) & 7) << 4);
}

// ---------------- fp16 single-pass GEMM, fp16 out (+bias), row-offset --------
#define HT 16384
#define HSTAGE (2 * HT)
#define HSMEM  (3 * HSTAGE)           // 98304

__global__ void __launch_bounds__(256, 2) gemm16_kernel(
    const __half* __restrict__ A, const __half* __restrict__ B,
    const float* __restrict__ bias, __half* __restrict__ C,
    int M, int N, int K, int moff)
{
    extern __shared__ char smem[];
    const uint32_t sb = smem_to_u32(smem);
    const int tid = threadIdx.x;
    const int lane = tid & 31, wid = tid >> 5;
    const int m0 = blockIdx.y * 128 + moff, n0 = blockIdx.x * 128;
    const int nk = K >> 6;

    auto load_stage = [&](int s, int j) {
        const uint32_t sbase = sb + (uint32_t)s * HSTAGE;
        const int lchk = tid & 7;
        const int lrow = tid >> 3;        // 0..31
        const bool jv = (j < nk);
        const long long k0 = jv ? ((long long)j << 6) : 0;
#pragma unroll
        for (int it = 0; it < 4; it++) {
            int row = lrow + it * 32;
            bool av = jv && (m0 + row < M);
            int gr = (m0 + row < M) ? (m0 + row) : 0;
            cp16(swz(sbase, row, lchk * 8),
                 A + (size_t)gr * K + k0 + lchk * 8, av);
            cp16(swz(sbase + HT, row, lchk * 8),
                 B + (size_t)(n0 + row) * K + k0 + lchk * 8, jv);
        }
    };

    float acc[2][8][4];
#pragma unroll
    for (int a = 0; a < 2; a++)
#pragma unroll
        for (int b = 0; b < 8; b++)
#pragma unroll
            for (int c = 0; c < 4; c++) acc[a][b][c] = 0.f;

    load_stage(0, 0);
    CP_COMMIT();
    load_stage(1, 1);
    CP_COMMIT();

    const int mw = (wid & 3) * 32;      // 4 warp rows
    const int nw = (wid >> 2) * 64;     // 2 warp cols
    const int rsel = lane & 15;
    const int khalf = (lane >> 4) * 8;

    for (int i = 0; i < nk; i++) {
        CP_WAIT1();
        __syncthreads();
        load_stage((i + 2) % 3, i + 2);
        CP_COMMIT();

        const uint32_t sA = sb + (uint32_t)(i % 3) * HSTAGE;
        const uint32_t sB = sA + HT;
#pragma unroll
        for (int ks = 0; ks < 4; ks++) {
            const int ke = ks * 16 + khalf;
            uint32_t a[2][4], b[4][4];
#pragma unroll
            for (int mi = 0; mi < 2; mi++)
                ldsm4(a[mi], swz(sA, mw + mi * 16 + rsel, ke));
#pragma unroll
            for (int bi = 0; bi < 4; bi++)
                ldsm4(b[bi], swz(sB, nw + bi * 16 + rsel, ke));
#pragma unroll
            for (int mi = 0; mi < 2; mi++)
#pragma unroll
                for (int nj = 0; nj < 8; nj++) {
                    uint32_t b2[2] = { b[nj >> 1][nj & 1], b[nj >> 1][(nj & 1) + 2] };
                    mma_fp16(acc[mi][nj], a[mi], b2);
                }
        }
    }

#pragma unroll
    for (int mi = 0; mi < 2; mi++) {
#pragma unroll
        for (int nj = 0; nj < 8; nj++) {
            int col = n0 + nw + nj * 8 + (lane & 3) * 2;
            float bx = 0.f, by = 0.f;
            if (bias) { bx = bias[col]; by = bias[col + 1]; }
            int r0 = m0 + mw + mi * 16 + (lane >> 2);
            int r1 = r0 + 8;
            if (r0 < M)
                ((__half2*)C)[((size_t)r0 * N + col) >> 1] =
                    __halves2half2(__float2half(acc[mi][nj][0] + bx),
                                   __float2half(acc[mi][nj][1] + by));
            if (r1 < M)
                ((__half2*)C)[((size_t)r1 * N + col) >> 1] =
                    __halves2half2(__float2half(acc[mi][nj][2] + bx),
                                   __float2half(acc[mi][nj][3] + by));
        }
    }
}

// ---------------- per-node attention coefficients es/ed (fp16 hmat) ----------
__global__ void attn_kernel(const __half* __restrict__ hmat,
                            const float* __restrict__ a_src,
                            const float* __restrict__ a_dst,
                            float* __restrict__ es, float* __restrict__ ed,
                            int H, int off) {
    const int C = 512;
    int i = blockIdx.x + off;
    int hh = threadIdx.x >> 5;
    int lane = threadIdx.x & 31;
    const __half2* hr = (const __half2*)(hmat + (size_t)i * H * C + hh * C);
    float s = 0.f, d = 0.f;
    for (int c2 = lane; c2 < C / 2; c2 += 32) {
        float2 f = __half22float2(hr[c2]);
        s += f.x * a_src[hh * C + 2 * c2] + f.y * a_src[hh * C + 2 * c2 + 1];
        d += f.x * a_dst[hh * C + 2 * c2] + f.y * a_dst[hh * C + 2 * c2 + 1];
    }
#pragma unroll
    for (int o = 16; o > 0; o >>= 1) {
        s += __shfl_xor_sync(0xffffffffu, s, o);
        d += __shfl_xor_sync(0xffffffffu, d, o);
    }
    if (lane == 0) { es[i * H + hh] = s; ed[i * H + hh] = d; }
}

// ---------------- fused softmax + weighted aggregation -----------------------
#define CAP 128

template <int HC, int H, int MODE>
__global__ void aggregate_kernel(const __half* __restrict__ hmat,
                                 const float* __restrict__ es,
                                 const float* __restrict__ ed,
                                 const float* __restrict__ bias,
                                 float* __restrict__ outF,
                                 __half* __restrict__ outH, int off) {
    __shared__ float sm_alpha[CAP * H];
    __shared__ int   sm_srcs[CAP];
    __shared__ float sm_m[H], sm_inv[H];
    __shared__ float4 sm_red[MODE == 1 ? 256 : 1];

    int i = blockIdx.x + off;
    int t = threadIdx.x;
    int lane = t & 31, wid = t >> 5;
    int p0 = g_rowptr[i], p1 = g_rowptr[i + 1];

    // --- softmax stats: warp per head ---
    if (wid < H) {
        float edi = ed[i * H + wid];
        float m = -1e30f;
        for (int p = p0 + lane; p < p1; p += 32) {
            float e = es[g_csrsrc[p] * H + wid] + edi;
            e = (e > 0.f) ? e : 0.2f * e;
            m = fmaxf(m, e);
        }
#pragma unroll
        for (int o = 16; o > 0; o >>= 1) m = fmaxf(m, __shfl_xor_sync(0xffffffffu, m, o));
        float den = 0.f;
        for (int p = p0 + lane; p < p1; p += 32) {
            float e = es[g_csrsrc[p] * H + wid] + edi;
            e = (e > 0.f) ? e : 0.2f * e;
            den += __expf(e - m);
        }
#pragma unroll
        for (int o = 16; o > 0; o >>= 1) den += __shfl_xor_sync(0xffffffffu, den, o);
        if (lane == 0) { sm_m[wid] = m; sm_inv[wid] = 1.f / den; }
    }
    __syncthreads();

    if (MODE == 0) {
        const int base = t * 8;
        const int hd = t >> 6;          // head of col block (8t/512)
        float acc[8];
#pragma unroll
        for (int k = 0; k < 8; k++) acc[k] = 0.f;

        for (int c0 = p0; c0 < p1; c0 += CAP) {
            int n = min(p1 - c0, CAP);
            for (int idx = t; idx < n * H; idx += 256) {
                int j = idx >> 2, h = idx & (H - 1);
                int s = g_csrsrc[c0 + j];
                if (h == 0) sm_srcs[j] = s;
                float e = es[s * H + h] + ed[i * H + h];
                e = (e > 0.f) ? e : 0.2f * e;
                sm_alpha[j * H + h] = __expf(e - sm_m[h]) * sm_inv[h];
            }
            __syncthreads();
            for (int j = 0; j < n; j++) {
                int s = sm_srcs[j];
                float av = sm_alpha[j * H + hd];
                uint4 rv = *(const uint4*)(hmat + (size_t)s * HC + base);
                float2 f0 = __half22float2(*(__half2*)&rv.x);
                float2 f1 = __half22float2(*(__half2*)&rv.y);
                float2 f2 = __half22float2(*(__half2*)&rv.z);
                float2 f3 = __half22float2(*(__half2*)&rv.w);
                acc[0] += av * f0.x; acc[1] += av * f0.y;
                acc[2] += av * f1.x; acc[3] += av * f1.y;
                acc[4] += av * f2.x; acc[5] += av * f2.y;
                acc[6] += av * f3.x; acc[7] += av * f3.y;
            }
            __syncthreads();
        }

        float4 b0 = *(const float4*)(bias + base);
        float4 b1 = *(const float4*)(bias + base + 4);
        float v[8] = { acc[0] + b0.x, acc[1] + b0.y, acc[2] + b0.z, acc[3] + b0.w,
                       acc[4] + b1.x, acc[5] + b1.y, acc[6] + b1.z, acc[7] + b1.w };
        __half h[8];
#pragma unroll
        for (int k = 0; k < 8; k++) {
            float e = (v[k] > 0.f) ? v[k] : (__expf(v[k]) - 1.f);
            h[k] = __float2half(e);
        }
        uint4 ov;
        ov.x = *(uint32_t*)&h[0]; ov.y = *(uint32_t*)&h[2];
        ov.z = *(uint32_t*)&h[4]; ov.w = *(uint32_t*)&h[6];
        *(uint4*)(outH + (size_t)i * HC + base) = ov;
    } else {
        const int base = t * 4;
        const int hd = t >> 7;          // head of col block (4t/512)
        float4 acc = make_float4(0.f, 0.f, 0.f, 0.f);

        for (int c0 = p0; c0 < p1; c0 += CAP) {
            int n = min(p1 - c0, CAP);
            for (int idx = t; idx < n * H; idx += 256) {
                int j = idx >> 1, h = idx & (H - 1);
                int s = g_csrsrc[c0 + j];
                if (h == 0) sm_srcs[j] = s;
                float e = es[s * H + h] + ed[i * H + h];
                e = (e > 0.f) ? e : 0.2f * e;
                sm_alpha[j * H + h] = __expf(e - sm_m[h]) * sm_inv[h];
            }
            __syncthreads();
            for (int j = 0; j < n; j++) {
                int s = sm_srcs[j];
                float av = sm_alpha[j * H + hd];
                uint2 rv = *(const uint2*)(hmat + (size_t)s * HC + base);
                float2 f0 = __half22float2(*(__half2*)&rv.x);
                float2 f1 = __half22float2(*(__half2*)&rv.y);
                acc.x += av * f0.x; acc.y += av * f0.y;
                acc.z += av * f1.x; acc.w += av * f1.y;
            }
            __syncthreads();
        }

        sm_red[t] = acc;
        __syncthreads();
        if (t < 128) {
            float4 v0 = sm_red[t], v1 = sm_red[t + 128];
            float4 b = ((const float4*)bias)[t];
            float4 r;
            r.x = 0.5f * (v0.x + v1.x) + b.x;
            r.y = 0.5f * (v0.y + v1.y) + b.y;
            r.z = 0.5f * (v0.z + v1.z) + b.z;
            r.w = 0.5f * (v0.w + v1.w) + b.w;
            ((float4*)outF)[(size_t)i * 128 + t] = r;
        }
    }
}

// ---------------- host launch helpers ----------------------------------------
static void run_gemm16(const __half* a, const __half* w, const float* bias,
                       __half* C, int M, int N, int K, int moff, int rows,
                       cudaStream_t st) {
    dim3 grid(N / 128, (rows + 127) / 128);
    gemm16_kernel<<<grid, 256, HSMEM, st>>>(a, w, bias, C, M, N, K, moff);
}

extern "C" void kernel_launch(void* const* d_in, const int* in_sizes, int n_in,
                              void* d_out, int out_size) {
    const float* x      = (const float*)d_in[0];
    const void*  ei     = d_in[1];
    const float* proj_w = (const float*)d_in[2];
    const float* proj_b = (const float*)d_in[3];
    const float* w1  = (const float*)d_in[4];
    const float* as1 = (const float*)d_in[5];
    const float* ad1 = (const float*)d_in[6];
    const float* b1  = (const float*)d_in[7];
    const float* w2  = (const float*)d_in[8];
    const float* as2 = (const float*)d_in[9];
    const float* ad2 = (const float*)d_in[10];
    const float* b2  = (const float*)d_in[11];
    const float* w3  = (const float*)d_in[12];
    const float* as3 = (const float*)d_in[13];
    const float* ad3 = (const float*)d_in[14];
    const float* b3  = (const float*)d_in[15];
    float* out = (float*)d_out;

    __half *hmA, *hmB, *P0, *P1, *WtP, *Wt1, *Wt2, *Wt3;
    float *esA, *edA, *esB, *edB;
    cudaGetSymbolAddress((void**)&hmA, g_hmatA);
    cudaGetSymbolAddress((void**)&hmB, g_hmatB);
    cudaGetSymbolAddress((void**)&P0, g_P0);
    cudaGetSymbolAddress((void**)&P1, g_P1);
    cudaGetSymbolAddress((void**)&WtP, g_WtP);
    cudaGetSymbolAddress((void**)&Wt1, g_Wt1);
    cudaGetSymbolAddress((void**)&Wt2, g_Wt2);
    cudaGetSymbolAddress((void**)&Wt3, g_Wt3);
    cudaGetSymbolAddress((void**)&esA, g_esA);
    cudaGetSymbolAddress((void**)&edA, g_edA);
    cudaGetSymbolAddress((void**)&esB, g_esB);
    cudaGetSymbolAddress((void**)&edB, g_edB);

    static cudaStream_t s2 = nullptr, sW = nullptr, sC = nullptr;
    static cudaEvent_t evRoot, evWp, evW1, evW2, evW3, evCSR, evEnd2;
    static cudaEvent_t evT1[3], evT2[3];
    if (!s2) {
        cudaFuncSetAttribute((const void*)gemm16_kernel,
                             cudaFuncAttributeMaxDynamicSharedMemorySize, HSMEM);
        cudaStreamCreateWithFlags(&s2, cudaStreamNonBlocking);
        cudaStreamCreateWithFlags(&sW, cudaStreamNonBlocking);
        cudaStreamCreateWithFlags(&sC, cudaStreamNonBlocking);
        cudaEventCreateWithFlags(&evRoot, cudaEventDisableTiming);
        cudaEventCreateWithFlags(&evWp,  cudaEventDisableTiming);
        cudaEventCreateWithFlags(&evW1,  cudaEventDisableTiming);
        cudaEventCreateWithFlags(&evW2,  cudaEventDisableTiming);
        cudaEventCreateWithFlags(&evW3,  cudaEventDisableTiming);
        cudaEventCreateWithFlags(&evCSR, cudaEventDisableTiming);
        cudaEventCreateWithFlags(&evEnd2, cudaEventDisableTiming);
        for (int k = 0; k < 3; k++) {
            cudaEventCreateWithFlags(&evT1[k], cudaEventDisableTiming);
            cudaEventCreateWithFlags(&evT2[k], cudaEventDisableTiming);
        }
    }

    // ---- fork side streams off the capture-origin stream ----
    cudaEventRecord(evRoot, 0);
    cudaStreamWaitEvent(s2, evRoot, 0);
    cudaStreamWaitEvent(sW, evRoot, 0);
    cudaStreamWaitEvent(sC, evRoot, 0);

    // stream W: weight transposes
    cvt_transpose_f16_kernel<<<dim3(512 / 32, 256 / 32), dim3(32, 8), 0, sW>>>(proj_w, WtP, 256, 512);
    cudaEventRecord(evWp, sW);
    cvt_transpose_f16_kernel<<<dim3(2048 / 32, 512 / 32), dim3(32, 8), 0, sW>>>(w1, Wt1, 512, 2048);
    cudaEventRecord(evW1, sW);
    cvt_transpose_f16_kernel<<<dim3(2048 / 32, 2048 / 32), dim3(32, 8), 0, sW>>>(w2, Wt2, 2048, 2048);
    cudaEventRecord(evW2, sW);
    cvt_transpose_f16_kernel<<<dim3(1024 / 32, 2048 / 32), dim3(32, 8), 0, sW>>>(w3, Wt3, 2048, 1024);
    cudaEventRecord(evW3, sW);

    // stream C: CSR build
    detect_init_kernel<<<(NN + 255) / 256, 256, 0, sC>>>((const unsigned int*)ei);
    count_kernel<<<(EE + 255) / 256, 256, 0, sC>>>(ei);
    scan_fillself_kernel<<<1, 1024, 0, sC>>>();
    filledges_kernel<<<(EE + 255) / 256, 256, 0, sC>>>(ei);
    cudaEventRecord(evCSR, sC);

    // ---- half-pipelined main chain: stream 0 (rows [0,MH1)), s2 (rows [MH1,NN)) ----
    cvt_f16_kernel<<<(MH1 * 256 / 4 + 255) / 256, 256, 0, 0>>>(x, P0, MH1 * 256 / 4);
    cvt_f16_kernel<<<(MH2 * 256 / 4 + 255) / 256, 256, 0, s2>>>(
        x + (size_t)MH1 * 256, P0 + (size_t)MH1 * 256, MH2 * 256 / 4);

    // proj GEMM halves (fp16, +bias): P1 = P0 @ WtP^T
    cudaStreamWaitEvent(0, evWp, 0);
    run_gemm16(P0, WtP, proj_b, P1, NN, 512, 256, 0, MH1, 0);
    cudaStreamWaitEvent(s2, evWp, 0);
    run_gemm16(P0, WtP, proj_b, P1, NN, 512, 256, MH1, MH2, s2);

    // ---- layer 1: hmA = P1 @ Wt1^T ; agg -> P0 ----
    cudaStreamWaitEvent(0, evW1, 0);
    run_gemm16(P1, Wt1, nullptr, hmA, NN, 2048, 512, 0, MH1, 0);
    cudaStreamWaitEvent(s2, evW1, 0);
    run_gemm16(P1, Wt1, nullptr, hmA, NN, 2048, 512, MH1, MH2, s2);
    attn_kernel<<<MH1, 128, 0, 0>>>(hmA, as1, ad1, esA, edA, 4, 0);
    cudaEventRecord(evT1[0], 0);
    attn_kernel<<<MH2, 128, 0, s2>>>(hmA, as1, ad1, esA, edA, 4, MH1);
    cudaEventRecord(evT2[0], s2);
    cudaStreamWaitEvent(0, evT2[0], 0);
    cudaStreamWaitEvent(0, evCSR, 0);
    aggregate_kernel<2048, 4, 0><<<MH1, 256, 0, 0>>>(hmA, esA, edA, b1, nullptr, P0, 0);
    cudaStreamWaitEvent(s2, evT1[0], 0);
    cudaStreamWaitEvent(s2, evCSR, 0);
    aggregate_kernel<2048, 4, 0><<<MH2, 256, 0, s2>>>(hmA, esA, edA, b1, nullptr, P0, MH1);

    // ---- layer 2: hmB = P0 @ Wt2^T ; agg -> P1 ----
    cudaStreamWaitEvent(0, evW2, 0);
    run_gemm16(P0, Wt2, nullptr, hmB, NN, 2048, 2048, 0, MH1, 0);
    cudaStreamWaitEvent(s2, evW2, 0);
    run_gemm16(P0, Wt2, nullptr, hmB, NN, 2048, 2048, MH1, MH2, s2);
    attn_kernel<<<MH1, 128, 0, 0>>>(hmB, as2, ad2, esB, edB, 4, 0);
    cudaEventRecord(evT1[1], 0);
    attn_kernel<<<MH2, 128, 0, s2>>>(hmB, as2, ad2, esB, edB, 4, MH1);
    cudaEventRecord(evT2[1], s2);
    cudaStreamWaitEvent(0, evT2[1], 0);
    aggregate_kernel<2048, 4, 0><<<MH1, 256, 0, 0>>>(hmB, esB, edB, b2, nullptr, P1, 0);
    cudaStreamWaitEvent(s2, evT1[1], 0);
    aggregate_kernel<2048, 4, 0><<<MH2, 256, 0, s2>>>(hmB, esB, edB, b2, nullptr, P1, MH1);

    // ---- layer 3: hmA = P1 @ Wt3^T ; agg -> out (mean heads) ----
    cudaStreamWaitEvent(0, evW3, 0);
    run_gemm16(P1, Wt3, nullptr, hmA, NN, 1024, 2048, 0, MH1, 0);
    cudaStreamWaitEvent(s2, evW3, 0);
    run_gemm16(P1, Wt3, nullptr, hmA, NN, 1024, 2048, MH1, MH2, s2);
    attn_kernel<<<MH1, 64, 0, 0>>>(hmA, as3, ad3, esA, edA, 2, 0);
    cudaEventRecord(evT1[2], 0);
    attn_kernel<<<MH2, 64, 0, s2>>>(hmA, as3, ad3, esA, edA, 2, MH1);
    cudaEventRecord(evT2[2], s2);
    cudaStreamWaitEvent(0, evT2[2], 0);
    aggregate_kernel<1024, 2, 1><<<MH1, 256, 0, 0>>>(hmA, esA, edA, b3, out, nullptr, 0);
    cudaStreamWaitEvent(s2, evT1[2], 0);
    aggregate_kernel<1024, 2, 1><<<MH2, 256, 0, s2>>>(hmA, esA, edA, b3, out, nullptr, MH1);

    // ---- join s2 back into the origin stream ----
    cudaEventRecord(evEnd2, s2);
    cudaStreamWaitEvent(0, evEnd2, 0);
}

// round 17
// speedup vs baseline: 3.5429x; 1.0179x over previous
#include <cuda_runtime.h>
#include <cuda_fp16.h>
#include <math.h>
#include <stdint.h>

#define NN 10000
#define EE 160000
#define ET 170000   // edges + self loops
#define MH1 5120    // node/row half split
#define MH2 (NN - MH1)

// ---------------- scratch (device globals; no allocations allowed) ----------
__device__ __align__(16) __half g_hmatA[NN * 2048];  // layers 1 and 3
__device__ __align__(16) __half g_hmatB[NN * 2048];  // layer 2
// es/ed for all 3 layers, contiguous for one memset:
// [0]=esA [1]=edA [2]=esB [3]=edB [4]=esC [5]=edC, each NN*4 floats
__device__ float g_esed[6 * NN * 4];
__device__ int   g_counts [NN];
__device__ int   g_rowptr [NN + 1];
__device__ int   g_fillpos[NN];
__device__ int   g_csrsrc [ET];
__device__ int   g_is64;
// fp16 activation ping-pong + per-layer weight buffers
__device__ __align__(16) __half g_P0[NN * 2048];
__device__ __align__(16) __half g_P1[NN * 2048];
__device__ __align__(16) __half g_WtP[512 * 256];
__device__ __align__(16) __half g_Wt1[2048 * 512];
__device__ __align__(16) __half g_Wt2[2048 * 2048];
__device__ __align__(16) __half g_Wt3[1024 * 2048];

// ============================ PTX helpers (baseline, sm_80+) =================
__device__ __forceinline__ uint32_t smem_to_u32(const void* p) {
    uint32_t a;
    asm("{ .reg .u64 t; cvta.to.shared.u64 t, %1; cvt.u32.u64 %0, t; }" : "=r"(a) : "l"(p));
    return a;
}

__device__ __forceinline__ void cp16(uint32_t dst, const void* src, bool v) {
    int sz = v ? 16 : 0;
    asm volatile("cp.async.cg.shared.global [%0], [%1], 16, %2;\n"
                 :: "r"(dst), "l"(src), "r"(sz) : "memory");
}
#define CP_COMMIT() asm volatile("cp.async.commit_group;" ::: "memory")
#define CP_WAIT1()  asm volatile("cp.async.wait_group 1;" ::: "memory")

__device__ __forceinline__ void ldsm4(uint32_t* r, uint32_t addr) {
    asm volatile("ldmatrix.sync.aligned.m8n8.x4.shared.b16 {%0,%1,%2,%3}, [%4];"
                 : "=r"(r[0]), "=r"(r[1]), "=r"(r[2]), "=r"(r[3]) : "r"(addr));
}

__device__ __forceinline__ void mma_fp16(float* c, const uint32_t* a, const uint32_t* b) {
    asm volatile(
        "mma.sync.aligned.m16n8k16.row.col.f32.f16.f16.f32 "
        "{%0,%1,%2,%3}, {%4,%5,%6,%7}, {%8,%9}, {%0,%1,%2,%3};"
        : "+f"(c[0]), "+f"(c[1]), "+f"(c[2]), "+f"(c[3])
        : "r"(a[0]), "r"(a[1]), "r"(a[2]), "r"(a[3]), "r"(b[0]), "r"(b[1]));
}

__device__ __forceinline__ int edge_at(const void* ei, long long idx) {
    if (g_is64) return (int)((const long long*)ei)[idx];
    return ((const int*)ei)[idx];
}

// ---------------- CSR build ---------------------------------------------------
__global__ void detect_init_kernel(const unsigned int* p) {
    int i = blockIdx.x * blockDim.x + threadIdx.x;
    if (i < NN) g_counts[i] = 1;           // self loop pre-counted
    if (i == 0) {
        int is64 = 1;
        for (int j = 0; j < 128; j++)
            if (p[2 * j + 1] != 0u) { is64 = 0; break; }
        g_is64 = is64;
    }
}
__global__ void count_kernel(const void* ei) {
    int e = blockIdx.x * blockDim.x + threadIdx.x;
    if (e < EE) atomicAdd(&g_counts[edge_at(ei, (long long)EE + e)], 1);
}
__global__ void scan_fillself_kernel() {
    __shared__ int sh[1024];
    int t = threadIdx.x;
    const int chunk = (NN + 1023) >> 10;
    int base = t * chunk;
    int s = 0;
    for (int j = 0; j < chunk; j++) { int idx = base + j; if (idx < NN) s += g_counts[idx]; }
    sh[t] = s;
    __syncthreads();
    for (int off = 1; off < 1024; off <<= 1) {
        int v = (t >= off) ? sh[t - off] : 0;
        __syncthreads();
        sh[t] += v;
        __syncthreads();
    }
    int prefix = (t > 0) ? sh[t - 1] : 0;
    for (int j = 0; j < chunk; j++) {
        int idx = base + j;
        if (idx < NN) { g_rowptr[idx] = prefix; prefix += g_counts[idx]; }
    }
    if (t == 0) g_rowptr[NN] = sh[1023];
    __syncthreads();
    for (int idx = t; idx < NN; idx += 1024) {
        int r = g_rowptr[idx];
        g_csrsrc[r] = idx;
        g_fillpos[idx] = r + 1;
    }
}
__global__ void filledges_kernel(const void* ei) {
    int e = blockIdx.x * blockDim.x + threadIdx.x;
    if (e < EE) {
        int s = edge_at(ei, e);
        int d = edge_at(ei, (long long)EE + e);
        g_csrsrc[atomicAdd(&g_fillpos[d], 1)] = s;
    }
}

// ---------------- fp32 -> fp16 convert (input x) ------------------------------
__global__ void cvt_f16_kernel(const float* __restrict__ x,
                               __half* __restrict__ o, int n4) {
    int i = blockIdx.x * blockDim.x + threadIdx.x;
    if (i >= n4) return;
    float4 v = ((const float4*)x)[i];
    ((__half2*)o)[2 * i]     = __halves2half2(__float2half(v.x), __float2half(v.y));
    ((__half2*)o)[2 * i + 1] = __halves2half2(__float2half(v.z), __float2half(v.w));
}

// ---------------- weight transpose: W[K,N] -> Wt[N,K] fp16 -------------------
__global__ void cvt_transpose_f16_kernel(const float* __restrict__ W,
                                         __half* __restrict__ th, int K, int N) {
    __shared__ float tile[32][33];
    int n0 = blockIdx.x * 32, k0 = blockIdx.y * 32;
    int tx = threadIdx.x, ty = threadIdx.y;   // 32 x 8
    for (int r = ty; r < 32; r += 8)
        tile[r][tx] = W[(size_t)(k0 + r) * N + n0 + tx];
    __syncthreads();
    for (int r = ty; r < 32; r += 8)
        th[(size_t)(n0 + r) * K + k0 + tx] = __float2half(tile[tx][r]);
}

__device__ __forceinline__ uint32_t swz(uint32_t base, int row, int kelem) {
    return base + row * 128 + ((((kelem >> 3) ^ row) & 7) << 4);
}

// ---------------- fp16 single-pass GEMM, fp16 out (+bias), row-offset --------
// ES=1: epilogue also computes es/ed partials (dot with a_src/a_dst) and
// atomically accumulates into es/ed (must be pre-zeroed). CTA's 128-col tile
// lies within one head (128 | 512).
#define HT 16384
#define HSTAGE (2 * HT)
#define HSMEM  (3 * HSTAGE)           // 98304

template <int ES>
__global__ void __launch_bounds__(256, 2) gemm16_kernel(
    const __half* __restrict__ A, const __half* __restrict__ B,
    const float* __restrict__ bias, __half* __restrict__ C,
    const float* __restrict__ a_src, const float* __restrict__ a_dst,
    float* __restrict__ es, float* __restrict__ ed, int H,
    int M, int N, int K, int moff)
{
    extern __shared__ char smem[];
    const uint32_t sb = smem_to_u32(smem);
    const int tid = threadIdx.x;
    const int lane = tid & 31, wid = tid >> 5;
    const int m0 = blockIdx.y * 128 + moff, n0 = blockIdx.x * 128;
    const int nk = K >> 6;

    auto load_stage = [&](int s, int j) {
        const uint32_t sbase = sb + (uint32_t)s * HSTAGE;
        const int lchk = tid & 7;
        const int lrow = tid >> 3;        // 0..31
        const bool jv = (j < nk);
        const long long k0 = jv ? ((long long)j << 6) : 0;
#pragma unroll
        for (int it = 0; it < 4; it++) {
            int row = lrow + it * 32;
            bool av = jv && (m0 + row < M);
            int gr = (m0 + row < M) ? (m0 + row) : 0;
            cp16(swz(sbase, row, lchk * 8),
                 A + (size_t)gr * K + k0 + lchk * 8, av);
            cp16(swz(sbase + HT, row, lchk * 8),
                 B + (size_t)(n0 + row) * K + k0 + lchk * 8, jv);
        }
    };

    float acc[2][8][4];
#pragma unroll
    for (int a = 0; a < 2; a++)
#pragma unroll
        for (int b = 0; b < 8; b++)
#pragma unroll
            for (int c = 0; c < 4; c++) acc[a][b][c] = 0.f;

    load_stage(0, 0);
    CP_COMMIT();
    load_stage(1, 1);
    CP_COMMIT();

    const int mw = (wid & 3) * 32;      // 4 warp rows
    const int nw = (wid >> 2) * 64;     // 2 warp cols
    const int rsel = lane & 15;
    const int khalf = (lane >> 4) * 8;

    for (int i = 0; i < nk; i++) {
        CP_WAIT1();
        __syncthreads();
        load_stage((i + 2) % 3, i + 2);
        CP_COMMIT();

        const uint32_t sA = sb + (uint32_t)(i % 3) * HSTAGE;
        const uint32_t sB = sA + HT;
#pragma unroll
        for (int ks = 0; ks < 4; ks++) {
            const int ke = ks * 16 + khalf;
            uint32_t a[2][4], b[4][4];
#pragma unroll
            for (int mi = 0; mi < 2; mi++)
                ldsm4(a[mi], swz(sA, mw + mi * 16 + rsel, ke));
#pragma unroll
            for (int bi = 0; bi < 4; bi++)
                ldsm4(b[bi], swz(sB, nw + bi * 16 + rsel, ke));
#pragma unroll
            for (int mi = 0; mi < 2; mi++)
#pragma unroll
                for (int nj = 0; nj < 8; nj++) {
                    uint32_t b2[2] = { b[nj >> 1][nj & 1], b[nj >> 1][(nj & 1) + 2] };
                    mma_fp16(acc[mi][nj], a[mi], b2);
                }
        }
    }

    // fp16 store epilogue
#pragma unroll
    for (int mi = 0; mi < 2; mi++) {
#pragma unroll
        for (int nj = 0; nj < 8; nj++) {
            int col = n0 + nw + nj * 8 + (lane & 3) * 2;
            float bx = 0.f, by = 0.f;
            if (bias) { bx = bias[col]; by = bias[col + 1]; }
            int r0 = m0 + mw + mi * 16 + (lane >> 2);
            int r1 = r0 + 8;
            if (r0 < M)
                ((__half2*)C)[((size_t)r0 * N + col) >> 1] =
                    __halves2half2(__float2half(acc[mi][nj][0] + bx),
                                   __float2half(acc[mi][nj][1] + by));
            if (r1 < M)
                ((__half2*)C)[((size_t)r1 * N + col) >> 1] =
                    __halves2half2(__float2half(acc[mi][nj][2] + bx),
                                   __float2half(acc[mi][nj][3] + by));
        }
    }

    // fused attention-coefficient epilogue: es/ed partial dot + atomic add
    if (ES) {
        const int head = n0 >> 9;                 // n0 / 512
        float esp[2][2] = {{0.f, 0.f}, {0.f, 0.f}};
        float edp[2][2] = {{0.f, 0.f}, {0.f, 0.f}};
#pragma unroll
        for (int nj = 0; nj < 8; nj++) {
            int col = n0 + nw + nj * 8 + (lane & 3) * 2;
            float as0 = __ldg(a_src + col), as1 = __ldg(a_src + col + 1);
            float ad0 = __ldg(a_dst + col), ad1 = __ldg(a_dst + col + 1);
#pragma unroll
            for (int mi = 0; mi < 2; mi++) {
                esp[mi][0] += acc[mi][nj][0] * as0 + acc[mi][nj][1] * as1;
                esp[mi][1] += acc[mi][nj][2] * as0 + acc[mi][nj][3] * as1;
                edp[mi][0] += acc[mi][nj][0] * ad0 + acc[mi][nj][1] * ad1;
                edp[mi][1] += acc[mi][nj][2] * ad0 + acc[mi][nj][3] * ad1;
            }
        }
        // reduce over the 4 lanes sharing each row (lane&3)
#pragma unroll
        for (int o = 1; o <= 2; o <<= 1) {
#pragma unroll
            for (int mi = 0; mi < 2; mi++)
#pragma unroll
                for (int rr = 0; rr < 2; rr++) {
                    esp[mi][rr] += __shfl_xor_sync(0xffffffffu, esp[mi][rr], o);
                    edp[mi][rr] += __shfl_xor_sync(0xffffffffu, edp[mi][rr], o);
                }
        }
        if ((lane & 3) == 0) {
#pragma unroll
            for (int mi = 0; mi < 2; mi++)
#pragma unroll
                for (int rr = 0; rr < 2; rr++) {
                    int row = m0 + mw + mi * 16 + (lane >> 2) + rr * 8;
                    if (row < M) {
                        atomicAdd(&es[row * H + head], esp[mi][rr]);
                        atomicAdd(&ed[row * H + head], edp[mi][rr]);
                    }
                }
        }
    }
}

// ---------------- fused softmax + weighted aggregation -----------------------
#define CAP 128

template <int HC, int H, int MODE>
__global__ void aggregate_kernel(const __half* __restrict__ hmat,
                                 const float* __restrict__ es,
                                 const float* __restrict__ ed,
                                 const float* __restrict__ bias,
                                 float* __restrict__ outF,
                                 __half* __restrict__ outH, int off) {
    __shared__ float sm_alpha[CAP * H];
    __shared__ int   sm_srcs[CAP];
    __shared__ float sm_m[H], sm_inv[H];
    __shared__ float4 sm_red[MODE == 1 ? 256 : 1];

    int i = blockIdx.x + off;
    int t = threadIdx.x;
    int lane = t & 31, wid = t >> 5;
    int p0 = g_rowptr[i], p1 = g_rowptr[i + 1];

    // --- softmax stats: warp per head ---
    if (wid < H) {
        float edi = ed[i * H + wid];
        float m = -1e30f;
        for (int p = p0 + lane; p < p1; p += 32) {
            float e = es[g_csrsrc[p] * H + wid] + edi;
            e = (e > 0.f) ? e : 0.2f * e;
            m = fmaxf(m, e);
        }
#pragma unroll
        for (int o = 16; o > 0; o >>= 1) m = fmaxf(m, __shfl_xor_sync(0xffffffffu, m, o));
        float den = 0.f;
        for (int p = p0 + lane; p < p1; p += 32) {
            float e = es[g_csrsrc[p] * H + wid] + edi;
            e = (e > 0.f) ? e : 0.2f * e;
            den += __expf(e - m);
        }
#pragma unroll
        for (int o = 16; o > 0; o >>= 1) den += __shfl_xor_sync(0xffffffffu, den, o);
        if (lane == 0) { sm_m[wid] = m; sm_inv[wid] = 1.f / den; }
    }
    __syncthreads();

    if (MODE == 0) {
        const int base = t * 8;
        const int hd = t >> 6;          // head of col block (8t/512)
        float acc[8];
#pragma unroll
        for (int k = 0; k < 8; k++) acc[k] = 0.f;

        for (int c0 = p0; c0 < p1; c0 += CAP) {
            int n = min(p1 - c0, CAP);
            for (int idx = t; idx < n * H; idx += 256) {
                int j = idx >> 2, h = idx & (H - 1);
                int s = g_csrsrc[c0 + j];
                if (h == 0) sm_srcs[j] = s;
                float e = es[s * H + h] + ed[i * H + h];
                e = (e > 0.f) ? e : 0.2f * e;
                sm_alpha[j * H + h] = __expf(e - sm_m[h]) * sm_inv[h];
            }
            __syncthreads();
            for (int j = 0; j < n; j++) {
                int s = sm_srcs[j];
                float av = sm_alpha[j * H + hd];
                uint4 rv = *(const uint4*)(hmat + (size_t)s * HC + base);
                float2 f0 = __half22float2(*(__half2*)&rv.x);
                float2 f1 = __half22float2(*(__half2*)&rv.y);
                float2 f2 = __half22float2(*(__half2*)&rv.z);
                float2 f3 = __half22float2(*(__half2*)&rv.w);
                acc[0] += av * f0.x; acc[1] += av * f0.y;
                acc[2] += av * f1.x; acc[3] += av * f1.y;
                acc[4] += av * f2.x; acc[5] += av * f2.y;
                acc[6] += av * f3.x; acc[7] += av * f3.y;
            }
            __syncthreads();
        }

        float4 b0 = *(const float4*)(bias + base);
        float4 b1 = *(const float4*)(bias + base + 4);
        float v[8] = { acc[0] + b0.x, acc[1] + b0.y, acc[2] + b0.z, acc[3] + b0.w,
                       acc[4] + b1.x, acc[5] + b1.y, acc[6] + b1.z, acc[7] + b1.w };
        __half h[8];
#pragma unroll
        for (int k = 0; k < 8; k++) {
            float e = (v[k] > 0.f) ? v[k] : (__expf(v[k]) - 1.f);
            h[k] = __float2half(e);
        }
        uint4 ov;
        ov.x = *(uint32_t*)&h[0]; ov.y = *(uint32_t*)&h[2];
        ov.z = *(uint32_t*)&h[4]; ov.w = *(uint32_t*)&h[6];
        *(uint4*)(outH + (size_t)i * HC + base) = ov;
    } else {
        const int base = t * 4;
        const int hd = t >> 7;          // head of col block (4t/512)
        float4 acc = make_float4(0.f, 0.f, 0.f, 0.f);

        for (int c0 = p0; c0 < p1; c0 += CAP) {
            int n = min(p1 - c0, CAP);
            for (int idx = t; idx < n * H; idx += 256) {
                int j = idx >> 1, h = idx & (H - 1);
                int s = g_csrsrc[c0 + j];
                if (h == 0) sm_srcs[j] = s;
                float e = es[s * H + h] + ed[i * H + h];
                e = (e > 0.f) ? e : 0.2f * e;
                sm_alpha[j * H + h] = __expf(e - sm_m[h]) * sm_inv[h];
            }
            __syncthreads();
            for (int j = 0; j < n; j++) {
                int s = sm_srcs[j];
                float av = sm_alpha[j * H + hd];
                uint2 rv = *(const uint2*)(hmat + (size_t)s * HC + base);
                float2 f0 = __half22float2(*(__half2*)&rv.x);
                float2 f1 = __half22float2(*(__half2*)&rv.y);
                acc.x += av * f0.x; acc.y += av * f0.y;
                acc.z += av * f1.x; acc.w += av * f1.y;
            }
            __syncthreads();
        }

        sm_red[t] = acc;
        __syncthreads();
        if (t < 128) {
            float4 v0 = sm_red[t], v1 = sm_red[t + 128];
            float4 b = ((const float4*)bias)[t];
            float4 r;
            r.x = 0.5f * (v0.x + v1.x) + b.x;
            r.y = 0.5f * (v0.y + v1.y) + b.y;
            r.z = 0.5f * (v0.z + v1.z) + b.z;
            r.w = 0.5f * (v0.w + v1.w) + b.w;
            ((float4*)outF)[(size_t)i * 128 + t] = r;
        }
    }
}

// ---------------- host launch helpers ----------------------------------------
static void run_gemm_proj(const __half* a, const __half* w, const float* bias,
                          __half* C, int M, int N, int K, int moff, int rows,
                          cudaStream_t st) {
    dim3 grid(N / 128, (rows + 127) / 128);
    gemm16_kernel<0><<<grid, 256, HSMEM, st>>>(a, w, bias, C,
                                               nullptr, nullptr, nullptr, nullptr, 0,
                                               M, N, K, moff);
}
static void run_gemm_attn(const __half* a, const __half* w, __half* C,
                          const float* as, const float* ad,
                          float* es, float* ed, int H,
                          int M, int N, int K, int moff, int rows,
                          cudaStream_t st) {
    dim3 grid(N / 128, (rows + 127) / 128);
    gemm16_kernel<1><<<grid, 256, HSMEM, st>>>(a, w, nullptr, C,
                                               as, ad, es, ed, H,
                                               M, N, K, moff);
}

extern "C" void kernel_launch(void* const* d_in, const int* in_sizes, int n_in,
                              void* d_out, int out_size) {
    const float* x      = (const float*)d_in[0];
    const void*  ei     = d_in[1];
    const float* proj_w = (const float*)d_in[2];
    const float* proj_b = (const float*)d_in[3];
    const float* w1  = (const float*)d_in[4];
    const float* as1 = (const float*)d_in[5];
    const float* ad1 = (const float*)d_in[6];
    const float* b1  = (const float*)d_in[7];
    const float* w2  = (const float*)d_in[8];
    const float* as2 = (const float*)d_in[9];
    const float* ad2 = (const float*)d_in[10];
    const float* b2  = (const float*)d_in[11];
    const float* w3  = (const float*)d_in[12];
    const float* as3 = (const float*)d_in[13];
    const float* ad3 = (const float*)d_in[14];
    const float* b3  = (const float*)d_in[15];
    float* out = (float*)d_out;

    __half *hmA, *hmB, *P0, *P1, *WtP, *Wt1, *Wt2, *Wt3;
    float* esed;
    cudaGetSymbolAddress((void**)&hmA, g_hmatA);
    cudaGetSymbolAddress((void**)&hmB, g_hmatB);
    cudaGetSymbolAddress((void**)&P0, g_P0);
    cudaGetSymbolAddress((void**)&P1, g_P1);
    cudaGetSymbolAddress((void**)&WtP, g_WtP);
    cudaGetSymbolAddress((void**)&Wt1, g_Wt1);
    cudaGetSymbolAddress((void**)&Wt2, g_Wt2);
    cudaGetSymbolAddress((void**)&Wt3, g_Wt3);
    cudaGetSymbolAddress((void**)&esed, g_esed);
    float* esA = esed;
    float* edA = esed + NN * 4;
    float* esB = esed + 2 * NN * 4;
    float* edB = esed + 3 * NN * 4;
    float* esC = esed + 4 * NN * 4;
    float* edC = esed + 5 * NN * 4;

    static cudaStream_t s2 = nullptr, sW = nullptr, sC = nullptr;
    static cudaEvent_t evRoot, evWp, evW1, evW2, evW3, evCSR, evEnd2;
    static cudaEvent_t evG1[2], evG2[2], evG3[2];
    if (!s2) {
        cudaFuncSetAttribute((const void*)gemm16_kernel<0>,
                             cudaFuncAttributeMaxDynamicSharedMemorySize, HSMEM);
        cudaFuncSetAttribute((const void*)gemm16_kernel<1>,
                             cudaFuncAttributeMaxDynamicSharedMemorySize, HSMEM);
        cudaStreamCreateWithFlags(&s2, cudaStreamNonBlocking);
        cudaStreamCreateWithFlags(&sW, cudaStreamNonBlocking);
        cudaStreamCreateWithFlags(&sC, cudaStreamNonBlocking);
        cudaEventCreateWithFlags(&evRoot, cudaEventDisableTiming);
        cudaEventCreateWithFlags(&evWp,  cudaEventDisableTiming);
        cudaEventCreateWithFlags(&evW1,  cudaEventDisableTiming);
        cudaEventCreateWithFlags(&evW2,  cudaEventDisableTiming);
        cudaEventCreateWithFlags(&evW3,  cudaEventDisableTiming);
        cudaEventCreateWithFlags(&evCSR, cudaEventDisableTiming);
        cudaEventCreateWithFlags(&evEnd2, cudaEventDisableTiming);
        for (int k = 0; k < 2; k++) {
            cudaEventCreateWithFlags(&evG1[k], cudaEventDisableTiming);
            cudaEventCreateWithFlags(&evG2[k], cudaEventDisableTiming);
            cudaEventCreateWithFlags(&evG3[k], cudaEventDisableTiming);
        }
    }

    // ---- fork side streams off the capture-origin stream ----
    cudaEventRecord(evRoot, 0);
    cudaStreamWaitEvent(s2, evRoot, 0);
    cudaStreamWaitEvent(sW, evRoot, 0);
    cudaStreamWaitEvent(sC, evRoot, 0);

    // stream W: zero es/ed block, then weight transposes.
    // Every gemm waits on an evW*, which transitively orders the memset.
    cudaMemsetAsync(esed, 0, 6 * NN * 4 * sizeof(float), sW);
    cvt_transpose_f16_kernel<<<dim3(512 / 32, 256 / 32), dim3(32, 8), 0, sW>>>(proj_w, WtP, 256, 512);
    cudaEventRecord(evWp, sW);
    cvt_transpose_f16_kernel<<<dim3(2048 / 32, 512 / 32), dim3(32, 8), 0, sW>>>(w1, Wt1, 512, 2048);
    cudaEventRecord(evW1, sW);
    cvt_transpose_f16_kernel<<<dim3(2048 / 32, 2048 / 32), dim3(32, 8), 0, sW>>>(w2, Wt2, 2048, 2048);
    cudaEventRecord(evW2, sW);
    cvt_transpose_f16_kernel<<<dim3(1024 / 32, 2048 / 32), dim3(32, 8), 0, sW>>>(w3, Wt3, 2048, 1024);
    cudaEventRecord(evW3, sW);

    // stream C: CSR build
    detect_init_kernel<<<(NN + 255) / 256, 256, 0, sC>>>((const unsigned int*)ei);
    count_kernel<<<(EE + 255) / 256, 256, 0, sC>>>(ei);
    scan_fillself_kernel<<<1, 1024, 0, sC>>>();
    filledges_kernel<<<(EE + 255) / 256, 256, 0, sC>>>(ei);
    cudaEventRecord(evCSR, sC);

    // ---- half-pipelined main chain: stream 0 (rows [0,MH1)), s2 (rows [MH1,NN)) ----
    cvt_f16_kernel<<<(MH1 * 256 / 4 + 255) / 256, 256, 0, 0>>>(x, P0, MH1 * 256 / 4);
    cvt_f16_kernel<<<(MH2 * 256 / 4 + 255) / 256, 256, 0, s2>>>(
        x + (size_t)MH1 * 256, P0 + (size_t)MH1 * 256, MH2 * 256 / 4);

    // proj GEMM halves (fp16, +bias): P1 = P0 @ WtP^T
    cudaStreamWaitEvent(0, evWp, 0);
    run_gemm_proj(P0, WtP, proj_b, P1, NN, 512, 256, 0, MH1, 0);
    cudaStreamWaitEvent(s2, evWp, 0);
    run_gemm_proj(P0, WtP, proj_b, P1, NN, 512, 256, MH1, MH2, s2);

    // ---- layer 1: hmA = P1 @ Wt1^T (+es/ed) ; agg -> P0 ----
    cudaStreamWaitEvent(0, evW1, 0);
    run_gemm_attn(P1, Wt1, hmA, as1, ad1, esA, edA, 4, NN, 2048, 512, 0, MH1, 0);
    cudaEventRecord(evG1[0], 0);
    cudaStreamWaitEvent(s2, evW1, 0);
    run_gemm_attn(P1, Wt1, hmA, as1, ad1, esA, edA, 4, NN, 2048, 512, MH1, MH2, s2);
    cudaEventRecord(evG1[1], s2);
    cudaStreamWaitEvent(0, evG1[1], 0);
    cudaStreamWaitEvent(0, evCSR, 0);
    aggregate_kernel<2048, 4, 0><<<MH1, 256, 0, 0>>>(hmA, esA, edA, b1, nullptr, P0, 0);
    cudaStreamWaitEvent(s2, evG1[0], 0);
    cudaStreamWaitEvent(s2, evCSR, 0);
    aggregate_kernel<2048, 4, 0><<<MH2, 256, 0, s2>>>(hmA, esA, edA, b1, nullptr, P0, MH1);

    // ---- layer 2: hmB = P0 @ Wt2^T (+es/ed) ; agg -> P1 ----
    cudaStreamWaitEvent(0, evW2, 0);
    run_gemm_attn(P0, Wt2, hmB, as2, ad2, esB, edB, 4, NN, 2048, 2048, 0, MH1, 0);
    cudaEventRecord(evG2[0], 0);
    cudaStreamWaitEvent(s2, evW2, 0);
    run_gemm_attn(P0, Wt2, hmB, as2, ad2, esB, edB, 4, NN, 2048, 2048, MH1, MH2, s2);
    cudaEventRecord(evG2[1], s2);
    cudaStreamWaitEvent(0, evG2[1], 0);
    aggregate_kernel<2048, 4, 0><<<MH1, 256, 0, 0>>>(hmB, esB, edB, b2, nullptr, P1, 0);
    cudaStreamWaitEvent(s2, evG2[0], 0);
    aggregate_kernel<2048, 4, 0><<<MH2, 256, 0, s2>>>(hmB, esB, edB, b2, nullptr, P1, MH1);

    // ---- layer 3: hmA = P1 @ Wt3^T (+es/ed) ; agg -> out (mean heads) ----
    cudaStreamWaitEvent(0, evW3, 0);
    run_gemm_attn(P1, Wt3, hmA, as3, ad3, esC, edC, 2, NN, 1024, 2048, 0, MH1, 0);
    cudaEventRecord(evG3[0], 0);
    cudaStreamWaitEvent(s2, evW3, 0);
    run_gemm_attn(P1, Wt3, hmA, as3, ad3, esC, edC, 2, NN, 1024, 2048, MH1, MH2, s2);
    cudaEventRecord(evG3[1], s2);
    cudaStreamWaitEvent(0, evG3[1], 0);
    aggregate_kernel<1024, 2, 1><<<MH1, 256, 0, 0>>>(hmA, esC, edC, b3, out, nullptr, 0);
    cudaStreamWaitEvent(s2, evG3[0], 0);
    aggregate_kernel<1024, 2, 1><<<MH2, 256, 0, s2>>>(hmA, esC, edC, b3, out, nullptr, MH1);

    // ---- join s2 back into the origin stream ----
    cudaEventRecord(evEnd2, s2);
    cudaStreamWaitEvent(0, evEnd2, 0);
}